// round 1
// baseline (speedup 1.0000x reference)
#include <cuda_runtime.h>
#include <math.h>
#include <stdint.h>

#define BB 4
#define TT 2048
#define NHH 16
#define HCC 64
#define DD 1024
#define RHH 4
#define SHH 6
#define MAXL 100

// ---------------- scratch (device globals: allowed) ----------------
__device__ float g_Q[BB * TT * DD];
__device__ float g_K[BB * TT * DD];
__device__ float g_V[BB * TT * DD];
__device__ float g_ctx[BB * TT * DD];
__device__ float g_PS[BB * TT * DD];
__device__ float g_Pval[NHH][MAXL + 1];
__device__ float g_wmix[2];  // [0]=w, [1]=1-w

// ---------------- setup: Pval table + mix weight ----------------
__global__ void setup_kernel(const float* __restrict__ mu,
                             const float* __restrict__ lam,
                             const float* __restrict__ g1,
                             const float* __restrict__ g2,
                             const float* __restrict__ th1,
                             const float* __restrict__ th2) {
    int h = threadIdx.x;
    if (h == 0) {
        float w = 1.0f / (1.0f + __expf(-mu[0]));
        g_wmix[0] = w;
        g_wmix[1] = 1.0f - w;
    }
    if (h < NHH) {
        float base, theta = 0.0f;
        int kind;
        if (h < RHH) { base = lam[h]; kind = 0; }
        else if (h < RHH + SHH) { base = g1[h - RHH]; theta = th1[h - RHH]; kind = 1; }
        else { base = g2[h - RHH - SHH]; theta = th2[h - RHH - SHH]; kind = 2; }
        float p = 1.0f;
        g_Pval[h][0] = 0.0f;
        for (int L = 1; L <= MAXL; L++) {
            p *= base;  // exact signed pow for integer L
            float v = p;
            if (kind == 1) v *= sinf(theta * (float)L);
            else if (kind == 2) v *= cosf(theta * (float)L);
            g_Pval[h][L] = v;
        }
    }
}

// ---------------- SGEMM: C[M,N] = A[M,K] @ W[N,K]^T + bias ----------------
__global__ __launch_bounds__(256) void sgemm_bias(
    const float* __restrict__ A, const float* __restrict__ W,
    const float* __restrict__ bias, float* __restrict__ C,
    int M, int N, int K) {
    __shared__ float As[8][128];
    __shared__ float Bs[8][128];
    int tid = threadIdx.x;
    int m0 = blockIdx.y * 128, n0 = blockIdx.x * 128;
    int tr = tid >> 4, tc = tid & 15;
    int lrow = tid >> 1, lseg = (tid & 1) << 2;
    const float* Ap = A + (size_t)(m0 + lrow) * K + lseg;
    const float* Wp = W + (size_t)(n0 + lrow) * K + lseg;
    float acc[8][8] = {};
    for (int k0 = 0; k0 < K; k0 += 8) {
        float4 av = *(const float4*)(Ap + k0);
        float4 wv = *(const float4*)(Wp + k0);
        __syncthreads();
        As[lseg + 0][lrow] = av.x; As[lseg + 1][lrow] = av.y;
        As[lseg + 2][lrow] = av.z; As[lseg + 3][lrow] = av.w;
        Bs[lseg + 0][lrow] = wv.x; Bs[lseg + 1][lrow] = wv.y;
        Bs[lseg + 2][lrow] = wv.z; Bs[lseg + 3][lrow] = wv.w;
        __syncthreads();
#pragma unroll
        for (int kk = 0; kk < 8; kk++) {
            float ra[8], rb[8];
            *(float4*)(ra)     = *(const float4*)&As[kk][tr * 8];
            *(float4*)(ra + 4) = *(const float4*)&As[kk][tr * 8 + 4];
            *(float4*)(rb)     = *(const float4*)&Bs[kk][tc * 8];
            *(float4*)(rb + 4) = *(const float4*)&Bs[kk][tc * 8 + 4];
#pragma unroll
            for (int i = 0; i < 8; i++)
#pragma unroll
                for (int j = 0; j < 8; j++)
                    acc[i][j] += ra[i] * rb[j];
        }
    }
    float rbias[8];
#pragma unroll
    for (int j = 0; j < 8; j++) rbias[j] = bias[n0 + tc * 8 + j];
#pragma unroll
    for (int i = 0; i < 8; i++) {
        float* Cp = C + (size_t)(m0 + tr * 8 + i) * N + n0 + tc * 8;
#pragma unroll
        for (int j = 0; j < 8; j++) Cp[j] = acc[i][j] + rbias[j];
    }
}

// ---------------- Flash attention: ctx = (1-w) * softmax(Q K^T) V ----------------
// Block: 128 threads; q-tile=128, k-tile=64, d=64.
// smem layout (floats): Qs[64][132] | Ks[64][68] | Vs[64][68] | Ps[128][65]
#define FL_QS_STRIDE 132
#define FL_KS_STRIDE 68
#define FL_VS_STRIDE 68
#define FL_PS_STRIDE 65
#define FL_SMEM_FLOATS (64 * FL_QS_STRIDE + 64 * FL_KS_STRIDE + 64 * FL_VS_STRIDE + 128 * FL_PS_STRIDE)

extern __shared__ float fl_smem[];

__global__ __launch_bounds__(128, 2) void flash_kernel() {
    float* Qs = fl_smem;
    float* Ks = Qs + 64 * FL_QS_STRIDE;
    float* Vs = Ks + 64 * FL_KS_STRIDE;
    float* Ps = Vs + 64 * FL_VS_STRIDE;

    int tid = threadIdx.x;
    int b = blockIdx.z, h = blockIdx.y;
    int q0 = blockIdx.x * 128;
    int tr = tid >> 3;   // 0..15 : q-row group (and q-row group for O)
    int tc = tid & 7;    // 0..7  : k-col group (S phase) / d-col group (O phase)

    // ---- load Q tile transposed: Qs[d][q] ----
    {
        const float* src = g_Q + ((size_t)(b * TT + q0 + tid)) * DD + h * HCC;
#pragma unroll
        for (int f = 0; f < 16; f++) {
            float4 v = *(const float4*)(src + f * 4);
            Qs[(f * 4 + 0) * FL_QS_STRIDE + tid] = v.x;
            Qs[(f * 4 + 1) * FL_QS_STRIDE + tid] = v.y;
            Qs[(f * 4 + 2) * FL_QS_STRIDE + tid] = v.z;
            Qs[(f * 4 + 3) * FL_QS_STRIDE + tid] = v.w;
        }
    }

    float m[8], l[8], o[8][8];
#pragma unroll
    for (int i = 0; i < 8; i++) {
        m[i] = -3.0e38f; l[i] = 0.0f;
#pragma unroll
        for (int j = 0; j < 8; j++) o[i][j] = 0.0f;
    }

    int krow = tid >> 1;
    int half = (tid & 1) * 32;

    for (int kt = 0; kt < TT / 64; kt++) {
        // stage K,V tile into registers (overlap with previous O-gemm)
        float4 kreg[8], vreg[8];
        const float* kp = g_K + ((size_t)(b * TT + kt * 64 + krow)) * DD + h * HCC + half;
        const float* vp = g_V + ((size_t)(b * TT + kt * 64 + krow)) * DD + h * HCC + half;
#pragma unroll
        for (int f = 0; f < 8; f++) kreg[f] = *(const float4*)(kp + f * 4);
#pragma unroll
        for (int f = 0; f < 8; f++) vreg[f] = *(const float4*)(vp + f * 4);

        __syncthreads();  // previous tile fully consumed
#pragma unroll
        for (int f = 0; f < 8; f++) {
            int d = half + f * 4;
            Ks[(d + 0) * FL_KS_STRIDE + krow] = kreg[f].x;
            Ks[(d + 1) * FL_KS_STRIDE + krow] = kreg[f].y;
            Ks[(d + 2) * FL_KS_STRIDE + krow] = kreg[f].z;
            Ks[(d + 3) * FL_KS_STRIDE + krow] = kreg[f].w;
            *(float4*)&Vs[krow * FL_VS_STRIDE + d] = vreg[f];
        }
        __syncthreads();

        // ---- S = Q K^T  (q-tile 128 x k-tile 64) ----
        float sacc[8][8] = {};
#pragma unroll 8
        for (int d = 0; d < 64; d++) {
            float ra[8], rb[8];
            *(float4*)(ra)     = *(const float4*)&Qs[d * FL_QS_STRIDE + tr * 8];
            *(float4*)(ra + 4) = *(const float4*)&Qs[d * FL_QS_STRIDE + tr * 8 + 4];
            *(float4*)(rb)     = *(const float4*)&Ks[d * FL_KS_STRIDE + tc * 8];
            *(float4*)(rb + 4) = *(const float4*)&Ks[d * FL_KS_STRIDE + tc * 8 + 4];
#pragma unroll
            for (int i = 0; i < 8; i++)
#pragma unroll
                for (int j = 0; j < 8; j++)
                    sacc[i][j] += ra[i] * rb[j];
        }

        // ---- online softmax (row stats across 8 lanes of tc) ----
#pragma unroll
        for (int i = 0; i < 8; i++) {
            float mr = sacc[i][0];
#pragma unroll
            for (int j = 1; j < 8; j++) mr = fmaxf(mr, sacc[i][j]);
            mr = fmaxf(mr, __shfl_xor_sync(0xffffffffu, mr, 1, 8));
            mr = fmaxf(mr, __shfl_xor_sync(0xffffffffu, mr, 2, 8));
            mr = fmaxf(mr, __shfl_xor_sync(0xffffffffu, mr, 4, 8));
            float mnew = fmaxf(m[i], mr);
            float corr = __expf(m[i] - mnew);
            m[i] = mnew;
            float rs = 0.0f;
#pragma unroll
            for (int j = 0; j < 8; j++) {
                float p = __expf(sacc[i][j] - mnew);
                sacc[i][j] = p;
                rs += p;
            }
            rs += __shfl_xor_sync(0xffffffffu, rs, 1, 8);
            rs += __shfl_xor_sync(0xffffffffu, rs, 2, 8);
            rs += __shfl_xor_sync(0xffffffffu, rs, 4, 8);
            l[i] = l[i] * corr + rs;
#pragma unroll
            for (int j = 0; j < 8; j++) o[i][j] *= corr;
#pragma unroll
            for (int j = 0; j < 8; j++)
                Ps[(tr * 8 + i) * FL_PS_STRIDE + tc * 8 + j] = sacc[i][j];
        }
        __syncthreads();

        // ---- O += P V  (q-tile 128 x d 64, reduce over k-tile 64) ----
#pragma unroll 4
        for (int k = 0; k < 64; k++) {
            float rp[8], rv[8];
#pragma unroll
            for (int i = 0; i < 8; i++)
                rp[i] = Ps[(tr * 8 + i) * FL_PS_STRIDE + k];
            *(float4*)(rv)     = *(const float4*)&Vs[k * FL_VS_STRIDE + tc * 8];
            *(float4*)(rv + 4) = *(const float4*)&Vs[k * FL_VS_STRIDE + tc * 8 + 4];
#pragma unroll
            for (int i = 0; i < 8; i++)
#pragma unroll
                for (int j = 0; j < 8; j++)
                    o[i][j] += rp[i] * rv[j];
        }
    }

    // ---- epilogue: ctx = (1-w) * O / l ----
    float w1 = g_wmix[1];
#pragma unroll
    for (int i = 0; i < 8; i++) {
        float inv = w1 / l[i];
        float* dst = g_ctx + ((size_t)(b * TT + q0 + tr * 8 + i)) * DD + h * HCC + tc * 8;
#pragma unroll
        for (int j = 0; j < 8; j++) dst[j] = o[i][j] * inv;
    }
}

// ---------------- prefix sums of V along t, per (b,h,c) ----------------
__global__ void prefix_kernel() {
    int b = blockIdx.x >> 4;
    int h = blockIdx.x & 15;
    int c = threadIdx.x;  // 0..63
    const float* vp = g_V + ((size_t)(b * TT)) * DD + h * HCC + c;
    float* ps = g_PS + ((size_t)(b * TT)) * DD + h * HCC + c;
    float run = 0.0f;
    for (int t = 0; t < TT; t++) {
        run += vp[(size_t)t * DD];
        ps[(size_t)t * DD] = run;
    }
}

// ---------------- PV: ctx += w * (P @ V) via 99-tap conv + prefix ----------------
__global__ __launch_bounds__(256) void pv_kernel() {
    __shared__ float Vw[162 * 64];
    __shared__ float Pv[MAXL + 1];
    int b = blockIdx.z, h = blockIdx.y;
    int q0 = blockIdx.x * 64;
    int tid = threadIdx.x;
    if (tid <= MAXL) Pv[tid] = g_Pval[h][tid];
    // V rows q0-99 .. q0+62  (idx r <-> t = q0-99+r)
    for (int idx = tid; idx < 162 * 64; idx += 256) {
        int r = idx >> 6, c = idx & 63;
        int tg = q0 - 99 + r;
        Vw[idx] = (tg >= 0) ? g_V[((size_t)(b * TT + tg)) * DD + h * HCC + c] : 0.0f;
    }
    __syncthreads();
    int c = tid & 63, qq = tid >> 6;  // qq: 0..3
    float w = g_wmix[0];
#pragma unroll 1
    for (int ii = 0; ii < 16; ii++) {
        int ql = qq * 16 + ii;
        int qg = q0 + ql;
        float acc = 0.0f;
        int jmax = min(99, qg);
        for (int j = 1; j <= jmax; j++)
            acc += Pv[j] * Vw[((ql - j + 99) << 6) | c];
        if (qg >= 100)
            acc += Pv[MAXL] * g_PS[((size_t)(b * TT + qg - 100)) * DD + h * HCC + c];
        size_t oi = ((size_t)(b * TT + qg)) * DD + h * HCC + c;
        g_ctx[oi] += w * acc;
    }
}

// ---------------- launch ----------------
extern "C" void kernel_launch(void* const* d_in, const int* in_sizes, int n_in,
                              void* d_out, int out_size) {
    const float* x   = (const float*)d_in[0];
    const float* mu  = (const float*)d_in[1];
    const float* lam = (const float*)d_in[2];
    const float* g1  = (const float*)d_in[3];
    const float* g2  = (const float*)d_in[4];
    const float* th1 = (const float*)d_in[5];
    const float* th2 = (const float*)d_in[6];
    const float* Wq  = (const float*)d_in[7];
    const float* bq  = (const float*)d_in[8];
    const float* Wk  = (const float*)d_in[9];
    const float* bk  = (const float*)d_in[10];
    const float* Wv  = (const float*)d_in[11];
    const float* bv  = (const float*)d_in[12];
    const float* Wf  = (const float*)d_in[13];
    const float* bf  = (const float*)d_in[14];
    float* out = (float*)d_out;

    float *Qd, *Kd, *Vd, *CTXd;
    cudaGetSymbolAddress((void**)&Qd, g_Q);
    cudaGetSymbolAddress((void**)&Kd, g_K);
    cudaGetSymbolAddress((void**)&Vd, g_V);
    cudaGetSymbolAddress((void**)&CTXd, g_ctx);

    setup_kernel<<<1, 32>>>(mu, lam, g1, g2, th1, th2);

    dim3 ggrid(DD / 128, (BB * TT) / 128);
    sgemm_bias<<<ggrid, 256>>>(x, Wq, bq, Qd, BB * TT, DD, DD);
    sgemm_bias<<<ggrid, 256>>>(x, Wk, bk, Kd, BB * TT, DD, DD);
    sgemm_bias<<<ggrid, 256>>>(x, Wv, bv, Vd, BB * TT, DD, DD);

    static int smem_set = 0;
    (void)smem_set;
    cudaFuncSetAttribute(flash_kernel, cudaFuncAttributeMaxDynamicSharedMemorySize,
                         FL_SMEM_FLOATS * sizeof(float));
    dim3 fgrid(TT / 128, NHH, BB);
    flash_kernel<<<fgrid, 128, FL_SMEM_FLOATS * sizeof(float)>>>();

    prefix_kernel<<<BB * NHH, 64>>>();

    dim3 pvgrid(TT / 64, NHH, BB);
    pv_kernel<<<pvgrid, 256>>>();

    sgemm_bias<<<ggrid, 256>>>(CTXd, Wf, bf, out, BB * TT, DD, DD);
}

// round 4
// speedup vs baseline: 1.3138x; 1.3138x over previous
#include <cuda_runtime.h>
#include <cuda_bf16.h>
#include <math.h>
#include <stdint.h>

#define BB 4
#define TT 2048
#define NHH 16
#define HCC 64
#define DD 1024
#define RHH 4
#define SHH 6
#define MAXL 100

// ---------------- scratch (device globals: allowed) ----------------
__device__ float g_Q[BB * TT * DD];
__device__ float g_K[BB * TT * DD];
__device__ float g_V[BB * TT * DD];
__device__ float g_ctx[BB * TT * DD];
__device__ float g_PS[BB * TT * DD];
__device__ float g_Pval[NHH][MAXL + 1];
__device__ float g_wmix[2];  // [0]=w, [1]=1-w

// bf16x2 split operands
__device__ __nv_bfloat16 g_xh[BB * TT * DD];
__device__ __nv_bfloat16 g_xl[BB * TT * DD];
__device__ __nv_bfloat16 g_wh[4 * DD * DD];
__device__ __nv_bfloat16 g_wl[4 * DD * DD];

// ---------------- PTX helpers (baseline ISA only: sm_80-class) ----------------
__device__ __forceinline__ uint32_t smem_u32(const void* p) {
    uint32_t a;
    asm("{ .reg .u64 t; cvta.to.shared.u64 t, %1; cvt.u32.u64 %0, t; }" : "=r"(a) : "l"(p));
    return a;
}

#define CP_ASYNC16(dst, src) \
    asm volatile("cp.async.cg.shared.global [%0], [%1], 16;" :: "r"(dst), "l"(src))
#define CP_COMMIT() asm volatile("cp.async.commit_group;")
#define CP_WAIT1() asm volatile("cp.async.wait_group 1;")
#define CP_WAIT0() asm volatile("cp.async.wait_group 0;")

#define LDM_X4(r0, r1, r2, r3, addr) \
    asm volatile("ldmatrix.sync.aligned.m8n8.x4.shared.b16 {%0,%1,%2,%3}, [%4];" \
                 : "=r"(r0), "=r"(r1), "=r"(r2), "=r"(r3) : "r"(addr))

#define MMA16816(c0, c1, c2, c3, a0, a1, a2, a3, b0, b1) \
    asm volatile("mma.sync.aligned.m16n8k16.row.col.f32.bf16.bf16.f32 " \
                 "{%0,%1,%2,%3}, {%4,%5,%6,%7}, {%8,%9}, {%0,%1,%2,%3};" \
                 : "+f"(c0), "+f"(c1), "+f"(c2), "+f"(c3) \
                 : "r"(a0), "r"(a1), "r"(a2), "r"(a3), "r"(b0), "r"(b1))

// ---------------- setup: Pval table + mix weight ----------------
__global__ void setup_kernel(const float* __restrict__ mu,
                             const float* __restrict__ lam,
                             const float* __restrict__ g1,
                             const float* __restrict__ g2,
                             const float* __restrict__ th1,
                             const float* __restrict__ th2) {
    int h = threadIdx.x;
    if (h == 0) {
        float w = 1.0f / (1.0f + __expf(-mu[0]));
        g_wmix[0] = w;
        g_wmix[1] = 1.0f - w;
    }
    if (h < NHH) {
        float base, theta = 0.0f;
        int kind;
        if (h < RHH) { base = lam[h]; kind = 0; }
        else if (h < RHH + SHH) { base = g1[h - RHH]; theta = th1[h - RHH]; kind = 1; }
        else { base = g2[h - RHH - SHH]; theta = th2[h - RHH - SHH]; kind = 2; }
        float p = 1.0f;
        g_Pval[h][0] = 0.0f;
        for (int L = 1; L <= MAXL; L++) {
            p *= base;
            float v = p;
            if (kind == 1) v *= sinf(theta * (float)L);
            else if (kind == 2) v *= cosf(theta * (float)L);
            g_Pval[h][L] = v;
        }
    }
}

// ---------------- fp32 -> bf16 hi/lo split ----------------
__global__ __launch_bounds__(256) void cvt_split(const float* __restrict__ in,
                                                 __nv_bfloat16* __restrict__ hi,
                                                 __nv_bfloat16* __restrict__ lo,
                                                 int n4) {
    int i = blockIdx.x * blockDim.x + threadIdx.x;
    if (i >= n4) return;
    float4 v = ((const float4*)in)[i];
    __nv_bfloat16 h0 = __float2bfloat16(v.x);
    __nv_bfloat16 h1 = __float2bfloat16(v.y);
    __nv_bfloat16 h2 = __float2bfloat16(v.z);
    __nv_bfloat16 h3 = __float2bfloat16(v.w);
    __nv_bfloat16 l0 = __float2bfloat16(v.x - __bfloat162float(h0));
    __nv_bfloat16 l1 = __float2bfloat16(v.y - __bfloat162float(h1));
    __nv_bfloat16 l2 = __float2bfloat16(v.z - __bfloat162float(h2));
    __nv_bfloat16 l3 = __float2bfloat16(v.w - __bfloat162float(h3));
    __nv_bfloat162 hp0 = __halves2bfloat162(h0, h1);
    __nv_bfloat162 hp1 = __halves2bfloat162(h2, h3);
    __nv_bfloat162 lp0 = __halves2bfloat162(l0, l1);
    __nv_bfloat162 lp1 = __halves2bfloat162(l2, l3);
    uint2 hw, lw;
    hw.x = *(uint32_t*)&hp0; hw.y = *(uint32_t*)&hp1;
    lw.x = *(uint32_t*)&lp0; lw.y = *(uint32_t*)&lp1;
    ((uint2*)hi)[i] = hw;
    ((uint2*)lo)[i] = lw;
}

// ---------------- HMMA bf16x2 GEMM: C[M,1024] = A[M,1024] @ W[1024,1024]^T + bias ----
// CTA 128x128, 8 warps (warp tile 32x64), K-step 32, 2-stage cp.async pipeline.
// smem tile: 128 rows x 32 cols bf16, padded stride 40 elems (80B) -> conflict-free ldmatrix.
#define G_TILE_B 10240          // 128*40*2
#define G_STAGE_B (4 * G_TILE_B)
#define G_SMEM (2 * G_STAGE_B)  // 81920

__global__ __launch_bounds__(256) void gemm_mma(
    const __nv_bfloat16* __restrict__ Ah, const __nv_bfloat16* __restrict__ Al,
    const __nv_bfloat16* __restrict__ Bh, const __nv_bfloat16* __restrict__ Bl,
    const float* __restrict__ bias, float* __restrict__ C) {
    extern __shared__ char gsm[];
    const uint32_t smBase = smem_u32(gsm);

    const int tid = threadIdx.x;
    const int lane = tid & 31;
    const int wid = tid >> 5;
    const int wm = wid & 3;       // m 32-row block
    const int wn = wid >> 2;      // n 64-col block
    const int m0 = blockIdx.y * 128;
    const int n0 = blockIdx.x * 128;

    const __nv_bfloat16* srcs[4];
    srcs[0] = Ah + (size_t)m0 * DD;
    srcs[1] = Al + (size_t)m0 * DD;
    srcs[2] = Bh + (size_t)n0 * DD;
    srcs[3] = Bl + (size_t)n0 * DD;

    // precomputed per-thread load coords: chunks tid*2, tid*2+1
    const int ch0 = tid * 2;
    const int lrow0 = ch0 >> 2, lcol0 = (ch0 & 3) * 8;
    const int lrow1 = (ch0 + 1) >> 2, lcol1 = ((ch0 + 1) & 3) * 8;

    float c[2][8][4];
#pragma unroll
    for (int mi = 0; mi < 2; mi++)
#pragma unroll
        for (int ni = 0; ni < 8; ni++)
#pragma unroll
            for (int r = 0; r < 4; r++) c[mi][ni][r] = 0.0f;

    // ---- prologue: load stage 0 ----
    {
        uint32_t sb = smBase;
#pragma unroll
        for (int t = 0; t < 4; t++) {
            CP_ASYNC16(sb + t * G_TILE_B + lrow0 * 80 + lcol0 * 2,
                       srcs[t] + (size_t)lrow0 * DD + lcol0);
            CP_ASYNC16(sb + t * G_TILE_B + lrow1 * 80 + lcol1 * 2,
                       srcs[t] + (size_t)lrow1 * DD + lcol1);
        }
        CP_COMMIT();
    }

    // per-lane fragment addresses (offsets within a stage)
    const uint32_t aOff = (uint32_t)((wm * 32 + (lane & 15)) * 80 + ((lane >> 4) * 8) * 2);
    const uint32_t bOff = (uint32_t)((wn * 64 + ((lane >> 4) & 1) * 8 + (lane & 7)) * 80 +
                                     (((lane >> 3) & 1) * 8) * 2);

    const int NIT = DD / 32;  // 32
    for (int it = 0; it < NIT; it++) {
        if (it + 1 < NIT) {
            uint32_t sb = smBase + ((it + 1) & 1) * G_STAGE_B;
            int k0 = (it + 1) * 32;
#pragma unroll
            for (int t = 0; t < 4; t++) {
                CP_ASYNC16(sb + t * G_TILE_B + lrow0 * 80 + lcol0 * 2,
                           srcs[t] + (size_t)lrow0 * DD + k0 + lcol0);
                CP_ASYNC16(sb + t * G_TILE_B + lrow1 * 80 + lcol1 * 2,
                           srcs[t] + (size_t)lrow1 * DD + k0 + lcol1);
            }
            CP_COMMIT();
            CP_WAIT1();
        } else {
            CP_WAIT0();
        }
        __syncthreads();

        const uint32_t aBase = smBase + (it & 1) * G_STAGE_B;
        const uint32_t bBase = aBase + 2 * G_TILE_B;
#pragma unroll
        for (int kk = 0; kk < 2; kk++) {
            uint32_t ah[2][4], al[2][4];
#pragma unroll
            for (int mi = 0; mi < 2; mi++) {
                uint32_t a = aBase + aOff + (uint32_t)(mi * 16 * 80 + kk * 32);
                LDM_X4(ah[mi][0], ah[mi][1], ah[mi][2], ah[mi][3], a);
                LDM_X4(al[mi][0], al[mi][1], al[mi][2], al[mi][3], a + G_TILE_B);
            }
            uint32_t bh[8][2], bl[8][2];
#pragma unroll
            for (int nq = 0; nq < 4; nq++) {
                uint32_t a = bBase + bOff + (uint32_t)(nq * 16 * 80 + kk * 32);
                LDM_X4(bh[nq * 2][0], bh[nq * 2][1], bh[nq * 2 + 1][0], bh[nq * 2 + 1][1], a);
                LDM_X4(bl[nq * 2][0], bl[nq * 2][1], bl[nq * 2 + 1][0], bl[nq * 2 + 1][1],
                       a + G_TILE_B);
            }
#pragma unroll
            for (int mi = 0; mi < 2; mi++)
#pragma unroll
                for (int ni = 0; ni < 8; ni++) {
                    float* cc = c[mi][ni];
                    MMA16816(cc[0], cc[1], cc[2], cc[3],
                             ah[mi][0], ah[mi][1], ah[mi][2], ah[mi][3],
                             bh[ni][0], bh[ni][1]);
                    MMA16816(cc[0], cc[1], cc[2], cc[3],
                             ah[mi][0], ah[mi][1], ah[mi][2], ah[mi][3],
                             bl[ni][0], bl[ni][1]);
                    MMA16816(cc[0], cc[1], cc[2], cc[3],
                             al[mi][0], al[mi][1], al[mi][2], al[mi][3],
                             bh[ni][0], bh[ni][1]);
                }
        }
        __syncthreads();
    }

    // ---- epilogue ----
#pragma unroll
    for (int mi = 0; mi < 2; mi++) {
        int row = m0 + wm * 32 + mi * 16 + (lane >> 2);
#pragma unroll
        for (int ni = 0; ni < 8; ni++) {
            int col = n0 + wn * 64 + ni * 8 + (lane & 3) * 2;
            float b0 = bias[col], b1 = bias[col + 1];
            float2 v0 = make_float2(c[mi][ni][0] + b0, c[mi][ni][1] + b1);
            float2 v1 = make_float2(c[mi][ni][2] + b0, c[mi][ni][3] + b1);
            *(float2*)(C + (size_t)row * DD + col) = v0;
            *(float2*)(C + (size_t)(row + 8) * DD + col) = v1;
        }
    }
}

// ---------------- Flash attention: ctx = (1-w) * softmax(Q K^T) V ----------------
#define FL_QS_STRIDE 132
#define FL_KS_STRIDE 68
#define FL_VS_STRIDE 68
#define FL_PS_STRIDE 65
#define FL_SMEM_FLOATS (64 * FL_QS_STRIDE + 64 * FL_KS_STRIDE + 64 * FL_VS_STRIDE + 128 * FL_PS_STRIDE)

extern __shared__ float fl_smem[];

__global__ __launch_bounds__(128, 2) void flash_kernel() {
    float* Qs = fl_smem;
    float* Ks = Qs + 64 * FL_QS_STRIDE;
    float* Vs = Ks + 64 * FL_KS_STRIDE;
    float* Ps = Vs + 64 * FL_VS_STRIDE;

    int tid = threadIdx.x;
    int b = blockIdx.z, h = blockIdx.y;
    int q0 = blockIdx.x * 128;
    int tr = tid >> 3;
    int tc = tid & 7;

    {
        const float* src = g_Q + ((size_t)(b * TT + q0 + tid)) * DD + h * HCC;
#pragma unroll
        for (int f = 0; f < 16; f++) {
            float4 v = *(const float4*)(src + f * 4);
            Qs[(f * 4 + 0) * FL_QS_STRIDE + tid] = v.x;
            Qs[(f * 4 + 1) * FL_QS_STRIDE + tid] = v.y;
            Qs[(f * 4 + 2) * FL_QS_STRIDE + tid] = v.z;
            Qs[(f * 4 + 3) * FL_QS_STRIDE + tid] = v.w;
        }
    }

    float m[8], l[8], o[8][8];
#pragma unroll
    for (int i = 0; i < 8; i++) {
        m[i] = -3.0e38f; l[i] = 0.0f;
#pragma unroll
        for (int j = 0; j < 8; j++) o[i][j] = 0.0f;
    }

    int krow = tid >> 1;
    int half = (tid & 1) * 32;

    for (int kt = 0; kt < TT / 64; kt++) {
        float4 kreg[8], vreg[8];
        const float* kp = g_K + ((size_t)(b * TT + kt * 64 + krow)) * DD + h * HCC + half;
        const float* vp = g_V + ((size_t)(b * TT + kt * 64 + krow)) * DD + h * HCC + half;
#pragma unroll
        for (int f = 0; f < 8; f++) kreg[f] = *(const float4*)(kp + f * 4);
#pragma unroll
        for (int f = 0; f < 8; f++) vreg[f] = *(const float4*)(vp + f * 4);

        __syncthreads();
#pragma unroll
        for (int f = 0; f < 8; f++) {
            int d = half + f * 4;
            Ks[(d + 0) * FL_KS_STRIDE + krow] = kreg[f].x;
            Ks[(d + 1) * FL_KS_STRIDE + krow] = kreg[f].y;
            Ks[(d + 2) * FL_KS_STRIDE + krow] = kreg[f].z;
            Ks[(d + 3) * FL_KS_STRIDE + krow] = kreg[f].w;
            *(float4*)&Vs[krow * FL_VS_STRIDE + d] = vreg[f];
        }
        __syncthreads();

        float sacc[8][8] = {};
#pragma unroll 8
        for (int d = 0; d < 64; d++) {
            float ra[8], rb[8];
            *(float4*)(ra)     = *(const float4*)&Qs[d * FL_QS_STRIDE + tr * 8];
            *(float4*)(ra + 4) = *(const float4*)&Qs[d * FL_QS_STRIDE + tr * 8 + 4];
            *(float4*)(rb)     = *(const float4*)&Ks[d * FL_KS_STRIDE + tc * 8];
            *(float4*)(rb + 4) = *(const float4*)&Ks[d * FL_KS_STRIDE + tc * 8 + 4];
#pragma unroll
            for (int i = 0; i < 8; i++)
#pragma unroll
                for (int j = 0; j < 8; j++)
                    sacc[i][j] += ra[i] * rb[j];
        }

#pragma unroll
        for (int i = 0; i < 8; i++) {
            float mr = sacc[i][0];
#pragma unroll
            for (int j = 1; j < 8; j++) mr = fmaxf(mr, sacc[i][j]);
            mr = fmaxf(mr, __shfl_xor_sync(0xffffffffu, mr, 1, 8));
            mr = fmaxf(mr, __shfl_xor_sync(0xffffffffu, mr, 2, 8));
            mr = fmaxf(mr, __shfl_xor_sync(0xffffffffu, mr, 4, 8));
            float mnew = fmaxf(m[i], mr);
            float corr = __expf(m[i] - mnew);
            m[i] = mnew;
            float rs = 0.0f;
#pragma unroll
            for (int j = 0; j < 8; j++) {
                float p = __expf(sacc[i][j] - mnew);
                sacc[i][j] = p;
                rs += p;
            }
            rs += __shfl_xor_sync(0xffffffffu, rs, 1, 8);
            rs += __shfl_xor_sync(0xffffffffu, rs, 2, 8);
            rs += __shfl_xor_sync(0xffffffffu, rs, 4, 8);
            l[i] = l[i] * corr + rs;
#pragma unroll
            for (int j = 0; j < 8; j++) o[i][j] *= corr;
#pragma unroll
            for (int j = 0; j < 8; j++)
                Ps[(tr * 8 + i) * FL_PS_STRIDE + tc * 8 + j] = sacc[i][j];
        }
        __syncthreads();

#pragma unroll 4
        for (int k = 0; k < 64; k++) {
            float rp[8], rv[8];
#pragma unroll
            for (int i = 0; i < 8; i++)
                rp[i] = Ps[(tr * 8 + i) * FL_PS_STRIDE + k];
            *(float4*)(rv)     = *(const float4*)&Vs[k * FL_VS_STRIDE + tc * 8];
            *(float4*)(rv + 4) = *(const float4*)&Vs[k * FL_VS_STRIDE + tc * 8 + 4];
#pragma unroll
            for (int i = 0; i < 8; i++)
#pragma unroll
                for (int j = 0; j < 8; j++)
                    o[i][j] += rp[i] * rv[j];
        }
    }

    float w1 = g_wmix[1];
#pragma unroll
    for (int i = 0; i < 8; i++) {
        float inv = w1 / l[i];
        float* dst = g_ctx + ((size_t)(b * TT + q0 + tr * 8 + i)) * DD + h * HCC + tc * 8;
#pragma unroll
        for (int j = 0; j < 8; j++) dst[j] = o[i][j] * inv;
    }
}

// ---------------- prefix sums of V along t, per (b,h,c) ----------------
__global__ void prefix_kernel() {
    int b = blockIdx.x >> 4;
    int h = blockIdx.x & 15;
    int c = threadIdx.x;
    const float* vp = g_V + ((size_t)(b * TT)) * DD + h * HCC + c;
    float* ps = g_PS + ((size_t)(b * TT)) * DD + h * HCC + c;
    float run = 0.0f;
    for (int t = 0; t < TT; t++) {
        run += vp[(size_t)t * DD];
        ps[(size_t)t * DD] = run;
    }
}

// ---------------- PV: ctx += w * (P @ V) via 99-tap conv + prefix ----------------
__global__ __launch_bounds__(256) void pv_kernel() {
    __shared__ float Vw[162 * 64];
    __shared__ float Pv[MAXL + 1];
    int b = blockIdx.z, h = blockIdx.y;
    int q0 = blockIdx.x * 64;
    int tid = threadIdx.x;
    if (tid <= MAXL) Pv[tid] = g_Pval[h][tid];
    for (int idx = tid; idx < 162 * 64; idx += 256) {
        int r = idx >> 6, c = idx & 63;
        int tg = q0 - 99 + r;
        Vw[idx] = (tg >= 0) ? g_V[((size_t)(b * TT + tg)) * DD + h * HCC + c] : 0.0f;
    }
    __syncthreads();
    int c = tid & 63, qq = tid >> 6;
    float w = g_wmix[0];
#pragma unroll 1
    for (int ii = 0; ii < 16; ii++) {
        int ql = qq * 16 + ii;
        int qg = q0 + ql;
        float acc = 0.0f;
        int jmax = min(99, qg);
        for (int j = 1; j <= jmax; j++)
            acc += Pv[j] * Vw[((ql - j + 99) << 6) | c];
        if (qg >= 100)
            acc += Pv[MAXL] * g_PS[((size_t)(b * TT + qg - 100)) * DD + h * HCC + c];
        size_t oi = ((size_t)(b * TT + qg)) * DD + h * HCC + c;
        g_ctx[oi] += w * acc;
    }
}

// ---------------- launch ----------------
extern "C" void kernel_launch(void* const* d_in, const int* in_sizes, int n_in,
                              void* d_out, int out_size) {
    const float* x   = (const float*)d_in[0];
    const float* mu  = (const float*)d_in[1];
    const float* lam = (const float*)d_in[2];
    const float* g1  = (const float*)d_in[3];
    const float* g2  = (const float*)d_in[4];
    const float* th1 = (const float*)d_in[5];
    const float* th2 = (const float*)d_in[6];
    const float* Wq  = (const float*)d_in[7];
    const float* bq  = (const float*)d_in[8];
    const float* Wk  = (const float*)d_in[9];
    const float* bk  = (const float*)d_in[10];
    const float* Wv  = (const float*)d_in[11];
    const float* bv  = (const float*)d_in[12];
    const float* Wf  = (const float*)d_in[13];
    const float* bf  = (const float*)d_in[14];
    float* out = (float*)d_out;

    float *Qd, *Kd, *Vd, *CTXd;
    cudaGetSymbolAddress((void**)&Qd, g_Q);
    cudaGetSymbolAddress((void**)&Kd, g_K);
    cudaGetSymbolAddress((void**)&Vd, g_V);
    cudaGetSymbolAddress((void**)&CTXd, g_ctx);
    __nv_bfloat16 *xh, *xl, *wh, *wl;
    cudaGetSymbolAddress((void**)&xh, g_xh);
    cudaGetSymbolAddress((void**)&xl, g_xl);
    cudaGetSymbolAddress((void**)&wh, g_wh);
    cudaGetSymbolAddress((void**)&wl, g_wl);

    setup_kernel<<<1, 32>>>(mu, lam, g1, g2, th1, th2);

    const int NX4 = (BB * TT * DD) / 4;
    const int NW4 = (DD * DD) / 4;
    cvt_split<<<(NX4 + 255) / 256, 256>>>(x, xh, xl, NX4);
    cvt_split<<<(NW4 + 255) / 256, 256>>>(Wq, wh + 0 * DD * DD, wl + 0 * DD * DD, NW4);
    cvt_split<<<(NW4 + 255) / 256, 256>>>(Wk, wh + 1 * DD * DD, wl + 1 * DD * DD, NW4);
    cvt_split<<<(NW4 + 255) / 256, 256>>>(Wv, wh + 2 * DD * DD, wl + 2 * DD * DD, NW4);
    cvt_split<<<(NW4 + 255) / 256, 256>>>(Wf, wh + 3 * DD * DD, wl + 3 * DD * DD, NW4);

    cudaFuncSetAttribute(gemm_mma, cudaFuncAttributeMaxDynamicSharedMemorySize, G_SMEM);
    dim3 ggrid(DD / 128, (BB * TT) / 128);
    gemm_mma<<<ggrid, 256, G_SMEM>>>(xh, xl, wh + 0 * DD * DD, wl + 0 * DD * DD, bq, Qd);
    gemm_mma<<<ggrid, 256, G_SMEM>>>(xh, xl, wh + 1 * DD * DD, wl + 1 * DD * DD, bk, Kd);
    gemm_mma<<<ggrid, 256, G_SMEM>>>(xh, xl, wh + 2 * DD * DD, wl + 2 * DD * DD, bv, Vd);

    cudaFuncSetAttribute(flash_kernel, cudaFuncAttributeMaxDynamicSharedMemorySize,
                         FL_SMEM_FLOATS * sizeof(float));
    dim3 fgrid(TT / 128, NHH, BB);
    flash_kernel<<<fgrid, 128, FL_SMEM_FLOATS * sizeof(float)>>>();

    prefix_kernel<<<BB * NHH, 64>>>();

    dim3 pvgrid(TT / 64, NHH, BB);
    pv_kernel<<<pvgrid, 256>>>();

    cvt_split<<<(NX4 + 255) / 256, 256>>>(CTXd, xh, xl, NX4);
    gemm_mma<<<ggrid, 256, G_SMEM>>>(xh, xl, wh + 3 * DD * DD, wl + 3 * DD * DD, bf, out);
}

// round 5
// speedup vs baseline: 1.9238x; 1.4643x over previous
#include <cuda_runtime.h>
#include <cuda_bf16.h>
#include <math.h>
#include <stdint.h>

#define BB 4
#define TT 2048
#define NHH 16
#define HCC 64
#define DD 1024
#define RHH 4
#define SHH 6
#define MAXL 100

// ---------------- scratch (device globals: allowed) ----------------
__device__ float g_Q[BB * TT * DD];
__device__ float g_K[BB * TT * DD];
__device__ float g_V[BB * TT * DD];
__device__ float g_ctx[BB * TT * DD];
__device__ float g_PS[BB * TT * DD];
__device__ float g_Pval[NHH][MAXL + 1];
__device__ float g_wmix[2];  // [0]=w, [1]=1-w

// bf16 split operand buffers
__device__ __nv_bfloat16 g_xh[BB * TT * DD];
__device__ __nv_bfloat16 g_xl[BB * TT * DD];
__device__ __nv_bfloat16 g_wh[4 * DD * DD];
__device__ __nv_bfloat16 g_wl[4 * DD * DD];
__device__ __nv_bfloat16 g_Qh[BB * TT * DD];
__device__ __nv_bfloat16 g_Ql[BB * TT * DD];
__device__ __nv_bfloat16 g_Kh[BB * TT * DD];
__device__ __nv_bfloat16 g_Kl[BB * TT * DD];
__device__ __nv_bfloat16 g_Vh[BB * TT * DD];
__device__ __nv_bfloat16 g_Vl[BB * TT * DD];

// ---------------- PTX helpers (baseline ISA only: sm_80-class) ----------------
__device__ __forceinline__ uint32_t smem_u32(const void* p) {
    uint32_t a;
    asm("{ .reg .u64 t; cvta.to.shared.u64 t, %1; cvt.u32.u64 %0, t; }" : "=r"(a) : "l"(p));
    return a;
}

#define CP_ASYNC16(dst, src) \
    asm volatile("cp.async.cg.shared.global [%0], [%1], 16;" :: "r"(dst), "l"(src))
#define CP_COMMIT() asm volatile("cp.async.commit_group;")
#define CP_WAIT1() asm volatile("cp.async.wait_group 1;")
#define CP_WAIT0() asm volatile("cp.async.wait_group 0;")

#define LDM_X4(r0, r1, r2, r3, addr) \
    asm volatile("ldmatrix.sync.aligned.m8n8.x4.shared.b16 {%0,%1,%2,%3}, [%4];" \
                 : "=r"(r0), "=r"(r1), "=r"(r2), "=r"(r3) : "r"(addr))

#define LDM_X4_T(r0, r1, r2, r3, addr) \
    asm volatile("ldmatrix.sync.aligned.m8n8.x4.trans.shared.b16 {%0,%1,%2,%3}, [%4];" \
                 : "=r"(r0), "=r"(r1), "=r"(r2), "=r"(r3) : "r"(addr))

#define MMA16816(c0, c1, c2, c3, a0, a1, a2, a3, b0, b1) \
    asm volatile("mma.sync.aligned.m16n8k16.row.col.f32.bf16.bf16.f32 " \
                 "{%0,%1,%2,%3}, {%4,%5,%6,%7}, {%8,%9}, {%0,%1,%2,%3};" \
                 : "+f"(c0), "+f"(c1), "+f"(c2), "+f"(c3) \
                 : "r"(a0), "r"(a1), "r"(a2), "r"(a3), "r"(b0), "r"(b1))

__device__ __forceinline__ uint32_t packbf2(float a, float b) {
    __nv_bfloat162 t = __floats2bfloat162_rn(a, b);
    return *(uint32_t*)&t;
}
__device__ __forceinline__ uint32_t packlo2(float a, float b, uint32_t hi) {
    __nv_bfloat162 hv = *(__nv_bfloat162*)&hi;
    return packbf2(a - __bfloat162float(hv.x), b - __bfloat162float(hv.y));
}

// ---------------- setup: Pval table + mix weight ----------------
__global__ void setup_kernel(const float* __restrict__ mu,
                             const float* __restrict__ lam,
                             const float* __restrict__ g1,
                             const float* __restrict__ g2,
                             const float* __restrict__ th1,
                             const float* __restrict__ th2) {
    int h = threadIdx.x;
    if (h == 0) {
        float w = 1.0f / (1.0f + __expf(-mu[0]));
        g_wmix[0] = w;
        g_wmix[1] = 1.0f - w;
    }
    if (h < NHH) {
        float base, theta = 0.0f;
        int kind;
        if (h < RHH) { base = lam[h]; kind = 0; }
        else if (h < RHH + SHH) { base = g1[h - RHH]; theta = th1[h - RHH]; kind = 1; }
        else { base = g2[h - RHH - SHH]; theta = th2[h - RHH - SHH]; kind = 2; }
        float p = 1.0f;
        g_Pval[h][0] = 0.0f;
        for (int L = 1; L <= MAXL; L++) {
            p *= base;
            float v = p;
            if (kind == 1) v *= sinf(theta * (float)L);
            else if (kind == 2) v *= cosf(theta * (float)L);
            g_Pval[h][L] = v;
        }
    }
}

// ---------------- fp32 -> bf16 hi/lo split ----------------
__global__ __launch_bounds__(256) void cvt_split(const float* __restrict__ in,
                                                 __nv_bfloat16* __restrict__ hi,
                                                 __nv_bfloat16* __restrict__ lo,
                                                 int n4) {
    int i = blockIdx.x * blockDim.x + threadIdx.x;
    if (i >= n4) return;
    float4 v = ((const float4*)in)[i];
    __nv_bfloat16 h0 = __float2bfloat16(v.x);
    __nv_bfloat16 h1 = __float2bfloat16(v.y);
    __nv_bfloat16 h2 = __float2bfloat16(v.z);
    __nv_bfloat16 h3 = __float2bfloat16(v.w);
    __nv_bfloat16 l0 = __float2bfloat16(v.x - __bfloat162float(h0));
    __nv_bfloat16 l1 = __float2bfloat16(v.y - __bfloat162float(h1));
    __nv_bfloat16 l2 = __float2bfloat16(v.z - __bfloat162float(h2));
    __nv_bfloat16 l3 = __float2bfloat16(v.w - __bfloat162float(h3));
    __nv_bfloat162 hp0 = __halves2bfloat162(h0, h1);
    __nv_bfloat162 hp1 = __halves2bfloat162(h2, h3);
    __nv_bfloat162 lp0 = __halves2bfloat162(l0, l1);
    __nv_bfloat162 lp1 = __halves2bfloat162(l2, l3);
    uint2 hw, lw;
    hw.x = *(uint32_t*)&hp0; hw.y = *(uint32_t*)&hp1;
    lw.x = *(uint32_t*)&lp0; lw.y = *(uint32_t*)&lp1;
    ((uint2*)hi)[i] = hw;
    ((uint2*)lo)[i] = lw;
}

// ---------------- HMMA bf16x2 GEMM: C = A @ W^T + bias (+ optional split out) ----
#define G_TILE_B 10240          // 128*40*2
#define G_STAGE_B (4 * G_TILE_B)
#define G_SMEM (2 * G_STAGE_B)  // 81920

__global__ __launch_bounds__(256) void gemm_mma(
    const __nv_bfloat16* __restrict__ Ah, const __nv_bfloat16* __restrict__ Al,
    const __nv_bfloat16* __restrict__ Bh, const __nv_bfloat16* __restrict__ Bl,
    const float* __restrict__ bias, float* __restrict__ C,
    __nv_bfloat16* __restrict__ Chi, __nv_bfloat16* __restrict__ Clo) {
    extern __shared__ char gsm[];
    const uint32_t smBase = smem_u32(gsm);

    const int tid = threadIdx.x;
    const int lane = tid & 31;
    const int wid = tid >> 5;
    const int wm = wid & 3;
    const int wn = wid >> 2;
    const int m0 = blockIdx.y * 128;
    const int n0 = blockIdx.x * 128;

    const __nv_bfloat16* srcs[4];
    srcs[0] = Ah + (size_t)m0 * DD;
    srcs[1] = Al + (size_t)m0 * DD;
    srcs[2] = Bh + (size_t)n0 * DD;
    srcs[3] = Bl + (size_t)n0 * DD;

    const int ch0 = tid * 2;
    const int lrow0 = ch0 >> 2, lcol0 = (ch0 & 3) * 8;
    const int lrow1 = (ch0 + 1) >> 2, lcol1 = ((ch0 + 1) & 3) * 8;

    float c[2][8][4];
#pragma unroll
    for (int mi = 0; mi < 2; mi++)
#pragma unroll
        for (int ni = 0; ni < 8; ni++)
#pragma unroll
            for (int r = 0; r < 4; r++) c[mi][ni][r] = 0.0f;

    {
        uint32_t sb = smBase;
#pragma unroll
        for (int t = 0; t < 4; t++) {
            CP_ASYNC16(sb + t * G_TILE_B + lrow0 * 80 + lcol0 * 2,
                       srcs[t] + (size_t)lrow0 * DD + lcol0);
            CP_ASYNC16(sb + t * G_TILE_B + lrow1 * 80 + lcol1 * 2,
                       srcs[t] + (size_t)lrow1 * DD + lcol1);
        }
        CP_COMMIT();
    }

    const uint32_t aOff = (uint32_t)((wm * 32 + (lane & 15)) * 80 + ((lane >> 4) * 8) * 2);
    const uint32_t bOff = (uint32_t)((wn * 64 + ((lane >> 4) & 1) * 8 + (lane & 7)) * 80 +
                                     (((lane >> 3) & 1) * 8) * 2);

    const int NIT = DD / 32;
    for (int it = 0; it < NIT; it++) {
        if (it + 1 < NIT) {
            uint32_t sb = smBase + ((it + 1) & 1) * G_STAGE_B;
            int k0 = (it + 1) * 32;
#pragma unroll
            for (int t = 0; t < 4; t++) {
                CP_ASYNC16(sb + t * G_TILE_B + lrow0 * 80 + lcol0 * 2,
                           srcs[t] + (size_t)lrow0 * DD + k0 + lcol0);
                CP_ASYNC16(sb + t * G_TILE_B + lrow1 * 80 + lcol1 * 2,
                           srcs[t] + (size_t)lrow1 * DD + k0 + lcol1);
            }
            CP_COMMIT();
            CP_WAIT1();
        } else {
            CP_WAIT0();
        }
        __syncthreads();

        const uint32_t aBase = smBase + (it & 1) * G_STAGE_B;
        const uint32_t bBase = aBase + 2 * G_TILE_B;
#pragma unroll
        for (int kk = 0; kk < 2; kk++) {
            uint32_t ah[2][4], al[2][4];
#pragma unroll
            for (int mi = 0; mi < 2; mi++) {
                uint32_t a = aBase + aOff + (uint32_t)(mi * 16 * 80 + kk * 32);
                LDM_X4(ah[mi][0], ah[mi][1], ah[mi][2], ah[mi][3], a);
                LDM_X4(al[mi][0], al[mi][1], al[mi][2], al[mi][3], a + G_TILE_B);
            }
            uint32_t bh[8][2], bl[8][2];
#pragma unroll
            for (int nq = 0; nq < 4; nq++) {
                uint32_t a = bBase + bOff + (uint32_t)(nq * 16 * 80 + kk * 32);
                LDM_X4(bh[nq * 2][0], bh[nq * 2][1], bh[nq * 2 + 1][0], bh[nq * 2 + 1][1], a);
                LDM_X4(bl[nq * 2][0], bl[nq * 2][1], bl[nq * 2 + 1][0], bl[nq * 2 + 1][1],
                       a + G_TILE_B);
            }
#pragma unroll
            for (int mi = 0; mi < 2; mi++)
#pragma unroll
                for (int ni = 0; ni < 8; ni++) {
                    float* cc = c[mi][ni];
                    MMA16816(cc[0], cc[1], cc[2], cc[3],
                             ah[mi][0], ah[mi][1], ah[mi][2], ah[mi][3],
                             bh[ni][0], bh[ni][1]);
                    MMA16816(cc[0], cc[1], cc[2], cc[3],
                             ah[mi][0], ah[mi][1], ah[mi][2], ah[mi][3],
                             bl[ni][0], bl[ni][1]);
                    MMA16816(cc[0], cc[1], cc[2], cc[3],
                             al[mi][0], al[mi][1], al[mi][2], al[mi][3],
                             bh[ni][0], bh[ni][1]);
                }
        }
        __syncthreads();
    }

    // ---- epilogue: fp32 + optional bf16 hi/lo split ----
#pragma unroll
    for (int mi = 0; mi < 2; mi++) {
        int row = m0 + wm * 32 + mi * 16 + (lane >> 2);
#pragma unroll
        for (int ni = 0; ni < 8; ni++) {
            int col = n0 + wn * 64 + ni * 8 + (lane & 3) * 2;
            float b0 = bias[col], b1 = bias[col + 1];
            float v00 = c[mi][ni][0] + b0, v01 = c[mi][ni][1] + b1;
            float v10 = c[mi][ni][2] + b0, v11 = c[mi][ni][3] + b1;
            *(float2*)(C + (size_t)row * DD + col) = make_float2(v00, v01);
            *(float2*)(C + (size_t)(row + 8) * DD + col) = make_float2(v10, v11);
            if (Chi != nullptr) {
                uint32_t h0 = packbf2(v00, v01);
                uint32_t l0v = packlo2(v00, v01, h0);
                uint32_t h1 = packbf2(v10, v11);
                uint32_t l1v = packlo2(v10, v11, h1);
                *(uint32_t*)(Chi + (size_t)row * DD + col) = h0;
                *(uint32_t*)(Clo + (size_t)row * DD + col) = l0v;
                *(uint32_t*)(Chi + (size_t)(row + 8) * DD + col) = h1;
                *(uint32_t*)(Clo + (size_t)(row + 8) * DD + col) = l1v;
            }
        }
    }
}

// ---------------- HMMA flash attention: ctx = (1-w) * softmax(Q K^T) V ----------------
// 8 warps, q-tile 128 (16 rows/warp), k-tile 64, 2-stage cp.async K/V pipeline.
// smem (bf16, stride 72): Qh[128] Ql[128] | 2 stages x (Kh[64] Kl[64] Vh[64] Vl[64])
#define FS 72
#define FL_QL_B 18432            // 128*72*2
#define FL_KV_B 36864
#define FL_KV_STG_B 36864        // 4 * 64*72*2
#define FL_ARR_B 9216            // 64*72*2
#define FL_SMEM_B (FL_KV_B + 2 * FL_KV_STG_B)  // 110592

__global__ __launch_bounds__(256) void flash_mma() {
    extern __shared__ char fsmem[];
    const uint32_t smB = smem_u32(fsmem);
    const int tid = threadIdx.x;
    const int lane = tid & 31, wid = tid >> 5;
    const int b = blockIdx.z, h = blockIdx.y, q0 = blockIdx.x * 128;
    const size_t hOff = (size_t)h * HCC;

    const __nv_bfloat16* kvsrc[4] = {
        g_Kh + (size_t)(b * TT) * DD + hOff,
        g_Kl + (size_t)(b * TT) * DD + hOff,
        g_Vh + (size_t)(b * TT) * DD + hOff,
        g_Vl + (size_t)(b * TT) * DD + hOff };

    // prologue group0: Q (both arrays) + KV stage0
    {
        const __nv_bfloat16* qsrc[2] = {
            g_Qh + (size_t)(b * TT + q0) * DD + hOff,
            g_Ql + (size_t)(b * TT + q0) * DD + hOff };
#pragma unroll
        for (int i = 0; i < 8; i++) {
            int cck = tid + i * 256;
            int arr = cck >> 10, r = (cck >> 3) & 127, c8 = (cck & 7) * 8;
            CP_ASYNC16(smB + arr * FL_QL_B + r * (FS * 2) + c8 * 2,
                       qsrc[arr] + (size_t)r * DD + c8);
        }
#pragma unroll
        for (int i = 0; i < 8; i++) {
            int cck = tid + i * 256;
            int arr = cck >> 9, r = (cck >> 3) & 63, c8 = (cck & 7) * 8;
            CP_ASYNC16(smB + FL_KV_B + arr * FL_ARR_B + r * (FS * 2) + c8 * 2,
                       kvsrc[arr] + (size_t)r * DD + c8);
        }
        CP_COMMIT();
    }

    // lane-derived fragment address pieces
    const int r0 = wid * 16;
    const int lrQ = (lane & 7) + ((lane >> 3) & 1) * 8;   // also V rows
    const int lcQ = (lane >> 4) * 8;                       // also V cols
    const int lrK = (lane & 7) + (lane >> 4) * 8;
    const int lcK = ((lane >> 3) & 1) * 8;
    const uint32_t qbase = smB + (uint32_t)((r0 + lrQ) * FS + lcQ) * 2;
    const uint32_t kOff = (uint32_t)(lrK * FS + lcK) * 2;
    const uint32_t vOff = (uint32_t)(lrQ * FS + lcQ) * 2;

    float m0 = -3.0e38f, m1 = -3.0e38f, l0 = 0.0f, l1 = 0.0f;
    float o[8][4];
#pragma unroll
    for (int i = 0; i < 8; i++)
#pragma unroll
        for (int j = 0; j < 4; j++) o[i][j] = 0.0f;
    uint32_t qah[4][4], qal[4][4];

    const int NKT = TT / 64;  // 32
    for (int kt = 0; kt < NKT; kt++) {
        if (kt + 1 < NKT) {
            uint32_t sb = smB + FL_KV_B + ((kt + 1) & 1) * FL_KV_STG_B;
            int t0 = (kt + 1) * 64;
#pragma unroll
            for (int i = 0; i < 8; i++) {
                int cck = tid + i * 256;
                int arr = cck >> 9, r = (cck >> 3) & 63, c8 = (cck & 7) * 8;
                CP_ASYNC16(sb + arr * FL_ARR_B + r * (FS * 2) + c8 * 2,
                           kvsrc[arr] + (size_t)(t0 + r) * DD + c8);
            }
            CP_COMMIT();
            CP_WAIT1();
        } else {
            CP_WAIT0();
        }
        __syncthreads();

        if (kt == 0) {
#pragma unroll
            for (int kk = 0; kk < 4; kk++) {
                LDM_X4(qah[kk][0], qah[kk][1], qah[kk][2], qah[kk][3], qbase + kk * 32);
                LDM_X4(qal[kk][0], qal[kk][1], qal[kk][2], qal[kk][3],
                       qbase + FL_QL_B + kk * 32);
            }
        }

        const uint32_t stg = smB + FL_KV_B + (kt & 1) * FL_KV_STG_B;

        // ---- S = Q K^T (16 x 64 per warp), 3-mma split ----
        float s[8][4];
#pragma unroll
        for (int i = 0; i < 8; i++)
#pragma unroll
            for (int j = 0; j < 4; j++) s[i][j] = 0.0f;
#pragma unroll
        for (int kk = 0; kk < 4; kk++) {
            uint32_t kb[8][2], kl[8][2];
#pragma unroll
            for (int p = 0; p < 4; p++) {
                uint32_t a = stg + kOff + (uint32_t)(p * 16 * FS + kk * 16) * 2;
                LDM_X4(kb[p * 2][0], kb[p * 2][1], kb[p * 2 + 1][0], kb[p * 2 + 1][1], a);
                LDM_X4(kl[p * 2][0], kl[p * 2][1], kl[p * 2 + 1][0], kl[p * 2 + 1][1],
                       a + FL_ARR_B);
            }
#pragma unroll
            for (int nj = 0; nj < 8; nj++) {
                float* ss = s[nj];
                MMA16816(ss[0], ss[1], ss[2], ss[3],
                         qah[kk][0], qah[kk][1], qah[kk][2], qah[kk][3],
                         kb[nj][0], kb[nj][1]);
                MMA16816(ss[0], ss[1], ss[2], ss[3],
                         qah[kk][0], qah[kk][1], qah[kk][2], qah[kk][3],
                         kl[nj][0], kl[nj][1]);
                MMA16816(ss[0], ss[1], ss[2], ss[3],
                         qal[kk][0], qal[kk][1], qal[kk][2], qal[kk][3],
                         kb[nj][0], kb[nj][1]);
            }
        }

        // ---- online softmax (rows r=lane>>2 and r+8; group-of-4 reduce) ----
        float mr0 = s[0][0], mr1 = s[0][2];
#pragma unroll
        for (int nj = 0; nj < 8; nj++) {
            mr0 = fmaxf(mr0, fmaxf(s[nj][0], s[nj][1]));
            mr1 = fmaxf(mr1, fmaxf(s[nj][2], s[nj][3]));
        }
        mr0 = fmaxf(mr0, __shfl_xor_sync(0xffffffffu, mr0, 1, 4));
        mr0 = fmaxf(mr0, __shfl_xor_sync(0xffffffffu, mr0, 2, 4));
        mr1 = fmaxf(mr1, __shfl_xor_sync(0xffffffffu, mr1, 1, 4));
        mr1 = fmaxf(mr1, __shfl_xor_sync(0xffffffffu, mr1, 2, 4));
        float mn0 = fmaxf(m0, mr0), mn1 = fmaxf(m1, mr1);
        float cor0 = __expf(m0 - mn0), cor1 = __expf(m1 - mn1);
        m0 = mn0; m1 = mn1;
        float rs0 = 0.0f, rs1 = 0.0f;
#pragma unroll
        for (int nj = 0; nj < 8; nj++) {
            s[nj][0] = __expf(s[nj][0] - mn0);
            s[nj][1] = __expf(s[nj][1] - mn0);
            s[nj][2] = __expf(s[nj][2] - mn1);
            s[nj][3] = __expf(s[nj][3] - mn1);
            rs0 += s[nj][0] + s[nj][1];
            rs1 += s[nj][2] + s[nj][3];
        }
        rs0 += __shfl_xor_sync(0xffffffffu, rs0, 1, 4);
        rs0 += __shfl_xor_sync(0xffffffffu, rs0, 2, 4);
        rs1 += __shfl_xor_sync(0xffffffffu, rs1, 1, 4);
        rs1 += __shfl_xor_sync(0xffffffffu, rs1, 2, 4);
        l0 = l0 * cor0 + rs0;
        l1 = l1 * cor1 + rs1;
#pragma unroll
        for (int nd = 0; nd < 8; nd++) {
            o[nd][0] *= cor0; o[nd][1] *= cor0;
            o[nd][2] *= cor1; o[nd][3] *= cor1;
        }

        // ---- repack P (C-frag -> A-frag) with hi/lo split ----
        uint32_t pah[4][4], pal[4][4];
#pragma unroll
        for (int kk = 0; kk < 4; kk++) {
            pah[kk][0] = packbf2(s[2 * kk][0], s[2 * kk][1]);
            pah[kk][1] = packbf2(s[2 * kk][2], s[2 * kk][3]);
            pah[kk][2] = packbf2(s[2 * kk + 1][0], s[2 * kk + 1][1]);
            pah[kk][3] = packbf2(s[2 * kk + 1][2], s[2 * kk + 1][3]);
            pal[kk][0] = packlo2(s[2 * kk][0], s[2 * kk][1], pah[kk][0]);
            pal[kk][1] = packlo2(s[2 * kk][2], s[2 * kk][3], pah[kk][1]);
            pal[kk][2] = packlo2(s[2 * kk + 1][0], s[2 * kk + 1][1], pah[kk][2]);
            pal[kk][3] = packlo2(s[2 * kk + 1][2], s[2 * kk + 1][3], pah[kk][3]);
        }

        // ---- O += P V (16 x 64 per warp), 3-mma split ----
        const uint32_t vbaseH = stg + 2 * FL_ARR_B + vOff;
#pragma unroll
        for (int kk = 0; kk < 4; kk++) {
            uint32_t vb[8][2], vl[8][2];
#pragma unroll
            for (int q = 0; q < 4; q++) {
                uint32_t a = vbaseH + (uint32_t)(kk * 16 * FS + q * 16) * 2;
                LDM_X4_T(vb[q * 2][0], vb[q * 2][1], vb[q * 2 + 1][0], vb[q * 2 + 1][1], a);
                LDM_X4_T(vl[q * 2][0], vl[q * 2][1], vl[q * 2 + 1][0], vl[q * 2 + 1][1],
                         a + FL_ARR_B);
            }
#pragma unroll
            for (int nd = 0; nd < 8; nd++) {
                float* oo = o[nd];
                MMA16816(oo[0], oo[1], oo[2], oo[3],
                         pah[kk][0], pah[kk][1], pah[kk][2], pah[kk][3],
                         vb[nd][0], vb[nd][1]);
                MMA16816(oo[0], oo[1], oo[2], oo[3],
                         pah[kk][0], pah[kk][1], pah[kk][2], pah[kk][3],
                         vl[nd][0], vl[nd][1]);
                MMA16816(oo[0], oo[1], oo[2], oo[3],
                         pal[kk][0], pal[kk][1], pal[kk][2], pal[kk][3],
                         vb[nd][0], vb[nd][1]);
            }
        }
        __syncthreads();
    }

    // ---- epilogue: ctx = (1-w) * O / l ----
    float w1 = g_wmix[1];
    float inv0 = w1 / l0, inv1 = w1 / l1;
    int row0 = q0 + r0 + (lane >> 2);
    float* dst0 = g_ctx + (size_t)(b * TT + row0) * DD + hOff + (lane & 3) * 2;
    float* dst1 = dst0 + 8 * DD;
#pragma unroll
    for (int nd = 0; nd < 8; nd++) {
        *(float2*)(dst0 + nd * 8) = make_float2(o[nd][0] * inv0, o[nd][1] * inv0);
        *(float2*)(dst1 + nd * 8) = make_float2(o[nd][2] * inv1, o[nd][3] * inv1);
    }
}

// ---------------- prefix sums of V along t, per (b,h,c) ----------------
__global__ void prefix_kernel() {
    int b = blockIdx.x >> 4;
    int h = blockIdx.x & 15;
    int c = threadIdx.x;
    const float* vp = g_V + ((size_t)(b * TT)) * DD + h * HCC + c;
    float* ps = g_PS + ((size_t)(b * TT)) * DD + h * HCC + c;
    float run = 0.0f;
    for (int t = 0; t < TT; t++) {
        run += vp[(size_t)t * DD];
        ps[(size_t)t * DD] = run;
    }
}

// ---------------- PV: out_split = ctx + w * (P @ V) via 99-tap conv + prefix ----------------
__global__ __launch_bounds__(256) void pv_kernel() {
    __shared__ float Vw[162 * 64];
    __shared__ float Pv[MAXL + 1];
    int b = blockIdx.z, h = blockIdx.y;
    int q0 = blockIdx.x * 64;
    int tid = threadIdx.x;
    if (tid <= MAXL) Pv[tid] = g_Pval[h][tid];
    for (int idx = tid; idx < 162 * 64; idx += 256) {
        int r = idx >> 6, c = idx & 63;
        int tg = q0 - 99 + r;
        Vw[idx] = (tg >= 0) ? g_V[((size_t)(b * TT + tg)) * DD + h * HCC + c] : 0.0f;
    }
    __syncthreads();
    int c = tid & 63, qq = tid >> 6;
    float w = g_wmix[0];
#pragma unroll 1
    for (int ii = 0; ii < 16; ii++) {
        int ql = qq * 16 + ii;
        int qg = q0 + ql;
        float acc = 0.0f;
        int jmax = min(99, qg);
        for (int j = 1; j <= jmax; j++)
            acc += Pv[j] * Vw[((ql - j + 99) << 6) | c];
        if (qg >= 100)
            acc += Pv[MAXL] * g_PS[((size_t)(b * TT + qg - 100)) * DD + h * HCC + c];
        size_t oi = ((size_t)(b * TT + qg)) * DD + h * HCC + c;
        float outv = g_ctx[oi] + w * acc;
        __nv_bfloat16 hh = __float2bfloat16(outv);
        g_xh[oi] = hh;
        g_xl[oi] = __float2bfloat16(outv - __bfloat162float(hh));
    }
}

// ---------------- launch ----------------
extern "C" void kernel_launch(void* const* d_in, const int* in_sizes, int n_in,
                              void* d_out, int out_size) {
    const float* x   = (const float*)d_in[0];
    const float* mu  = (const float*)d_in[1];
    const float* lam = (const float*)d_in[2];
    const float* g1  = (const float*)d_in[3];
    const float* g2  = (const float*)d_in[4];
    const float* th1 = (const float*)d_in[5];
    const float* th2 = (const float*)d_in[6];
    const float* Wq  = (const float*)d_in[7];
    const float* bq  = (const float*)d_in[8];
    const float* Wk  = (const float*)d_in[9];
    const float* bk  = (const float*)d_in[10];
    const float* Wv  = (const float*)d_in[11];
    const float* bv  = (const float*)d_in[12];
    const float* Wf  = (const float*)d_in[13];
    const float* bf  = (const float*)d_in[14];
    float* out = (float*)d_out;

    float *Qd, *Kd, *Vd, *CTXd;
    cudaGetSymbolAddress((void**)&Qd, g_Q);
    cudaGetSymbolAddress((void**)&Kd, g_K);
    cudaGetSymbolAddress((void**)&Vd, g_V);
    cudaGetSymbolAddress((void**)&CTXd, g_ctx);
    __nv_bfloat16 *xh, *xl, *wh, *wl, *qh, *ql, *kh, *kl, *vh, *vl;
    cudaGetSymbolAddress((void**)&xh, g_xh);
    cudaGetSymbolAddress((void**)&xl, g_xl);
    cudaGetSymbolAddress((void**)&wh, g_wh);
    cudaGetSymbolAddress((void**)&wl, g_wl);
    cudaGetSymbolAddress((void**)&qh, g_Qh);
    cudaGetSymbolAddress((void**)&ql, g_Ql);
    cudaGetSymbolAddress((void**)&kh, g_Kh);
    cudaGetSymbolAddress((void**)&kl, g_Kl);
    cudaGetSymbolAddress((void**)&vh, g_Vh);
    cudaGetSymbolAddress((void**)&vl, g_Vl);

    setup_kernel<<<1, 32>>>(mu, lam, g1, g2, th1, th2);

    const int NX4 = (BB * TT * DD) / 4;
    const int NW4 = (DD * DD) / 4;
    cvt_split<<<(NX4 + 255) / 256, 256>>>(x, xh, xl, NX4);
    cvt_split<<<(NW4 + 255) / 256, 256>>>(Wq, wh + 0 * DD * DD, wl + 0 * DD * DD, NW4);
    cvt_split<<<(NW4 + 255) / 256, 256>>>(Wk, wh + 1 * DD * DD, wl + 1 * DD * DD, NW4);
    cvt_split<<<(NW4 + 255) / 256, 256>>>(Wv, wh + 2 * DD * DD, wl + 2 * DD * DD, NW4);
    cvt_split<<<(NW4 + 255) / 256, 256>>>(Wf, wh + 3 * DD * DD, wl + 3 * DD * DD, NW4);

    cudaFuncSetAttribute(gemm_mma, cudaFuncAttributeMaxDynamicSharedMemorySize, G_SMEM);
    dim3 ggrid(DD / 128, (BB * TT) / 128);
    gemm_mma<<<ggrid, 256, G_SMEM>>>(xh, xl, wh + 0 * DD * DD, wl + 0 * DD * DD, bq, Qd, qh, ql);
    gemm_mma<<<ggrid, 256, G_SMEM>>>(xh, xl, wh + 1 * DD * DD, wl + 1 * DD * DD, bk, Kd, kh, kl);
    gemm_mma<<<ggrid, 256, G_SMEM>>>(xh, xl, wh + 2 * DD * DD, wl + 2 * DD * DD, bv, Vd, vh, vl);

    cudaFuncSetAttribute(flash_mma, cudaFuncAttributeMaxDynamicSharedMemorySize, FL_SMEM_B);
    dim3 fgrid(TT / 128, NHH, BB);
    flash_mma<<<fgrid, 256, FL_SMEM_B>>>();

    prefix_kernel<<<BB * NHH, 64>>>();

    dim3 pvgrid(TT / 64, NHH, BB);
    pv_kernel<<<pvgrid, 256>>>();

    gemm_mma<<<ggrid, 256, G_SMEM>>>(xh, xl, wh + 3 * DD * DD, wl + 3 * DD * DD, bf, out,
                                     nullptr, nullptr);
}

// round 8
// speedup vs baseline: 2.9478x; 1.5323x over previous
#include <cuda_runtime.h>
#include <cuda_bf16.h>
#include <math.h>
#include <stdint.h>

#define BB 4
#define TT 2048
#define NHH 16
#define HCC 64
#define DD 1024
#define RHH 4
#define SHH 6
#define MAXL 100

// ---------------- scratch (device globals: allowed) ----------------
__device__ float g_V[BB * TT * DD];
__device__ float g_ctx[BB * TT * DD];
__device__ float g_PS[BB * TT * DD];
__device__ float g_Pval[NHH][MAXL + 1];
__device__ float g_wmix[2];  // [0]=w, [1]=1-w

// bf16 split operand buffers
__device__ __nv_bfloat16 g_xh[BB * TT * DD];
__device__ __nv_bfloat16 g_xl[BB * TT * DD];
__device__ __nv_bfloat16 g_wh[4 * DD * DD];
__device__ __nv_bfloat16 g_wl[4 * DD * DD];
__device__ __nv_bfloat16 g_Qh[BB * TT * DD];
__device__ __nv_bfloat16 g_Ql[BB * TT * DD];
__device__ __nv_bfloat16 g_Kh[BB * TT * DD];
__device__ __nv_bfloat16 g_Kl[BB * TT * DD];
__device__ __nv_bfloat16 g_Vh[BB * TT * DD];
__device__ __nv_bfloat16 g_Vl[BB * TT * DD];

// ---------------- PTX helpers (baseline ISA only: sm_80-class) ----------------
__device__ __forceinline__ uint32_t smem_u32(const void* p) {
    uint32_t a;
    asm("{ .reg .u64 t; cvta.to.shared.u64 t, %1; cvt.u32.u64 %0, t; }" : "=r"(a) : "l"(p));
    return a;
}

#define CP_ASYNC16(dst, src) \
    asm volatile("cp.async.cg.shared.global [%0], [%1], 16;" :: "r"(dst), "l"(src))
#define CP_COMMIT() asm volatile("cp.async.commit_group;")
#define CP_WAIT1() asm volatile("cp.async.wait_group 1;")
#define CP_WAIT0() asm volatile("cp.async.wait_group 0;")

#define LDM_X4(r0, r1, r2, r3, addr) \
    asm volatile("ldmatrix.sync.aligned.m8n8.x4.shared.b16 {%0,%1,%2,%3}, [%4];" \
                 : "=r"(r0), "=r"(r1), "=r"(r2), "=r"(r3) : "r"(addr))

#define LDM_X4_T(r0, r1, r2, r3, addr) \
    asm volatile("ldmatrix.sync.aligned.m8n8.x4.trans.shared.b16 {%0,%1,%2,%3}, [%4];" \
                 : "=r"(r0), "=r"(r1), "=r"(r2), "=r"(r3) : "r"(addr))

#define MMA16816(c0, c1, c2, c3, a0, a1, a2, a3, b0, b1) \
    asm volatile("mma.sync.aligned.m16n8k16.row.col.f32.bf16.bf16.f32 " \
                 "{%0,%1,%2,%3}, {%4,%5,%6,%7}, {%8,%9}, {%0,%1,%2,%3};" \
                 : "+f"(c0), "+f"(c1), "+f"(c2), "+f"(c3) \
                 : "r"(a0), "r"(a1), "r"(a2), "r"(a3), "r"(b0), "r"(b1))

__device__ __forceinline__ uint32_t packbf2(float a, float b) {
    __nv_bfloat162 t = __floats2bfloat162_rn(a, b);
    return *(uint32_t*)&t;
}
__device__ __forceinline__ uint32_t packlo2(float a, float b, uint32_t hi) {
    __nv_bfloat162 hv = *(__nv_bfloat162*)&hi;
    return packbf2(a - __bfloat162float(hv.x), b - __bfloat162float(hv.y));
}

// ---------------- setup: Pval table + mix weight ----------------
__global__ void setup_kernel(const float* __restrict__ mu,
                             const float* __restrict__ lam,
                             const float* __restrict__ g1,
                             const float* __restrict__ g2,
                             const float* __restrict__ th1,
                             const float* __restrict__ th2) {
    int h = threadIdx.x;
    if (h == 0) {
        float w = 1.0f / (1.0f + __expf(-mu[0]));
        g_wmix[0] = w;
        g_wmix[1] = 1.0f - w;
    }
    if (h < NHH) {
        float base, theta = 0.0f;
        int kind;
        if (h < RHH) { base = lam[h]; kind = 0; }
        else if (h < RHH + SHH) { base = g1[h - RHH]; theta = th1[h - RHH]; kind = 1; }
        else { base = g2[h - RHH - SHH]; theta = th2[h - RHH - SHH]; kind = 2; }
        float p = 1.0f;
        g_Pval[h][0] = 0.0f;
        for (int L = 1; L <= MAXL; L++) {
            p *= base;
            float v = p;
            if (kind == 1) v *= sinf(theta * (float)L);
            else if (kind == 2) v *= cosf(theta * (float)L);
            g_Pval[h][L] = v;
        }
    }
}

// ---------------- fp32 -> bf16 hi/lo split ----------------
__global__ __launch_bounds__(256) void cvt_split(const float* __restrict__ in,
                                                 __nv_bfloat16* __restrict__ hi,
                                                 __nv_bfloat16* __restrict__ lo,
                                                 int n4) {
    int i = blockIdx.x * blockDim.x + threadIdx.x;
    if (i >= n4) return;
    float4 v = ((const float4*)in)[i];
    __nv_bfloat16 h0 = __float2bfloat16(v.x);
    __nv_bfloat16 h1 = __float2bfloat16(v.y);
    __nv_bfloat16 h2 = __float2bfloat16(v.z);
    __nv_bfloat16 h3 = __float2bfloat16(v.w);
    __nv_bfloat16 l0 = __float2bfloat16(v.x - __bfloat162float(h0));
    __nv_bfloat16 l1 = __float2bfloat16(v.y - __bfloat162float(h1));
    __nv_bfloat16 l2 = __float2bfloat16(v.z - __bfloat162float(h2));
    __nv_bfloat16 l3 = __float2bfloat16(v.w - __bfloat162float(h3));
    __nv_bfloat162 hp0 = __halves2bfloat162(h0, h1);
    __nv_bfloat162 hp1 = __halves2bfloat162(h2, h3);
    __nv_bfloat162 lp0 = __halves2bfloat162(l0, l1);
    __nv_bfloat162 lp1 = __halves2bfloat162(l2, l3);
    uint2 hw, lw;
    hw.x = *(uint32_t*)&hp0; hw.y = *(uint32_t*)&hp1;
    lw.x = *(uint32_t*)&lp0; lw.y = *(uint32_t*)&lp1;
    ((uint2*)hi)[i] = hw;
    ((uint2*)lo)[i] = lw;
}

// ---------------- HMMA bf16x2 GEMM: C = A @ W^T + bias (+ optional split out) ----
#define G_TILE_B 10240          // 128*40*2
#define G_STAGE_B (4 * G_TILE_B)
#define G_SMEM (2 * G_STAGE_B)  // 81920

__global__ __launch_bounds__(256, 2) void gemm_mma(
    const __nv_bfloat16* __restrict__ Ah, const __nv_bfloat16* __restrict__ Al,
    const __nv_bfloat16* __restrict__ Bh, const __nv_bfloat16* __restrict__ Bl,
    const float* __restrict__ bias, float* __restrict__ C,
    __nv_bfloat16* __restrict__ Chi, __nv_bfloat16* __restrict__ Clo) {
    extern __shared__ char gsm[];
    const uint32_t smBase = smem_u32(gsm);

    const int tid = threadIdx.x;
    const int lane = tid & 31;
    const int wid = tid >> 5;
    const int wm = wid & 3;
    const int wn = wid >> 2;
    const int m0 = blockIdx.y * 128;
    const int n0 = blockIdx.x * 128;

    const __nv_bfloat16* srcs[4];
    srcs[0] = Ah + (size_t)m0 * DD;
    srcs[1] = Al + (size_t)m0 * DD;
    srcs[2] = Bh + (size_t)n0 * DD;
    srcs[3] = Bl + (size_t)n0 * DD;

    const int ch0 = tid * 2;
    const int lrow0 = ch0 >> 2, lcol0 = (ch0 & 3) * 8;
    const int lrow1 = (ch0 + 1) >> 2, lcol1 = ((ch0 + 1) & 3) * 8;

    float c[2][8][4];
#pragma unroll
    for (int mi = 0; mi < 2; mi++)
#pragma unroll
        for (int ni = 0; ni < 8; ni++)
#pragma unroll
            for (int r = 0; r < 4; r++) c[mi][ni][r] = 0.0f;

    {
        uint32_t sb = smBase;
#pragma unroll
        for (int t = 0; t < 4; t++) {
            CP_ASYNC16(sb + t * G_TILE_B + lrow0 * 80 + lcol0 * 2,
                       srcs[t] + (size_t)lrow0 * DD + lcol0);
            CP_ASYNC16(sb + t * G_TILE_B + lrow1 * 80 + lcol1 * 2,
                       srcs[t] + (size_t)lrow1 * DD + lcol1);
        }
        CP_COMMIT();
    }

    const uint32_t aOff = (uint32_t)((wm * 32 + (lane & 15)) * 80 + ((lane >> 4) * 8) * 2);
    const uint32_t bOff = (uint32_t)((wn * 64 + ((lane >> 4) & 1) * 8 + (lane & 7)) * 80 +
                                     (((lane >> 3) & 1) * 8) * 2);

    const int NIT = DD / 32;
    for (int it = 0; it < NIT; it++) {
        if (it + 1 < NIT) {
            uint32_t sb = smBase + ((it + 1) & 1) * G_STAGE_B;
            int k0 = (it + 1) * 32;
#pragma unroll
            for (int t = 0; t < 4; t++) {
                CP_ASYNC16(sb + t * G_TILE_B + lrow0 * 80 + lcol0 * 2,
                           srcs[t] + (size_t)lrow0 * DD + k0 + lcol0);
                CP_ASYNC16(sb + t * G_TILE_B + lrow1 * 80 + lcol1 * 2,
                           srcs[t] + (size_t)lrow1 * DD + k0 + lcol1);
            }
            CP_COMMIT();
            CP_WAIT1();
        } else {
            CP_WAIT0();
        }
        __syncthreads();

        const uint32_t aBase = smBase + (it & 1) * G_STAGE_B;
        const uint32_t bBase = aBase + 2 * G_TILE_B;
#pragma unroll
        for (int kk = 0; kk < 2; kk++) {
            uint32_t ah[2][4], al[2][4];
#pragma unroll
            for (int mi = 0; mi < 2; mi++) {
                uint32_t a = aBase + aOff + (uint32_t)(mi * 16 * 80 + kk * 32);
                LDM_X4(ah[mi][0], ah[mi][1], ah[mi][2], ah[mi][3], a);
                LDM_X4(al[mi][0], al[mi][1], al[mi][2], al[mi][3], a + G_TILE_B);
            }
            // bh used by two mma groups, then dead before bl loads (reg peak control)
            {
                uint32_t bh[8][2];
#pragma unroll
                for (int nq = 0; nq < 4; nq++) {
                    uint32_t a = bBase + bOff + (uint32_t)(nq * 16 * 80 + kk * 32);
                    LDM_X4(bh[nq * 2][0], bh[nq * 2][1], bh[nq * 2 + 1][0], bh[nq * 2 + 1][1], a);
                }
#pragma unroll
                for (int mi = 0; mi < 2; mi++)
#pragma unroll
                    for (int ni = 0; ni < 8; ni++) {
                        float* cc = c[mi][ni];
                        MMA16816(cc[0], cc[1], cc[2], cc[3],
                                 ah[mi][0], ah[mi][1], ah[mi][2], ah[mi][3],
                                 bh[ni][0], bh[ni][1]);
                        MMA16816(cc[0], cc[1], cc[2], cc[3],
                                 al[mi][0], al[mi][1], al[mi][2], al[mi][3],
                                 bh[ni][0], bh[ni][1]);
                    }
            }
            {
                uint32_t bl[8][2];
#pragma unroll
                for (int nq = 0; nq < 4; nq++) {
                    uint32_t a = bBase + bOff + (uint32_t)(nq * 16 * 80 + kk * 32) + G_TILE_B;
                    LDM_X4(bl[nq * 2][0], bl[nq * 2][1], bl[nq * 2 + 1][0], bl[nq * 2 + 1][1], a);
                }
#pragma unroll
                for (int mi = 0; mi < 2; mi++)
#pragma unroll
                    for (int ni = 0; ni < 8; ni++) {
                        float* cc = c[mi][ni];
                        MMA16816(cc[0], cc[1], cc[2], cc[3],
                                 ah[mi][0], ah[mi][1], ah[mi][2], ah[mi][3],
                                 bl[ni][0], bl[ni][1]);
                    }
            }
        }
        __syncthreads();
    }

    // ---- epilogue: optional fp32 + optional bf16 hi/lo split ----
#pragma unroll
    for (int mi = 0; mi < 2; mi++) {
        int row = m0 + wm * 32 + mi * 16 + (lane >> 2);
#pragma unroll
        for (int ni = 0; ni < 8; ni++) {
            int col = n0 + wn * 64 + ni * 8 + (lane & 3) * 2;
            float b0 = bias[col], b1 = bias[col + 1];
            float v00 = c[mi][ni][0] + b0, v01 = c[mi][ni][1] + b1;
            float v10 = c[mi][ni][2] + b0, v11 = c[mi][ni][3] + b1;
            if (C != nullptr) {
                *(float2*)(C + (size_t)row * DD + col) = make_float2(v00, v01);
                *(float2*)(C + (size_t)(row + 8) * DD + col) = make_float2(v10, v11);
            }
            if (Chi != nullptr) {
                uint32_t h0 = packbf2(v00, v01);
                uint32_t l0v = packlo2(v00, v01, h0);
                uint32_t h1 = packbf2(v10, v11);
                uint32_t l1v = packlo2(v10, v11, h1);
                *(uint32_t*)(Chi + (size_t)row * DD + col) = h0;
                *(uint32_t*)(Clo + (size_t)row * DD + col) = l0v;
                *(uint32_t*)(Chi + (size_t)(row + 8) * DD + col) = h1;
                *(uint32_t*)(Clo + (size_t)(row + 8) * DD + col) = l1v;
            }
        }
    }
}

// ---------------- HMMA flash attention: ctx = (1-w) * softmax(Q K^T) V ----------------
// 8 warps, q-tile 128 (16 rows/warp), k-tile 64, 2-stage cp.async K/V pipeline.
// Q lives in registers (direct LDG); smem = 2 stages x (Kh Kl Vh Vl), stride 72.
#define FS 72
#define FL_KV_STG_B 36864        // 4 * 64*72*2
#define FL_ARR_B 9216            // 64*72*2
#define FL_SMEM_B (2 * FL_KV_STG_B)  // 73728

__global__ __launch_bounds__(256, 2) void flash_mma() {
    extern __shared__ char fsmem[];
    const uint32_t smB = smem_u32(fsmem);
    const int tid = threadIdx.x;
    const int lane = tid & 31, wid = tid >> 5;
    const int b = blockIdx.z, h = blockIdx.y, q0 = blockIdx.x * 128;
    const size_t hOff = (size_t)h * HCC;

    const __nv_bfloat16* kvsrc[4] = {
        g_Kh + (size_t)(b * TT) * DD + hOff,
        g_Kl + (size_t)(b * TT) * DD + hOff,
        g_Vh + (size_t)(b * TT) * DD + hOff,
        g_Vl + (size_t)(b * TT) * DD + hOff };

    // prologue: KV stage0
    {
#pragma unroll
        for (int i = 0; i < 8; i++) {
            int cck = tid + i * 256;
            int arr = cck >> 9, r = (cck >> 3) & 63, c8 = (cck & 7) * 8;
            CP_ASYNC16(smB + arr * FL_ARR_B + r * (FS * 2) + c8 * 2,
                       kvsrc[arr] + (size_t)r * DD + c8);
        }
        CP_COMMIT();
    }

    const int r0 = wid * 16;
    // ---- Q fragments straight from global (A-frag = 2 consecutive-k bf16) ----
    uint32_t qah[4][4], qal[4][4];
    {
        const int rA = lane >> 2, cA = (lane & 3) * 2;
        const __nv_bfloat16* qhp = g_Qh + (size_t)(b * TT + q0 + r0 + rA) * DD + hOff + cA;
        const __nv_bfloat16* qlp = g_Ql + (size_t)(b * TT + q0 + r0 + rA) * DD + hOff + cA;
#pragma unroll
        for (int kk = 0; kk < 4; kk++) {
            qah[kk][0] = *(const uint32_t*)(qhp + kk * 16);
            qah[kk][1] = *(const uint32_t*)(qhp + 8 * DD + kk * 16);
            qah[kk][2] = *(const uint32_t*)(qhp + kk * 16 + 8);
            qah[kk][3] = *(const uint32_t*)(qhp + 8 * DD + kk * 16 + 8);
            qal[kk][0] = *(const uint32_t*)(qlp + kk * 16);
            qal[kk][1] = *(const uint32_t*)(qlp + 8 * DD + kk * 16);
            qal[kk][2] = *(const uint32_t*)(qlp + kk * 16 + 8);
            qal[kk][3] = *(const uint32_t*)(qlp + 8 * DD + kk * 16 + 8);
        }
    }

    const int lrQ = (lane & 7) + ((lane >> 3) & 1) * 8;   // V rows
    const int lcQ = (lane >> 4) * 8;                       // V cols
    const int lrK = (lane & 7) + (lane >> 4) * 8;
    const int lcK = ((lane >> 3) & 1) * 8;
    const uint32_t kOff = (uint32_t)(lrK * FS + lcK) * 2;
    const uint32_t vOff = (uint32_t)(lrQ * FS + lcQ) * 2;

    float m0 = -3.0e38f, m1 = -3.0e38f, l0 = 0.0f, l1 = 0.0f;
    float o[8][4];
#pragma unroll
    for (int i = 0; i < 8; i++)
#pragma unroll
        for (int j = 0; j < 4; j++) o[i][j] = 0.0f;

    const int NKT = TT / 64;  // 32
    for (int kt = 0; kt < NKT; kt++) {
        if (kt + 1 < NKT) {
            uint32_t sb = smB + ((kt + 1) & 1) * FL_KV_STG_B;
            int t0 = (kt + 1) * 64;
#pragma unroll
            for (int i = 0; i < 8; i++) {
                int cck = tid + i * 256;
                int arr = cck >> 9, r = (cck >> 3) & 63, c8 = (cck & 7) * 8;
                CP_ASYNC16(sb + arr * FL_ARR_B + r * (FS * 2) + c8 * 2,
                           kvsrc[arr] + (size_t)(t0 + r) * DD + c8);
            }
            CP_COMMIT();
            CP_WAIT1();
        } else {
            CP_WAIT0();
        }
        __syncthreads();

        const uint32_t stg = smB + (kt & 1) * FL_KV_STG_B;

        // ---- S = Q K^T (16 x 64 per warp), 3-mma split, reg-peak-controlled ----
        float s[8][4];
#pragma unroll
        for (int i = 0; i < 8; i++)
#pragma unroll
            for (int j = 0; j < 4; j++) s[i][j] = 0.0f;
#pragma unroll
        for (int kk = 0; kk < 4; kk++) {
            {
                uint32_t kb[8][2];
#pragma unroll
                for (int p = 0; p < 4; p++) {
                    uint32_t a = stg + kOff + (uint32_t)(p * 16 * FS + kk * 16) * 2;
                    LDM_X4(kb[p * 2][0], kb[p * 2][1], kb[p * 2 + 1][0], kb[p * 2 + 1][1], a);
                }
#pragma unroll
                for (int nj = 0; nj < 8; nj++) {
                    float* ss = s[nj];
                    MMA16816(ss[0], ss[1], ss[2], ss[3],
                             qah[kk][0], qah[kk][1], qah[kk][2], qah[kk][3],
                             kb[nj][0], kb[nj][1]);
                    MMA16816(ss[0], ss[1], ss[2], ss[3],
                             qal[kk][0], qal[kk][1], qal[kk][2], qal[kk][3],
                             kb[nj][0], kb[nj][1]);
                }
            }
            {
                uint32_t kl[8][2];
#pragma unroll
                for (int p = 0; p < 4; p++) {
                    uint32_t a = stg + kOff + (uint32_t)(p * 16 * FS + kk * 16) * 2 + FL_ARR_B;
                    LDM_X4(kl[p * 2][0], kl[p * 2][1], kl[p * 2 + 1][0], kl[p * 2 + 1][1], a);
                }
#pragma unroll
                for (int nj = 0; nj < 8; nj++) {
                    float* ss = s[nj];
                    MMA16816(ss[0], ss[1], ss[2], ss[3],
                             qah[kk][0], qah[kk][1], qah[kk][2], qah[kk][3],
                             kl[nj][0], kl[nj][1]);
                }
            }
        }

        // ---- online softmax ----
        float mr0 = s[0][0], mr1 = s[0][2];
#pragma unroll
        for (int nj = 0; nj < 8; nj++) {
            mr0 = fmaxf(mr0, fmaxf(s[nj][0], s[nj][1]));
            mr1 = fmaxf(mr1, fmaxf(s[nj][2], s[nj][3]));
        }
        mr0 = fmaxf(mr0, __shfl_xor_sync(0xffffffffu, mr0, 1, 4));
        mr0 = fmaxf(mr0, __shfl_xor_sync(0xffffffffu, mr0, 2, 4));
        mr1 = fmaxf(mr1, __shfl_xor_sync(0xffffffffu, mr1, 1, 4));
        mr1 = fmaxf(mr1, __shfl_xor_sync(0xffffffffu, mr1, 2, 4));
        float mn0 = fmaxf(m0, mr0), mn1 = fmaxf(m1, mr1);
        float cor0 = __expf(m0 - mn0), cor1 = __expf(m1 - mn1);
        m0 = mn0; m1 = mn1;
        float rs0 = 0.0f, rs1 = 0.0f;
#pragma unroll
        for (int nj = 0; nj < 8; nj++) {
            s[nj][0] = __expf(s[nj][0] - mn0);
            s[nj][1] = __expf(s[nj][1] - mn0);
            s[nj][2] = __expf(s[nj][2] - mn1);
            s[nj][3] = __expf(s[nj][3] - mn1);
            rs0 += s[nj][0] + s[nj][1];
            rs1 += s[nj][2] + s[nj][3];
        }
        rs0 += __shfl_xor_sync(0xffffffffu, rs0, 1, 4);
        rs0 += __shfl_xor_sync(0xffffffffu, rs0, 2, 4);
        rs1 += __shfl_xor_sync(0xffffffffu, rs1, 1, 4);
        rs1 += __shfl_xor_sync(0xffffffffu, rs1, 2, 4);
        l0 = l0 * cor0 + rs0;
        l1 = l1 * cor1 + rs1;
#pragma unroll
        for (int nd = 0; nd < 8; nd++) {
            o[nd][0] *= cor0; o[nd][1] *= cor0;
            o[nd][2] *= cor1; o[nd][3] *= cor1;
        }

        // ---- repack P (C-frag -> A-frag) with hi/lo split; s dies here ----
        uint32_t pah[4][4], pal[4][4];
#pragma unroll
        for (int kk = 0; kk < 4; kk++) {
            pah[kk][0] = packbf2(s[2 * kk][0], s[2 * kk][1]);
            pah[kk][1] = packbf2(s[2 * kk][2], s[2 * kk][3]);
            pah[kk][2] = packbf2(s[2 * kk + 1][0], s[2 * kk + 1][1]);
            pah[kk][3] = packbf2(s[2 * kk + 1][2], s[2 * kk + 1][3]);
            pal[kk][0] = packlo2(s[2 * kk][0], s[2 * kk][1], pah[kk][0]);
            pal[kk][1] = packlo2(s[2 * kk][2], s[2 * kk][3], pah[kk][1]);
            pal[kk][2] = packlo2(s[2 * kk + 1][0], s[2 * kk + 1][1], pah[kk][2]);
            pal[kk][3] = packlo2(s[2 * kk + 1][2], s[2 * kk + 1][3], pah[kk][3]);
        }

        // ---- O += P V (16 x 64 per warp), 3-mma split, reg-peak-controlled ----
        const uint32_t vbaseH = stg + 2 * FL_ARR_B + vOff;
#pragma unroll
        for (int kk = 0; kk < 4; kk++) {
            {
                uint32_t vb[8][2];
#pragma unroll
                for (int q = 0; q < 4; q++) {
                    uint32_t a = vbaseH + (uint32_t)(kk * 16 * FS + q * 16) * 2;
                    LDM_X4_T(vb[q * 2][0], vb[q * 2][1], vb[q * 2 + 1][0], vb[q * 2 + 1][1], a);
                }
#pragma unroll
                for (int nd = 0; nd < 8; nd++) {
                    float* oo = o[nd];
                    MMA16816(oo[0], oo[1], oo[2], oo[3],
                             pah[kk][0], pah[kk][1], pah[kk][2], pah[kk][3],
                             vb[nd][0], vb[nd][1]);
                    MMA16816(oo[0], oo[1], oo[2], oo[3],
                             pal[kk][0], pal[kk][1], pal[kk][2], pal[kk][3],
                             vb[nd][0], vb[nd][1]);
                }
            }
            {
                uint32_t vl[8][2];
#pragma unroll
                for (int q = 0; q < 4; q++) {
                    uint32_t a = vbaseH + (uint32_t)(kk * 16 * FS + q * 16) * 2 + FL_ARR_B;
                    LDM_X4_T(vl[q * 2][0], vl[q * 2][1], vl[q * 2 + 1][0], vl[q * 2 + 1][1], a);
                }
#pragma unroll
                for (int nd = 0; nd < 8; nd++) {
                    float* oo = o[nd];
                    MMA16816(oo[0], oo[1], oo[2], oo[3],
                             pah[kk][0], pah[kk][1], pah[kk][2], pah[kk][3],
                             vl[nd][0], vl[nd][1]);
                }
            }
        }
        __syncthreads();
    }

    // ---- epilogue: ctx = (1-w) * O / l ----
    float w1 = g_wmix[1];
    float inv0 = w1 / l0, inv1 = w1 / l1;
    int row0 = q0 + r0 + (lane >> 2);
    float* dst0 = g_ctx + (size_t)(b * TT + row0) * DD + hOff + (lane & 3) * 2;
    float* dst1 = dst0 + 8 * DD;
#pragma unroll
    for (int nd = 0; nd < 8; nd++) {
        *(float2*)(dst0 + nd * 8) = make_float2(o[nd][0] * inv0, o[nd][1] * inv0);
        *(float2*)(dst1 + nd * 8) = make_float2(o[nd][2] * inv1, o[nd][3] * inv1);
    }
}

// ---------------- prefix sums of V along t, per (b,h,c): hierarchical ----------------
__global__ __launch_bounds__(256) void prefix_kernel() {
    __shared__ float part[4][64];
    int b = blockIdx.x >> 4;
    int h = blockIdx.x & 15;
    int c = threadIdx.x & 63;
    int ch = threadIdx.x >> 6;  // 0..3, each 512 t
    const float* vp = g_V + ((size_t)(b * TT + ch * 512)) * DD + h * HCC + c;
    float s0 = 0.0f, s1 = 0.0f, s2 = 0.0f, s3 = 0.0f;
    for (int t = 0; t < 512; t += 4) {
        s0 += vp[(size_t)(t + 0) * DD];
        s1 += vp[(size_t)(t + 1) * DD];
        s2 += vp[(size_t)(t + 2) * DD];
        s3 += vp[(size_t)(t + 3) * DD];
    }
    part[ch][c] = (s0 + s1) + (s2 + s3);
    __syncthreads();
    float run = 0.0f;
    for (int i = 0; i < ch; i++) run += part[i][c];
    float* ps = g_PS + ((size_t)(b * TT + ch * 512)) * DD + h * HCC + c;
    for (int t = 0; t < 512; t++) {
        run += vp[(size_t)t * DD];
        ps[(size_t)t * DD] = run;
    }
}

// ---------------- PV: out_split = ctx + w * (P @ V) via 99-tap conv + prefix ----------------
__global__ __launch_bounds__(256) void pv_kernel() {
    __shared__ float Vw[162 * 64];
    __shared__ float Pv[MAXL + 1];
    int b = blockIdx.z, h = blockIdx.y;
    int q0 = blockIdx.x * 64;
    int tid = threadIdx.x;
    if (tid <= MAXL) Pv[tid] = g_Pval[h][tid];
    for (int idx = tid; idx < 162 * 64; idx += 256) {
        int r = idx >> 6, c = idx & 63;
        int tg = q0 - 99 + r;
        Vw[idx] = (tg >= 0) ? g_V[((size_t)(b * TT + tg)) * DD + h * HCC + c] : 0.0f;
    }
    __syncthreads();
    int c = tid & 63, qq = tid >> 6;
    float w = g_wmix[0];
#pragma unroll 1
    for (int ii = 0; ii < 16; ii++) {
        int ql = qq * 16 + ii;
        int qg = q0 + ql;
        float a0 = 0.0f, a1 = 0.0f, a2 = 0.0f, a3 = 0.0f;
        int jmax = min(99, qg);
        int j = 1;
        for (; j + 3 <= jmax; j += 4) {
            a0 += Pv[j]     * Vw[((ql - j + 99) << 6) | c];
            a1 += Pv[j + 1] * Vw[((ql - j + 98) << 6) | c];
            a2 += Pv[j + 2] * Vw[((ql - j + 97) << 6) | c];
            a3 += Pv[j + 3] * Vw[((ql - j + 96) << 6) | c];
        }
        for (; j <= jmax; j++)
            a0 += Pv[j] * Vw[((ql - j + 99) << 6) | c];
        float acc = (a0 + a1) + (a2 + a3);
        if (qg >= 100)
            acc += Pv[MAXL] * g_PS[((size_t)(b * TT + qg - 100)) * DD + h * HCC + c];
        size_t oi = ((size_t)(b * TT + qg)) * DD + h * HCC + c;
        float outv = g_ctx[oi] + w * acc;
        __nv_bfloat16 hh = __float2bfloat16(outv);
        g_xh[oi] = hh;
        g_xl[oi] = __float2bfloat16(outv - __bfloat162float(hh));
    }
}

// ---------------- launch ----------------
extern "C" void kernel_launch(void* const* d_in, const int* in_sizes, int n_in,
                              void* d_out, int out_size) {
    const float* x   = (const float*)d_in[0];
    const float* mu  = (const float*)d_in[1];
    const float* lam = (const float*)d_in[2];
    const float* g1  = (const float*)d_in[3];
    const float* g2  = (const float*)d_in[4];
    const float* th1 = (const float*)d_in[5];
    const float* th2 = (const float*)d_in[6];
    const float* Wq  = (const float*)d_in[7];
    const float* bq  = (const float*)d_in[8];
    const float* Wk  = (const float*)d_in[9];
    const float* bk  = (const float*)d_in[10];
    const float* Wv  = (const float*)d_in[11];
    const float* bv  = (const float*)d_in[12];
    const float* Wf  = (const float*)d_in[13];
    const float* bf  = (const float*)d_in[14];
    float* out = (float*)d_out;

    float *Vd;
    cudaGetSymbolAddress((void**)&Vd, g_V);
    __nv_bfloat16 *xh, *xl, *wh, *wl, *qh, *ql, *kh, *kl, *vh, *vl;
    cudaGetSymbolAddress((void**)&xh, g_xh);
    cudaGetSymbolAddress((void**)&xl, g_xl);
    cudaGetSymbolAddress((void**)&wh, g_wh);
    cudaGetSymbolAddress((void**)&wl, g_wl);
    cudaGetSymbolAddress((void**)&qh, g_Qh);
    cudaGetSymbolAddress((void**)&ql, g_Ql);
    cudaGetSymbolAddress((void**)&kh, g_Kh);
    cudaGetSymbolAddress((void**)&kl, g_Kl);
    cudaGetSymbolAddress((void**)&vh, g_Vh);
    cudaGetSymbolAddress((void**)&vl, g_Vl);

    setup_kernel<<<1, 32>>>(mu, lam, g1, g2, th1, th2);

    const int NX4 = (BB * TT * DD) / 4;
    const int NW4 = (DD * DD) / 4;
    cvt_split<<<(NX4 + 255) / 256, 256>>>(x, xh, xl, NX4);
    cvt_split<<<(NW4 + 255) / 256, 256>>>(Wq, wh + 0 * DD * DD, wl + 0 * DD * DD, NW4);
    cvt_split<<<(NW4 + 255) / 256, 256>>>(Wk, wh + 1 * DD * DD, wl + 1 * DD * DD, NW4);
    cvt_split<<<(NW4 + 255) / 256, 256>>>(Wv, wh + 2 * DD * DD, wl + 2 * DD * DD, NW4);
    cvt_split<<<(NW4 + 255) / 256, 256>>>(Wf, wh + 3 * DD * DD, wl + 3 * DD * DD, NW4);

    cudaFuncSetAttribute(gemm_mma, cudaFuncAttributeMaxDynamicSharedMemorySize, G_SMEM);
    dim3 ggrid(DD / 128, (BB * TT) / 128);
    gemm_mma<<<ggrid, 256, G_SMEM>>>(xh, xl, wh + 0 * DD * DD, wl + 0 * DD * DD, bq,
                                     nullptr, qh, ql);
    gemm_mma<<<ggrid, 256, G_SMEM>>>(xh, xl, wh + 1 * DD * DD, wl + 1 * DD * DD, bk,
                                     nullptr, kh, kl);
    gemm_mma<<<ggrid, 256, G_SMEM>>>(xh, xl, wh + 2 * DD * DD, wl + 2 * DD * DD, bv,
                                     Vd, vh, vl);

    cudaFuncSetAttribute(flash_mma, cudaFuncAttributeMaxDynamicSharedMemorySize, FL_SMEM_B);
    dim3 fgrid(TT / 128, NHH, BB);
    flash_mma<<<fgrid, 256, FL_SMEM_B>>>();

    prefix_kernel<<<BB * NHH, 256>>>();

    dim3 pvgrid(TT / 64, NHH, BB);
    pv_kernel<<<pvgrid, 256>>>();

    gemm_mma<<<ggrid, 256, G_SMEM>>>(xh, xl, wh + 3 * DD * DD, wl + 3 * DD * DD, bf, out,
                                     nullptr, nullptr);
}

// round 9
// speedup vs baseline: 2.9525x; 1.0016x over previous
#include <cuda_runtime.h>
#include <cuda_bf16.h>
#include <math.h>
#include <stdint.h>

#define BB 4
#define TT 2048
#define NHH 16
#define HCC 64
#define DD 1024
#define RHH 4
#define SHH 6
#define MAXL 100

// ---------------- scratch (device globals: allowed) ----------------
__device__ float g_V[BB * TT * DD];
__device__ float g_ctx[BB * TT * DD];
__device__ float g_PS[BB * TT * DD];
__device__ float g_Pval[NHH][MAXL + 1];
__device__ float g_wmix[2];  // [0]=w, [1]=1-w

// bf16 split operand buffers
__device__ __nv_bfloat16 g_xh[BB * TT * DD];
__device__ __nv_bfloat16 g_xl[BB * TT * DD];
__device__ __nv_bfloat16 g_wh[4 * DD * DD];
__device__ __nv_bfloat16 g_wl[4 * DD * DD];
__device__ __nv_bfloat16 g_Qh[BB * TT * DD];
__device__ __nv_bfloat16 g_Ql[BB * TT * DD];
__device__ __nv_bfloat16 g_Kh[BB * TT * DD];
__device__ __nv_bfloat16 g_Kl[BB * TT * DD];
__device__ __nv_bfloat16 g_Vh[BB * TT * DD];
__device__ __nv_bfloat16 g_Vl[BB * TT * DD];

// ---------------- PTX helpers (baseline ISA only: sm_80-class) ----------------
__device__ __forceinline__ uint32_t smem_u32(const void* p) {
    uint32_t a;
    asm("{ .reg .u64 t; cvta.to.shared.u64 t, %1; cvt.u32.u64 %0, t; }" : "=r"(a) : "l"(p));
    return a;
}

#define CP_ASYNC16(dst, src) \
    asm volatile("cp.async.cg.shared.global [%0], [%1], 16;" :: "r"(dst), "l"(src))
#define CP_COMMIT() asm volatile("cp.async.commit_group;")
#define CP_WAIT1() asm volatile("cp.async.wait_group 1;")
#define CP_WAIT0() asm volatile("cp.async.wait_group 0;")

#define LDM_X4(r0, r1, r2, r3, addr) \
    asm volatile("ldmatrix.sync.aligned.m8n8.x4.shared.b16 {%0,%1,%2,%3}, [%4];" \
                 : "=r"(r0), "=r"(r1), "=r"(r2), "=r"(r3) : "r"(addr))

#define LDM_X4_T(r0, r1, r2, r3, addr) \
    asm volatile("ldmatrix.sync.aligned.m8n8.x4.trans.shared.b16 {%0,%1,%2,%3}, [%4];" \
                 : "=r"(r0), "=r"(r1), "=r"(r2), "=r"(r3) : "r"(addr))

#define MMA16816(c0, c1, c2, c3, a0, a1, a2, a3, b0, b1) \
    asm volatile("mma.sync.aligned.m16n8k16.row.col.f32.bf16.bf16.f32 " \
                 "{%0,%1,%2,%3}, {%4,%5,%6,%7}, {%8,%9}, {%0,%1,%2,%3};" \
                 : "+f"(c0), "+f"(c1), "+f"(c2), "+f"(c3) \
                 : "r"(a0), "r"(a1), "r"(a2), "r"(a3), "r"(b0), "r"(b1))

__device__ __forceinline__ uint32_t packbf2(float a, float b) {
    __nv_bfloat162 t = __floats2bfloat162_rn(a, b);
    return *(uint32_t*)&t;
}
__device__ __forceinline__ uint32_t packlo2(float a, float b, uint32_t hi) {
    __nv_bfloat162 hv = *(__nv_bfloat162*)&hi;
    return packbf2(a - __bfloat162float(hv.x), b - __bfloat162float(hv.y));
}

// ---------------- setup: Pval table + mix weight ----------------
__global__ void setup_kernel(const float* __restrict__ mu,
                             const float* __restrict__ lam,
                             const float* __restrict__ g1,
                             const float* __restrict__ g2,
                             const float* __restrict__ th1,
                             const float* __restrict__ th2) {
    int h = threadIdx.x;
    if (h == 0) {
        float w = 1.0f / (1.0f + __expf(-mu[0]));
        g_wmix[0] = w;
        g_wmix[1] = 1.0f - w;
    }
    if (h < NHH) {
        float base, theta = 0.0f;
        int kind;
        if (h < RHH) { base = lam[h]; kind = 0; }
        else if (h < RHH + SHH) { base = g1[h - RHH]; theta = th1[h - RHH]; kind = 1; }
        else { base = g2[h - RHH - SHH]; theta = th2[h - RHH - SHH]; kind = 2; }
        float p = 1.0f;
        g_Pval[h][0] = 0.0f;
        for (int L = 1; L <= MAXL; L++) {
            p *= base;
            float v = p;
            if (kind == 1) v *= sinf(theta * (float)L);
            else if (kind == 2) v *= cosf(theta * (float)L);
            g_Pval[h][L] = v;
        }
    }
}

// ---------------- fp32 -> bf16 hi/lo split (x / activations) ----------------
__global__ __launch_bounds__(256) void cvt_split(const float* __restrict__ in,
                                                 __nv_bfloat16* __restrict__ hi,
                                                 __nv_bfloat16* __restrict__ lo,
                                                 int n4) {
    int i = blockIdx.x * blockDim.x + threadIdx.x;
    if (i >= n4) return;
    float4 v = ((const float4*)in)[i];
    __nv_bfloat16 h0 = __float2bfloat16(v.x);
    __nv_bfloat16 h1 = __float2bfloat16(v.y);
    __nv_bfloat16 h2 = __float2bfloat16(v.z);
    __nv_bfloat16 h3 = __float2bfloat16(v.w);
    __nv_bfloat16 l0 = __float2bfloat16(v.x - __bfloat162float(h0));
    __nv_bfloat16 l1 = __float2bfloat16(v.y - __bfloat162float(h1));
    __nv_bfloat16 l2 = __float2bfloat16(v.z - __bfloat162float(h2));
    __nv_bfloat16 l3 = __float2bfloat16(v.w - __bfloat162float(h3));
    __nv_bfloat162 hp0 = __halves2bfloat162(h0, h1);
    __nv_bfloat162 hp1 = __halves2bfloat162(h2, h3);
    __nv_bfloat162 lp0 = __halves2bfloat162(l0, l1);
    __nv_bfloat162 lp1 = __halves2bfloat162(l2, l3);
    uint2 hw, lw;
    hw.x = *(uint32_t*)&hp0; hw.y = *(uint32_t*)&hp1;
    lw.x = *(uint32_t*)&lp0; lw.y = *(uint32_t*)&lp1;
    ((uint2*)hi)[i] = hw;
    ((uint2*)lo)[i] = lw;
}

// fused: all 4 weight matrices -> g_wh/g_wl (contiguous)
__global__ __launch_bounds__(256) void cvt_split_w(const float* __restrict__ w0,
                                                   const float* __restrict__ w1,
                                                   const float* __restrict__ w2,
                                                   const float* __restrict__ w3) {
    int i = blockIdx.x * blockDim.x + threadIdx.x;  // float4 index over 4*DD*DD/4
    const int per = DD * DD / 4;  // 262144
    int mat = i / per, local = i - mat * per;
    const float* src = (mat == 0) ? w0 : (mat == 1) ? w1 : (mat == 2) ? w2 : w3;
    float4 v = ((const float4*)src)[local];
    __nv_bfloat16 h0 = __float2bfloat16(v.x);
    __nv_bfloat16 h1 = __float2bfloat16(v.y);
    __nv_bfloat16 h2 = __float2bfloat16(v.z);
    __nv_bfloat16 h3 = __float2bfloat16(v.w);
    __nv_bfloat16 l0 = __float2bfloat16(v.x - __bfloat162float(h0));
    __nv_bfloat16 l1 = __float2bfloat16(v.y - __bfloat162float(h1));
    __nv_bfloat16 l2 = __float2bfloat16(v.z - __bfloat162float(h2));
    __nv_bfloat16 l3 = __float2bfloat16(v.w - __bfloat162float(h3));
    __nv_bfloat162 hp0 = __halves2bfloat162(h0, h1);
    __nv_bfloat162 hp1 = __halves2bfloat162(h2, h3);
    __nv_bfloat162 lp0 = __halves2bfloat162(l0, l1);
    __nv_bfloat162 lp1 = __halves2bfloat162(l2, l3);
    uint2 hw, lw;
    hw.x = *(uint32_t*)&hp0; hw.y = *(uint32_t*)&hp1;
    lw.x = *(uint32_t*)&lp0; lw.y = *(uint32_t*)&lp1;
    ((uint2*)g_wh)[i] = hw;
    ((uint2*)g_wl)[i] = lw;
}

// ---------------- HMMA bf16x2 GEMM: C = oscale*(A @ W^T + bias) ----
#define G_TILE_B 10240          // 128*40*2
#define G_STAGE_B (4 * G_TILE_B)
#define G_SMEM (2 * G_STAGE_B)  // 81920

__global__ __launch_bounds__(256, 2) void gemm_mma(
    const __nv_bfloat16* __restrict__ Ah, const __nv_bfloat16* __restrict__ Al,
    const __nv_bfloat16* __restrict__ Bh, const __nv_bfloat16* __restrict__ Bl,
    const float* __restrict__ bias, float* __restrict__ C,
    __nv_bfloat16* __restrict__ Chi, __nv_bfloat16* __restrict__ Clo,
    float oscale) {
    extern __shared__ char gsm[];
    const uint32_t smBase = smem_u32(gsm);

    const int tid = threadIdx.x;
    const int lane = tid & 31;
    const int wid = tid >> 5;
    const int wm = wid & 3;
    const int wn = wid >> 2;
    const int m0 = blockIdx.y * 128;
    const int n0 = blockIdx.x * 128;

    const __nv_bfloat16* srcs[4];
    srcs[0] = Ah + (size_t)m0 * DD;
    srcs[1] = Al + (size_t)m0 * DD;
    srcs[2] = Bh + (size_t)n0 * DD;
    srcs[3] = Bl + (size_t)n0 * DD;

    const int ch0 = tid * 2;
    const int lrow0 = ch0 >> 2, lcol0 = (ch0 & 3) * 8;
    const int lrow1 = (ch0 + 1) >> 2, lcol1 = ((ch0 + 1) & 3) * 8;

    float c[2][8][4];
#pragma unroll
    for (int mi = 0; mi < 2; mi++)
#pragma unroll
        for (int ni = 0; ni < 8; ni++)
#pragma unroll
            for (int r = 0; r < 4; r++) c[mi][ni][r] = 0.0f;

    {
        uint32_t sb = smBase;
#pragma unroll
        for (int t = 0; t < 4; t++) {
            CP_ASYNC16(sb + t * G_TILE_B + lrow0 * 80 + lcol0 * 2,
                       srcs[t] + (size_t)lrow0 * DD + lcol0);
            CP_ASYNC16(sb + t * G_TILE_B + lrow1 * 80 + lcol1 * 2,
                       srcs[t] + (size_t)lrow1 * DD + lcol1);
        }
        CP_COMMIT();
    }

    const uint32_t aOff = (uint32_t)((wm * 32 + (lane & 15)) * 80 + ((lane >> 4) * 8) * 2);
    const uint32_t bOff = (uint32_t)((wn * 64 + ((lane >> 4) & 1) * 8 + (lane & 7)) * 80 +
                                     (((lane >> 3) & 1) * 8) * 2);

    const int NIT = DD / 32;
    for (int it = 0; it < NIT; it++) {
        if (it + 1 < NIT) {
            uint32_t sb = smBase + ((it + 1) & 1) * G_STAGE_B;
            int k0 = (it + 1) * 32;
#pragma unroll
            for (int t = 0; t < 4; t++) {
                CP_ASYNC16(sb + t * G_TILE_B + lrow0 * 80 + lcol0 * 2,
                           srcs[t] + (size_t)lrow0 * DD + k0 + lcol0);
                CP_ASYNC16(sb + t * G_TILE_B + lrow1 * 80 + lcol1 * 2,
                           srcs[t] + (size_t)lrow1 * DD + k0 + lcol1);
            }
            CP_COMMIT();
            CP_WAIT1();
        } else {
            CP_WAIT0();
        }
        __syncthreads();

        const uint32_t aBase = smBase + (it & 1) * G_STAGE_B;
        const uint32_t bBase = aBase + 2 * G_TILE_B;
#pragma unroll
        for (int kk = 0; kk < 2; kk++) {
            uint32_t ah[2][4], al[2][4];
#pragma unroll
            for (int mi = 0; mi < 2; mi++) {
                uint32_t a = aBase + aOff + (uint32_t)(mi * 16 * 80 + kk * 32);
                LDM_X4(ah[mi][0], ah[mi][1], ah[mi][2], ah[mi][3], a);
                LDM_X4(al[mi][0], al[mi][1], al[mi][2], al[mi][3], a + G_TILE_B);
            }
            {
                uint32_t bh[8][2];
#pragma unroll
                for (int nq = 0; nq < 4; nq++) {
                    uint32_t a = bBase + bOff + (uint32_t)(nq * 16 * 80 + kk * 32);
                    LDM_X4(bh[nq * 2][0], bh[nq * 2][1], bh[nq * 2 + 1][0], bh[nq * 2 + 1][1], a);
                }
#pragma unroll
                for (int mi = 0; mi < 2; mi++)
#pragma unroll
                    for (int ni = 0; ni < 8; ni++) {
                        float* cc = c[mi][ni];
                        MMA16816(cc[0], cc[1], cc[2], cc[3],
                                 ah[mi][0], ah[mi][1], ah[mi][2], ah[mi][3],
                                 bh[ni][0], bh[ni][1]);
                        MMA16816(cc[0], cc[1], cc[2], cc[3],
                                 al[mi][0], al[mi][1], al[mi][2], al[mi][3],
                                 bh[ni][0], bh[ni][1]);
                    }
            }
            {
                uint32_t bl[8][2];
#pragma unroll
                for (int nq = 0; nq < 4; nq++) {
                    uint32_t a = bBase + bOff + (uint32_t)(nq * 16 * 80 + kk * 32) + G_TILE_B;
                    LDM_X4(bl[nq * 2][0], bl[nq * 2][1], bl[nq * 2 + 1][0], bl[nq * 2 + 1][1], a);
                }
#pragma unroll
                for (int mi = 0; mi < 2; mi++)
#pragma unroll
                    for (int ni = 0; ni < 8; ni++) {
                        float* cc = c[mi][ni];
                        MMA16816(cc[0], cc[1], cc[2], cc[3],
                                 ah[mi][0], ah[mi][1], ah[mi][2], ah[mi][3],
                                 bl[ni][0], bl[ni][1]);
                    }
            }
        }
        __syncthreads();
    }

    // ---- epilogue: optional fp32 + optional bf16 hi/lo split; oscale applied ----
#pragma unroll
    for (int mi = 0; mi < 2; mi++) {
        int row = m0 + wm * 32 + mi * 16 + (lane >> 2);
#pragma unroll
        for (int ni = 0; ni < 8; ni++) {
            int col = n0 + wn * 64 + ni * 8 + (lane & 3) * 2;
            float b0 = bias[col], b1 = bias[col + 1];
            float v00 = (c[mi][ni][0] + b0) * oscale, v01 = (c[mi][ni][1] + b1) * oscale;
            float v10 = (c[mi][ni][2] + b0) * oscale, v11 = (c[mi][ni][3] + b1) * oscale;
            if (C != nullptr) {
                *(float2*)(C + (size_t)row * DD + col) = make_float2(v00, v01);
                *(float2*)(C + (size_t)(row + 8) * DD + col) = make_float2(v10, v11);
            }
            if (Chi != nullptr) {
                uint32_t h0 = packbf2(v00, v01);
                uint32_t l0v = packlo2(v00, v01, h0);
                uint32_t h1 = packbf2(v10, v11);
                uint32_t l1v = packlo2(v10, v11, h1);
                *(uint32_t*)(Chi + (size_t)row * DD + col) = h0;
                *(uint32_t*)(Clo + (size_t)row * DD + col) = l0v;
                *(uint32_t*)(Chi + (size_t)(row + 8) * DD + col) = h1;
                *(uint32_t*)(Clo + (size_t)(row + 8) * DD + col) = l1v;
            }
        }
    }
}

// ---------------- HMMA flash attention: ctx = (1-w) * softmax(Q K^T) V ----------------
// 4 warps, q-tile 64 (16 rows/warp), k-tile 64, 2-stage cp.async K/V pipeline, occ 3.
// Q pre-scaled by log2(e) -> softmax in exp2 domain.
#define FS 72
#define FL_KV_STG_B 36864        // 4 * 64*72*2
#define FL_ARR_B 9216            // 64*72*2
#define FL_SMEM_B (2 * FL_KV_STG_B)  // 73728

__global__ __launch_bounds__(128, 3) void flash_mma() {
    extern __shared__ char fsmem[];
    const uint32_t smB = smem_u32(fsmem);
    const int tid = threadIdx.x;
    const int lane = tid & 31, wid = tid >> 5;
    const int b = blockIdx.z, h = blockIdx.y, q0 = blockIdx.x * 64;
    const size_t hOff = (size_t)h * HCC;

    const __nv_bfloat16* kvsrc[4] = {
        g_Kh + (size_t)(b * TT) * DD + hOff,
        g_Kl + (size_t)(b * TT) * DD + hOff,
        g_Vh + (size_t)(b * TT) * DD + hOff,
        g_Vl + (size_t)(b * TT) * DD + hOff };

    // prologue: KV stage0 (128 threads x 16 chunks)
    {
#pragma unroll
        for (int i = 0; i < 16; i++) {
            int cck = tid + i * 128;
            int arr = cck >> 9, r = (cck >> 3) & 63, c8 = (cck & 7) * 8;
            CP_ASYNC16(smB + arr * FL_ARR_B + r * (FS * 2) + c8 * 2,
                       kvsrc[arr] + (size_t)r * DD + c8);
        }
        CP_COMMIT();
    }

    const int r0 = wid * 16;
    // ---- Q fragments straight from global (A-frag = 2 consecutive-k bf16) ----
    uint32_t qah[4][4], qal[4][4];
    {
        const int rA = lane >> 2, cA = (lane & 3) * 2;
        const __nv_bfloat16* qhp = g_Qh + (size_t)(b * TT + q0 + r0 + rA) * DD + hOff + cA;
        const __nv_bfloat16* qlp = g_Ql + (size_t)(b * TT + q0 + r0 + rA) * DD + hOff + cA;
#pragma unroll
        for (int kk = 0; kk < 4; kk++) {
            qah[kk][0] = *(const uint32_t*)(qhp + kk * 16);
            qah[kk][1] = *(const uint32_t*)(qhp + 8 * DD + kk * 16);
            qah[kk][2] = *(const uint32_t*)(qhp + kk * 16 + 8);
            qah[kk][3] = *(const uint32_t*)(qhp + 8 * DD + kk * 16 + 8);
            qal[kk][0] = *(const uint32_t*)(qlp + kk * 16);
            qal[kk][1] = *(const uint32_t*)(qlp + 8 * DD + kk * 16);
            qal[kk][2] = *(const uint32_t*)(qlp + kk * 16 + 8);
            qal[kk][3] = *(const uint32_t*)(qlp + 8 * DD + kk * 16 + 8);
        }
    }

    const int lrQ = (lane & 7) + ((lane >> 3) & 1) * 8;   // V rows
    const int lcQ = (lane >> 4) * 8;                       // V cols
    const int lrK = (lane & 7) + (lane >> 4) * 8;
    const int lcK = ((lane >> 3) & 1) * 8;
    const uint32_t kOff = (uint32_t)(lrK * FS + lcK) * 2;
    const uint32_t vOff = (uint32_t)(lrQ * FS + lcQ) * 2;

    float m0 = -3.0e38f, m1 = -3.0e38f, l0 = 0.0f, l1 = 0.0f;
    float o[8][4];
#pragma unroll
    for (int i = 0; i < 8; i++)
#pragma unroll
        for (int j = 0; j < 4; j++) o[i][j] = 0.0f;

    const int NKT = TT / 64;  // 32
    for (int kt = 0; kt < NKT; kt++) {
        if (kt + 1 < NKT) {
            uint32_t sb = smB + ((kt + 1) & 1) * FL_KV_STG_B;
            int t0 = (kt + 1) * 64;
#pragma unroll
            for (int i = 0; i < 16; i++) {
                int cck = tid + i * 128;
                int arr = cck >> 9, r = (cck >> 3) & 63, c8 = (cck & 7) * 8;
                CP_ASYNC16(sb + arr * FL_ARR_B + r * (FS * 2) + c8 * 2,
                           kvsrc[arr] + (size_t)(t0 + r) * DD + c8);
            }
            CP_COMMIT();
            CP_WAIT1();
        } else {
            CP_WAIT0();
        }
        __syncthreads();

        const uint32_t stg = smB + (kt & 1) * FL_KV_STG_B;

        // ---- S = Q K^T (16 x 64 per warp), 3-mma split, reg-peak-controlled ----
        float s[8][4];
#pragma unroll
        for (int i = 0; i < 8; i++)
#pragma unroll
            for (int j = 0; j < 4; j++) s[i][j] = 0.0f;
#pragma unroll
        for (int kk = 0; kk < 4; kk++) {
            {
                uint32_t kb[8][2];
#pragma unroll
                for (int p = 0; p < 4; p++) {
                    uint32_t a = stg + kOff + (uint32_t)(p * 16 * FS + kk * 16) * 2;
                    LDM_X4(kb[p * 2][0], kb[p * 2][1], kb[p * 2 + 1][0], kb[p * 2 + 1][1], a);
                }
#pragma unroll
                for (int nj = 0; nj < 8; nj++) {
                    float* ss = s[nj];
                    MMA16816(ss[0], ss[1], ss[2], ss[3],
                             qah[kk][0], qah[kk][1], qah[kk][2], qah[kk][3],
                             kb[nj][0], kb[nj][1]);
                    MMA16816(ss[0], ss[1], ss[2], ss[3],
                             qal[kk][0], qal[kk][1], qal[kk][2], qal[kk][3],
                             kb[nj][0], kb[nj][1]);
                }
            }
            {
                uint32_t kl[8][2];
#pragma unroll
                for (int p = 0; p < 4; p++) {
                    uint32_t a = stg + kOff + (uint32_t)(p * 16 * FS + kk * 16) * 2 + FL_ARR_B;
                    LDM_X4(kl[p * 2][0], kl[p * 2][1], kl[p * 2 + 1][0], kl[p * 2 + 1][1], a);
                }
#pragma unroll
                for (int nj = 0; nj < 8; nj++) {
                    float* ss = s[nj];
                    MMA16816(ss[0], ss[1], ss[2], ss[3],
                             qah[kk][0], qah[kk][1], qah[kk][2], qah[kk][3],
                             kl[nj][0], kl[nj][1]);
                }
            }
        }

        // ---- online softmax (exp2 domain; Q pre-scaled by log2e) ----
        float mr0 = s[0][0], mr1 = s[0][2];
#pragma unroll
        for (int nj = 0; nj < 8; nj++) {
            mr0 = fmaxf(mr0, fmaxf(s[nj][0], s[nj][1]));
            mr1 = fmaxf(mr1, fmaxf(s[nj][2], s[nj][3]));
        }
        mr0 = fmaxf(mr0, __shfl_xor_sync(0xffffffffu, mr0, 1, 4));
        mr0 = fmaxf(mr0, __shfl_xor_sync(0xffffffffu, mr0, 2, 4));
        mr1 = fmaxf(mr1, __shfl_xor_sync(0xffffffffu, mr1, 1, 4));
        mr1 = fmaxf(mr1, __shfl_xor_sync(0xffffffffu, mr1, 2, 4));
        float mn0 = fmaxf(m0, mr0), mn1 = fmaxf(m1, mr1);
        float cor0 = exp2f(m0 - mn0), cor1 = exp2f(m1 - mn1);
        m0 = mn0; m1 = mn1;
        float rs0 = 0.0f, rs1 = 0.0f;
#pragma unroll
        for (int nj = 0; nj < 8; nj++) {
            s[nj][0] = exp2f(s[nj][0] - mn0);
            s[nj][1] = exp2f(s[nj][1] - mn0);
            s[nj][2] = exp2f(s[nj][2] - mn1);
            s[nj][3] = exp2f(s[nj][3] - mn1);
            rs0 += s[nj][0] + s[nj][1];
            rs1 += s[nj][2] + s[nj][3];
        }
        rs0 += __shfl_xor_sync(0xffffffffu, rs0, 1, 4);
        rs0 += __shfl_xor_sync(0xffffffffu, rs0, 2, 4);
        rs1 += __shfl_xor_sync(0xffffffffu, rs1, 1, 4);
        rs1 += __shfl_xor_sync(0xffffffffu, rs1, 2, 4);
        l0 = l0 * cor0 + rs0;
        l1 = l1 * cor1 + rs1;
#pragma unroll
        for (int nd = 0; nd < 8; nd++) {
            o[nd][0] *= cor0; o[nd][1] *= cor0;
            o[nd][2] *= cor1; o[nd][3] *= cor1;
        }

        // ---- repack P (C-frag -> A-frag) with hi/lo split; s dies here ----
        uint32_t pah[4][4], pal[4][4];
#pragma unroll
        for (int kk = 0; kk < 4; kk++) {
            pah[kk][0] = packbf2(s[2 * kk][0], s[2 * kk][1]);
            pah[kk][1] = packbf2(s[2 * kk][2], s[2 * kk][3]);
            pah[kk][2] = packbf2(s[2 * kk + 1][0], s[2 * kk + 1][1]);
            pah[kk][3] = packbf2(s[2 * kk + 1][2], s[2 * kk + 1][3]);
            pal[kk][0] = packlo2(s[2 * kk][0], s[2 * kk][1], pah[kk][0]);
            pal[kk][1] = packlo2(s[2 * kk][2], s[2 * kk][3], pah[kk][1]);
            pal[kk][2] = packlo2(s[2 * kk + 1][0], s[2 * kk + 1][1], pah[kk][2]);
            pal[kk][3] = packlo2(s[2 * kk + 1][2], s[2 * kk + 1][3], pah[kk][3]);
        }

        // ---- O += P V (16 x 64 per warp), 3-mma split, reg-peak-controlled ----
        const uint32_t vbaseH = stg + 2 * FL_ARR_B + vOff;
#pragma unroll
        for (int kk = 0; kk < 4; kk++) {
            {
                uint32_t vb[8][2];
#pragma unroll
                for (int q = 0; q < 4; q++) {
                    uint32_t a = vbaseH + (uint32_t)(kk * 16 * FS + q * 16) * 2;
                    LDM_X4_T(vb[q * 2][0], vb[q * 2][1], vb[q * 2 + 1][0], vb[q * 2 + 1][1], a);
                }
#pragma unroll
                for (int nd = 0; nd < 8; nd++) {
                    float* oo = o[nd];
                    MMA16816(oo[0], oo[1], oo[2], oo[3],
                             pah[kk][0], pah[kk][1], pah[kk][2], pah[kk][3],
                             vb[nd][0], vb[nd][1]);
                    MMA16816(oo[0], oo[1], oo[2], oo[3],
                             pal[kk][0], pal[kk][1], pal[kk][2], pal[kk][3],
                             vb[nd][0], vb[nd][1]);
                }
            }
            {
                uint32_t vl[8][2];
#pragma unroll
                for (int q = 0; q < 4; q++) {
                    uint32_t a = vbaseH + (uint32_t)(kk * 16 * FS + q * 16) * 2 + FL_ARR_B;
                    LDM_X4_T(vl[q * 2][0], vl[q * 2][1], vl[q * 2 + 1][0], vl[q * 2 + 1][1], a);
                }
#pragma unroll
                for (int nd = 0; nd < 8; nd++) {
                    float* oo = o[nd];
                    MMA16816(oo[0], oo[1], oo[2], oo[3],
                             pah[kk][0], pah[kk][1], pah[kk][2], pah[kk][3],
                             vl[nd][0], vl[nd][1]);
                }
            }
        }
        __syncthreads();
    }

    // ---- epilogue: ctx = (1-w) * O / l ----
    float w1 = g_wmix[1];
    float inv0 = w1 / l0, inv1 = w1 / l1;
    int row0 = q0 + r0 + (lane >> 2);
    float* dst0 = g_ctx + (size_t)(b * TT + row0) * DD + hOff + (lane & 3) * 2;
    float* dst1 = dst0 + 8 * DD;
#pragma unroll
    for (int nd = 0; nd < 8; nd++) {
        *(float2*)(dst0 + nd * 8) = make_float2(o[nd][0] * inv0, o[nd][1] * inv0);
        *(float2*)(dst1 + nd * 8) = make_float2(o[nd][2] * inv1, o[nd][3] * inv1);
    }
}

// ---------------- prefix sums of V along t, per (b,h,c): hierarchical ----------------
__global__ __launch_bounds__(256) void prefix_kernel() {
    __shared__ float part[4][64];
    int b = blockIdx.x >> 4;
    int h = blockIdx.x & 15;
    int c = threadIdx.x & 63;
    int ch = threadIdx.x >> 6;  // 0..3, each 512 t
    const float* vp = g_V + ((size_t)(b * TT + ch * 512)) * DD + h * HCC + c;
    float s0 = 0.0f, s1 = 0.0f, s2 = 0.0f, s3 = 0.0f;
    for (int t = 0; t < 512; t += 4) {
        s0 += vp[(size_t)(t + 0) * DD];
        s1 += vp[(size_t)(t + 1) * DD];
        s2 += vp[(size_t)(t + 2) * DD];
        s3 += vp[(size_t)(t + 3) * DD];
    }
    part[ch][c] = (s0 + s1) + (s2 + s3);
    __syncthreads();
    float run = 0.0f;
    for (int i = 0; i < ch; i++) run += part[i][c];
    float* ps = g_PS + ((size_t)(b * TT + ch * 512)) * DD + h * HCC + c;
    for (int t = 0; t < 512; t++) {
        run += vp[(size_t)t * DD];
        ps[(size_t)t * DD] = run;
    }
}

// ---------------- PV: out_split = ctx + w * (P @ V) via 99-tap conv + prefix ----------------
__global__ __launch_bounds__(256) void pv_kernel() {
    __shared__ float Vw[162 * 64];
    __shared__ float Pv[MAXL + 1];
    int b = blockIdx.z, h = blockIdx.y;
    int q0 = blockIdx.x * 64;
    int tid = threadIdx.x;
    if (tid <= MAXL) Pv[tid] = g_Pval[h][tid];
    for (int idx = tid; idx < 162 * 64; idx += 256) {
        int r = idx >> 6, c = idx & 63;
        int tg = q0 - 99 + r;
        Vw[idx] = (tg >= 0) ? g_V[((size_t)(b * TT + tg)) * DD + h * HCC + c] : 0.0f;
    }
    __syncthreads();
    int c = tid & 63, qq = tid >> 6;
    float w = g_wmix[0];
#pragma unroll 1
    for (int ii = 0; ii < 16; ii++) {
        int ql = qq * 16 + ii;
        int qg = q0 + ql;
        float a0 = 0.0f, a1 = 0.0f, a2 = 0.0f, a3 = 0.0f;
        int jmax = min(99, qg);
        int j = 1;
        for (; j + 3 <= jmax; j += 4) {
            a0 += Pv[j]     * Vw[((ql - j + 99) << 6) | c];
            a1 += Pv[j + 1] * Vw[((ql - j + 98) << 6) | c];
            a2 += Pv[j + 2] * Vw[((ql - j + 97) << 6) | c];
            a3 += Pv[j + 3] * Vw[((ql - j + 96) << 6) | c];
        }
        for (; j <= jmax; j++)
            a0 += Pv[j] * Vw[((ql - j + 99) << 6) | c];
        float acc = (a0 + a1) + (a2 + a3);
        if (qg >= 100)
            acc += Pv[MAXL] * g_PS[((size_t)(b * TT + qg - 100)) * DD + h * HCC + c];
        size_t oi = ((size_t)(b * TT + qg)) * DD + h * HCC + c;
        float outv = g_ctx[oi] + w * acc;
        __nv_bfloat16 hh = __float2bfloat16(outv);
        g_xh[oi] = hh;
        g_xl[oi] = __float2bfloat16(outv - __bfloat162float(hh));
    }
}

// ---------------- launch ----------------
extern "C" void kernel_launch(void* const* d_in, const int* in_sizes, int n_in,
                              void* d_out, int out_size) {
    const float* x   = (const float*)d_in[0];
    const float* mu  = (const float*)d_in[1];
    const float* lam = (const float*)d_in[2];
    const float* g1  = (const float*)d_in[3];
    const float* g2  = (const float*)d_in[4];
    const float* th1 = (const float*)d_in[5];
    const float* th2 = (const float*)d_in[6];
    const float* Wq  = (const float*)d_in[7];
    const float* bq  = (const float*)d_in[8];
    const float* Wk  = (const float*)d_in[9];
    const float* bk  = (const float*)d_in[10];
    const float* Wv  = (const float*)d_in[11];
    const float* bv  = (const float*)d_in[12];
    const float* Wf  = (const float*)d_in[13];
    const float* bf  = (const float*)d_in[14];
    float* out = (float*)d_out;

    float *Vd;
    cudaGetSymbolAddress((void**)&Vd, g_V);
    __nv_bfloat16 *xh, *xl, *wh, *wl, *qh, *ql, *kh, *kl, *vh, *vl;
    cudaGetSymbolAddress((void**)&xh, g_xh);
    cudaGetSymbolAddress((void**)&xl, g_xl);
    cudaGetSymbolAddress((void**)&wh, g_wh);
    cudaGetSymbolAddress((void**)&wl, g_wl);
    cudaGetSymbolAddress((void**)&qh, g_Qh);
    cudaGetSymbolAddress((void**)&ql, g_Ql);
    cudaGetSymbolAddress((void**)&kh, g_Kh);
    cudaGetSymbolAddress((void**)&kl, g_Kl);
    cudaGetSymbolAddress((void**)&vh, g_Vh);
    cudaGetSymbolAddress((void**)&vl, g_Vl);

    setup_kernel<<<1, 32>>>(mu, lam, g1, g2, th1, th2);

    const int NX4 = (BB * TT * DD) / 4;
    const int NW4ALL = (4 * DD * DD) / 4;
    cvt_split<<<(NX4 + 255) / 256, 256>>>(x, xh, xl, NX4);
    cvt_split_w<<<NW4ALL / 256, 256>>>(Wq, Wk, Wv, Wf);

    const float LOG2E = 1.4426950408889634f;
    cudaFuncSetAttribute(gemm_mma, cudaFuncAttributeMaxDynamicSharedMemorySize, G_SMEM);
    dim3 ggrid(DD / 128, (BB * TT) / 128);
    gemm_mma<<<ggrid, 256, G_SMEM>>>(xh, xl, wh + 0 * DD * DD, wl + 0 * DD * DD, bq,
                                     nullptr, qh, ql, LOG2E);
    gemm_mma<<<ggrid, 256, G_SMEM>>>(xh, xl, wh + 1 * DD * DD, wl + 1 * DD * DD, bk,
                                     nullptr, kh, kl, 1.0f);
    gemm_mma<<<ggrid, 256, G_SMEM>>>(xh, xl, wh + 2 * DD * DD, wl + 2 * DD * DD, bv,
                                     Vd, vh, vl, 1.0f);

    cudaFuncSetAttribute(flash_mma, cudaFuncAttributeMaxDynamicSharedMemorySize, FL_SMEM_B);
    dim3 fgrid(TT / 64, NHH, BB);
    flash_mma<<<fgrid, 128, FL_SMEM_B>>>();

    prefix_kernel<<<BB * NHH, 256>>>();

    dim3 pvgrid(TT / 64, NHH, BB);
    pv_kernel<<<pvgrid, 256>>>();

    gemm_mma<<<ggrid, 256, G_SMEM>>>(xh, xl, wh + 3 * DD * DD, wl + 3 * DD * DD, bf, out,
                                     nullptr, nullptr, 1.0f);
}

// round 11
// speedup vs baseline: 2.9677x; 1.0052x over previous
#include <cuda_runtime.h>
#include <cuda_bf16.h>
#include <math.h>
#include <stdint.h>

#define BB 4
#define TT 2048
#define NHH 16
#define HCC 64
#define DD 1024
#define RHH 4
#define SHH 6
#define MAXL 100

// ---------------- scratch (device globals: allowed) ----------------
__device__ float g_V[BB * TT * DD];
__device__ float g_ctx[BB * TT * DD];
__device__ float g_PS[BB * TT * DD];
__device__ float g_Pval[NHH][MAXL + 1];
__device__ float g_wmix[2];  // [0]=w, [1]=1-w

// bf16 split operand buffers
__device__ __nv_bfloat16 g_xh[BB * TT * DD];
__device__ __nv_bfloat16 g_xl[BB * TT * DD];
__device__ __nv_bfloat16 g_wh[4 * DD * DD];
__device__ __nv_bfloat16 g_wl[4 * DD * DD];
__device__ __nv_bfloat16 g_Qh[BB * TT * DD];
__device__ __nv_bfloat16 g_Ql[BB * TT * DD];
__device__ __nv_bfloat16 g_Kh[BB * TT * DD];
__device__ __nv_bfloat16 g_Kl[BB * TT * DD];
__device__ __nv_bfloat16 g_Vh[BB * TT * DD];
__device__ __nv_bfloat16 g_Vl[BB * TT * DD];

// ---------------- PTX helpers (baseline ISA only: sm_80-class) ----------------
__device__ __forceinline__ uint32_t smem_u32(const void* p) {
    uint32_t a;
    asm("{ .reg .u64 t; cvta.to.shared.u64 t, %1; cvt.u32.u64 %0, t; }" : "=r"(a) : "l"(p));
    return a;
}

#define CP_ASYNC16(dst, src) \
    asm volatile("cp.async.cg.shared.global [%0], [%1], 16;" :: "r"(dst), "l"(src))
#define CP_COMMIT() asm volatile("cp.async.commit_group;")
#define CP_WAIT1() asm volatile("cp.async.wait_group 1;")
#define CP_WAIT0() asm volatile("cp.async.wait_group 0;")

#define LDM_X4(r0, r1, r2, r3, addr) \
    asm volatile("ldmatrix.sync.aligned.m8n8.x4.shared.b16 {%0,%1,%2,%3}, [%4];" \
                 : "=r"(r0), "=r"(r1), "=r"(r2), "=r"(r3) : "r"(addr))

#define LDM_X4_T(r0, r1, r2, r3, addr) \
    asm volatile("ldmatrix.sync.aligned.m8n8.x4.trans.shared.b16 {%0,%1,%2,%3}, [%4];" \
                 : "=r"(r0), "=r"(r1), "=r"(r2), "=r"(r3) : "r"(addr))

#define MMA16816(c0, c1, c2, c3, a0, a1, a2, a3, b0, b1) \
    asm volatile("mma.sync.aligned.m16n8k16.row.col.f32.bf16.bf16.f32 " \
                 "{%0,%1,%2,%3}, {%4,%5,%6,%7}, {%8,%9}, {%0,%1,%2,%3};" \
                 : "+f"(c0), "+f"(c1), "+f"(c2), "+f"(c3) \
                 : "r"(a0), "r"(a1), "r"(a2), "r"(a3), "r"(b0), "r"(b1))

// SW128 swizzle (Swizzle<3,4,3>): XOR bits [6:4] with bits [9:7]
#define SW128B(o) ((o) ^ (((o) >> 3) & 0x70))

__device__ __forceinline__ uint32_t packbf2(float a, float b) {
    __nv_bfloat162 t = __floats2bfloat162_rn(a, b);
    return *(uint32_t*)&t;
}
__device__ __forceinline__ uint32_t packlo2(float a, float b, uint32_t hi) {
    __nv_bfloat162 hv = *(__nv_bfloat162*)&hi;
    return packbf2(a - __bfloat162float(hv.x), b - __bfloat162float(hv.y));
}

// ---------------- setup: Pval table + mix weight ----------------
__global__ void setup_kernel(const float* __restrict__ mu,
                             const float* __restrict__ lam,
                             const float* __restrict__ g1,
                             const float* __restrict__ g2,
                             const float* __restrict__ th1,
                             const float* __restrict__ th2) {
    int h = threadIdx.x;
    if (h == 0) {
        float w = 1.0f / (1.0f + __expf(-mu[0]));
        g_wmix[0] = w;
        g_wmix[1] = 1.0f - w;
    }
    if (h < NHH) {
        float base, theta = 0.0f;
        int kind;
        if (h < RHH) { base = lam[h]; kind = 0; }
        else if (h < RHH + SHH) { base = g1[h - RHH]; theta = th1[h - RHH]; kind = 1; }
        else { base = g2[h - RHH - SHH]; theta = th2[h - RHH - SHH]; kind = 2; }
        float p = 1.0f;
        g_Pval[h][0] = 0.0f;
        for (int L = 1; L <= MAXL; L++) {
            p *= base;
            float v = p;
            if (kind == 1) v *= sinf(theta * (float)L);
            else if (kind == 2) v *= cosf(theta * (float)L);
            g_Pval[h][L] = v;
        }
    }
}

// ---------------- fp32 -> bf16 hi/lo split (x / activations) ----------------
__global__ __launch_bounds__(256) void cvt_split(const float* __restrict__ in,
                                                 __nv_bfloat16* __restrict__ hi,
                                                 __nv_bfloat16* __restrict__ lo,
                                                 int n4) {
    int i = blockIdx.x * blockDim.x + threadIdx.x;
    if (i >= n4) return;
    float4 v = ((const float4*)in)[i];
    __nv_bfloat16 h0 = __float2bfloat16(v.x);
    __nv_bfloat16 h1 = __float2bfloat16(v.y);
    __nv_bfloat16 h2 = __float2bfloat16(v.z);
    __nv_bfloat16 h3 = __float2bfloat16(v.w);
    __nv_bfloat16 l0 = __float2bfloat16(v.x - __bfloat162float(h0));
    __nv_bfloat16 l1 = __float2bfloat16(v.y - __bfloat162float(h1));
    __nv_bfloat16 l2 = __float2bfloat16(v.z - __bfloat162float(h2));
    __nv_bfloat16 l3 = __float2bfloat16(v.w - __bfloat162float(h3));
    __nv_bfloat162 hp0 = __halves2bfloat162(h0, h1);
    __nv_bfloat162 hp1 = __halves2bfloat162(h2, h3);
    __nv_bfloat162 lp0 = __halves2bfloat162(l0, l1);
    __nv_bfloat162 lp1 = __halves2bfloat162(l2, l3);
    uint2 hw, lw;
    hw.x = *(uint32_t*)&hp0; hw.y = *(uint32_t*)&hp1;
    lw.x = *(uint32_t*)&lp0; lw.y = *(uint32_t*)&lp1;
    ((uint2*)hi)[i] = hw;
    ((uint2*)lo)[i] = lw;
}

// fused: all 4 weight matrices -> g_wh/g_wl (contiguous)
__global__ __launch_bounds__(256) void cvt_split_w(const float* __restrict__ w0,
                                                   const float* __restrict__ w1,
                                                   const float* __restrict__ w2,
                                                   const float* __restrict__ w3) {
    int i = blockIdx.x * blockDim.x + threadIdx.x;
    const int per = DD * DD / 4;
    int mat = i / per, local = i - mat * per;
    const float* src = (mat == 0) ? w0 : (mat == 1) ? w1 : (mat == 2) ? w2 : w3;
    float4 v = ((const float4*)src)[local];
    __nv_bfloat16 h0 = __float2bfloat16(v.x);
    __nv_bfloat16 h1 = __float2bfloat16(v.y);
    __nv_bfloat16 h2 = __float2bfloat16(v.z);
    __nv_bfloat16 h3 = __float2bfloat16(v.w);
    __nv_bfloat16 l0 = __float2bfloat16(v.x - __bfloat162float(h0));
    __nv_bfloat16 l1 = __float2bfloat16(v.y - __bfloat162float(h1));
    __nv_bfloat16 l2 = __float2bfloat16(v.z - __bfloat162float(h2));
    __nv_bfloat16 l3 = __float2bfloat16(v.w - __bfloat162float(h3));
    __nv_bfloat162 hp0 = __halves2bfloat162(h0, h1);
    __nv_bfloat162 hp1 = __halves2bfloat162(h2, h3);
    __nv_bfloat162 lp0 = __halves2bfloat162(l0, l1);
    __nv_bfloat162 lp1 = __halves2bfloat162(l2, l3);
    uint2 hw, lw;
    hw.x = *(uint32_t*)&hp0; hw.y = *(uint32_t*)&hp1;
    lw.x = *(uint32_t*)&lp0; lw.y = *(uint32_t*)&lp1;
    ((uint2*)g_wh)[i] = hw;
    ((uint2*)g_wl)[i] = lw;
}

// ---------------- HMMA bf16x2 GEMM: C = oscale*(A @ W^T + bias) ----
#define G_TILE_B 10240          // 128*40*2
#define G_STAGE_B (4 * G_TILE_B)
#define G_SMEM (2 * G_STAGE_B)  // 81920

__global__ __launch_bounds__(256, 2) void gemm_mma(
    const __nv_bfloat16* __restrict__ Ah, const __nv_bfloat16* __restrict__ Al,
    const __nv_bfloat16* __restrict__ Bh, const __nv_bfloat16* __restrict__ Bl,
    const float* __restrict__ bias, float* __restrict__ C,
    __nv_bfloat16* __restrict__ Chi, __nv_bfloat16* __restrict__ Clo,
    float oscale) {
    extern __shared__ char gsm[];
    const uint32_t smBase = smem_u32(gsm);

    const int tid = threadIdx.x;
    const int lane = tid & 31;
    const int wid = tid >> 5;
    const int wm = wid & 3;
    const int wn = wid >> 2;
    const int m0 = blockIdx.y * 128;
    const int n0 = blockIdx.x * 128;

    const __nv_bfloat16* srcs[4];
    srcs[0] = Ah + (size_t)m0 * DD;
    srcs[1] = Al + (size_t)m0 * DD;
    srcs[2] = Bh + (size_t)n0 * DD;
    srcs[3] = Bl + (size_t)n0 * DD;

    const int ch0 = tid * 2;
    const int lrow0 = ch0 >> 2, lcol0 = (ch0 & 3) * 8;
    const int lrow1 = (ch0 + 1) >> 2, lcol1 = ((ch0 + 1) & 3) * 8;

    float c[2][8][4];
#pragma unroll
    for (int mi = 0; mi < 2; mi++)
#pragma unroll
        for (int ni = 0; ni < 8; ni++)
#pragma unroll
            for (int r = 0; r < 4; r++) c[mi][ni][r] = 0.0f;

    {
        uint32_t sb = smBase;
#pragma unroll
        for (int t = 0; t < 4; t++) {
            CP_ASYNC16(sb + t * G_TILE_B + lrow0 * 80 + lcol0 * 2,
                       srcs[t] + (size_t)lrow0 * DD + lcol0);
            CP_ASYNC16(sb + t * G_TILE_B + lrow1 * 80 + lcol1 * 2,
                       srcs[t] + (size_t)lrow1 * DD + lcol1);
        }
        CP_COMMIT();
    }

    const uint32_t aOff = (uint32_t)((wm * 32 + (lane & 15)) * 80 + ((lane >> 4) * 8) * 2);
    const uint32_t bOff = (uint32_t)((wn * 64 + ((lane >> 4) & 1) * 8 + (lane & 7)) * 80 +
                                     (((lane >> 3) & 1) * 8) * 2);

    const int NIT = DD / 32;
    for (int it = 0; it < NIT; it++) {
        if (it + 1 < NIT) {
            uint32_t sb = smBase + ((it + 1) & 1) * G_STAGE_B;
            int k0 = (it + 1) * 32;
#pragma unroll
            for (int t = 0; t < 4; t++) {
                CP_ASYNC16(sb + t * G_TILE_B + lrow0 * 80 + lcol0 * 2,
                           srcs[t] + (size_t)lrow0 * DD + k0 + lcol0);
                CP_ASYNC16(sb + t * G_TILE_B + lrow1 * 80 + lcol1 * 2,
                           srcs[t] + (size_t)lrow1 * DD + k0 + lcol1);
            }
            CP_COMMIT();
            CP_WAIT1();
        } else {
            CP_WAIT0();
        }
        __syncthreads();

        const uint32_t aBase = smBase + (it & 1) * G_STAGE_B;
        const uint32_t bBase = aBase + 2 * G_TILE_B;
#pragma unroll
        for (int kk = 0; kk < 2; kk++) {
            uint32_t ah[2][4], al[2][4];
#pragma unroll
            for (int mi = 0; mi < 2; mi++) {
                uint32_t a = aBase + aOff + (uint32_t)(mi * 16 * 80 + kk * 32);
                LDM_X4(ah[mi][0], ah[mi][1], ah[mi][2], ah[mi][3], a);
                LDM_X4(al[mi][0], al[mi][1], al[mi][2], al[mi][3], a + G_TILE_B);
            }
            {
                uint32_t bh[8][2];
#pragma unroll
                for (int nq = 0; nq < 4; nq++) {
                    uint32_t a = bBase + bOff + (uint32_t)(nq * 16 * 80 + kk * 32);
                    LDM_X4(bh[nq * 2][0], bh[nq * 2][1], bh[nq * 2 + 1][0], bh[nq * 2 + 1][1], a);
                }
#pragma unroll
                for (int mi = 0; mi < 2; mi++)
#pragma unroll
                    for (int ni = 0; ni < 8; ni++) {
                        float* cc = c[mi][ni];
                        MMA16816(cc[0], cc[1], cc[2], cc[3],
                                 ah[mi][0], ah[mi][1], ah[mi][2], ah[mi][3],
                                 bh[ni][0], bh[ni][1]);
                        MMA16816(cc[0], cc[1], cc[2], cc[3],
                                 al[mi][0], al[mi][1], al[mi][2], al[mi][3],
                                 bh[ni][0], bh[ni][1]);
                    }
            }
            {
                uint32_t bl[8][2];
#pragma unroll
                for (int nq = 0; nq < 4; nq++) {
                    uint32_t a = bBase + bOff + (uint32_t)(nq * 16 * 80 + kk * 32) + G_TILE_B;
                    LDM_X4(bl[nq * 2][0], bl[nq * 2][1], bl[nq * 2 + 1][0], bl[nq * 2 + 1][1], a);
                }
#pragma unroll
                for (int mi = 0; mi < 2; mi++)
#pragma unroll
                    for (int ni = 0; ni < 8; ni++) {
                        float* cc = c[mi][ni];
                        MMA16816(cc[0], cc[1], cc[2], cc[3],
                                 ah[mi][0], ah[mi][1], ah[mi][2], ah[mi][3],
                                 bl[ni][0], bl[ni][1]);
                    }
            }
        }
        __syncthreads();
    }

    // ---- epilogue ----
#pragma unroll
    for (int mi = 0; mi < 2; mi++) {
        int row = m0 + wm * 32 + mi * 16 + (lane >> 2);
#pragma unroll
        for (int ni = 0; ni < 8; ni++) {
            int col = n0 + wn * 64 + ni * 8 + (lane & 3) * 2;
            float b0 = bias[col], b1 = bias[col + 1];
            float v00 = (c[mi][ni][0] + b0) * oscale, v01 = (c[mi][ni][1] + b1) * oscale;
            float v10 = (c[mi][ni][2] + b0) * oscale, v11 = (c[mi][ni][3] + b1) * oscale;
            if (C != nullptr) {
                *(float2*)(C + (size_t)row * DD + col) = make_float2(v00, v01);
                *(float2*)(C + (size_t)(row + 8) * DD + col) = make_float2(v10, v11);
            }
            if (Chi != nullptr) {
                uint32_t h0 = packbf2(v00, v01);
                uint32_t l0v = packlo2(v00, v01, h0);
                uint32_t h1 = packbf2(v10, v11);
                uint32_t l1v = packlo2(v10, v11, h1);
                *(uint32_t*)(Chi + (size_t)row * DD + col) = h0;
                *(uint32_t*)(Clo + (size_t)row * DD + col) = l0v;
                *(uint32_t*)(Chi + (size_t)(row + 8) * DD + col) = h1;
                *(uint32_t*)(Clo + (size_t)(row + 8) * DD + col) = l1v;
            }
        }
    }
}

// ---------------- HMMA flash attention: ctx = (1-w) * softmax(Q K^T) V ----------------
// 4 warps, q-tile 64, k-tile 64. SW128-swizzled zero-pad tiles (8KB each).
// K hi/lo double-buffered; V hi/lo single-buffered (issued at iter top, consumed
// after softmax -> latency hidden). occ 4 (48KB smem, 128 regs).
#define FL_KH 0            // [2 stages x 8192]
#define FL_KL 16384        // [2 stages x 8192]
#define FL_VH 32768
#define FL_VL 40960
#define FL_SMEM_B (49152 + 1024)

__global__ __launch_bounds__(128, 4) void flash_mma() {
    extern __shared__ char fsmem[];
    uint32_t smRaw = smem_u32(fsmem);
    const uint32_t smB = (smRaw + 1023u) & ~1023u;  // 1KB align for SW128
    const int tid = threadIdx.x;
    const int lane = tid & 31, wid = tid >> 5;
    const int b = blockIdx.z, h = blockIdx.y, q0 = blockIdx.x * 64;
    const size_t hOff = (size_t)h * HCC;

    const __nv_bfloat16* ksrc[2] = {
        g_Kh + (size_t)(b * TT) * DD + hOff,
        g_Kl + (size_t)(b * TT) * DD + hOff };
    const __nv_bfloat16* vsrc[2] = {
        g_Vh + (size_t)(b * TT) * DD + hOff,
        g_Vl + (size_t)(b * TT) * DD + hOff };

    // prologue: K(0) into stage 0
    {
#pragma unroll
        for (int i = 0; i < 8; i++) {
            int cck = tid + i * 128;           // 0..1023
            int arr = cck >> 9;                // 0=Kh,1=Kl
            int r = (cck >> 3) & 63, c16 = cck & 7;
            uint32_t off = SW128B((uint32_t)(r * 128 + c16 * 16));
            CP_ASYNC16(smB + FL_KH + arr * 16384 + off,
                       ksrc[arr] + (size_t)r * DD + c16 * 8);
        }
        CP_COMMIT();
    }

    const int r0 = wid * 16;
    // ---- Q fragments straight from global ----
    uint32_t qah[4][4], qal[4][4];
    {
        const int rA = lane >> 2, cA = (lane & 3) * 2;
        const __nv_bfloat16* qhp = g_Qh + (size_t)(b * TT + q0 + r0 + rA) * DD + hOff + cA;
        const __nv_bfloat16* qlp = g_Ql + (size_t)(b * TT + q0 + r0 + rA) * DD + hOff + cA;
#pragma unroll
        for (int kk = 0; kk < 4; kk++) {
            qah[kk][0] = *(const uint32_t*)(qhp + kk * 16);
            qah[kk][1] = *(const uint32_t*)(qhp + 8 * DD + kk * 16);
            qah[kk][2] = *(const uint32_t*)(qhp + kk * 16 + 8);
            qah[kk][3] = *(const uint32_t*)(qhp + 8 * DD + kk * 16 + 8);
            qal[kk][0] = *(const uint32_t*)(qlp + kk * 16);
            qal[kk][1] = *(const uint32_t*)(qlp + 8 * DD + kk * 16);
            qal[kk][2] = *(const uint32_t*)(qlp + kk * 16 + 8);
            qal[kk][3] = *(const uint32_t*)(qlp + 8 * DD + kk * 16 + 8);
        }
    }

    // lane pieces: K (non-trans ldmatrix) rows/slots; V (trans) rows/slots
    const int lrK = (lane & 7) + (lane >> 4) * 8;
    const int ksl = (lane >> 3) & 1;                 // 16B slot within kk pair
    const int lrV = (lane & 7) + ((lane >> 3) & 1) * 8;
    const int vsl = (lane >> 4);                     // 16B slot within q pair

    float m0 = -3.0e38f, m1 = -3.0e38f, l0 = 0.0f, l1 = 0.0f;
    float o[8][4];
#pragma unroll
    for (int i = 0; i < 8; i++)
#pragma unroll
        for (int j = 0; j < 4; j++) o[i][j] = 0.0f;

    const int NKT = TT / 64;  // 32
    for (int kt = 0; kt < NKT; kt++) {
        CP_WAIT0();          // K(kt) landed (V already drained last iter)
        __syncthreads();     // publish K(kt); all PV(kt-1) reads done

        if (kt + 1 < NKT) {
            int t0 = (kt + 1) * 64;
            uint32_t sb = smB + FL_KH + ((kt + 1) & 1) * 8192;
#pragma unroll
            for (int i = 0; i < 8; i++) {
                int cck = tid + i * 128;
                int arr = cck >> 9;
                int r = (cck >> 3) & 63, c16 = cck & 7;
                uint32_t off = SW128B((uint32_t)(r * 128 + c16 * 16));
                CP_ASYNC16(sb + arr * 16384 + off,
                           ksrc[arr] + (size_t)(t0 + r) * DD + c16 * 8);
            }
            CP_COMMIT();
        }
        {
            int t0 = kt * 64;
#pragma unroll
            for (int i = 0; i < 8; i++) {
                int cck = tid + i * 128;
                int arr = cck >> 9;
                int r = (cck >> 3) & 63, c16 = cck & 7;
                uint32_t off = SW128B((uint32_t)(r * 128 + c16 * 16));
                CP_ASYNC16(smB + FL_VH + arr * 8192 + off,
                           vsrc[arr] + (size_t)(t0 + r) * DD + c16 * 8);
            }
            CP_COMMIT();
        }

        const uint32_t kstg = smB + FL_KH + (kt & 1) * 8192;

        // ---- S = Q K^T (16 x 64 per warp), 3-mma split ----
        float s[8][4];
#pragma unroll
        for (int i = 0; i < 8; i++)
#pragma unroll
            for (int j = 0; j < 4; j++) s[i][j] = 0.0f;
#pragma unroll
        for (int kk = 0; kk < 4; kk++) {
            {
                uint32_t kb[8][2];
#pragma unroll
                for (int p = 0; p < 4; p++) {
                    uint32_t off = SW128B((uint32_t)((p * 16 + lrK) * 128 +
                                                     (kk * 2 + ksl) * 16));
                    LDM_X4(kb[p * 2][0], kb[p * 2][1], kb[p * 2 + 1][0], kb[p * 2 + 1][1],
                           kstg + off);
                }
#pragma unroll
                for (int nj = 0; nj < 8; nj++) {
                    float* ss = s[nj];
                    MMA16816(ss[0], ss[1], ss[2], ss[3],
                             qah[kk][0], qah[kk][1], qah[kk][2], qah[kk][3],
                             kb[nj][0], kb[nj][1]);
                    MMA16816(ss[0], ss[1], ss[2], ss[3],
                             qal[kk][0], qal[kk][1], qal[kk][2], qal[kk][3],
                             kb[nj][0], kb[nj][1]);
                }
            }
            {
                uint32_t kl[8][2];
#pragma unroll
                for (int p = 0; p < 4; p++) {
                    uint32_t off = SW128B((uint32_t)((p * 16 + lrK) * 128 +
                                                     (kk * 2 + ksl) * 16));
                    LDM_X4(kl[p * 2][0], kl[p * 2][1], kl[p * 2 + 1][0], kl[p * 2 + 1][1],
                           kstg + 16384 + off);
                }
#pragma unroll
                for (int nj = 0; nj < 8; nj++) {
                    float* ss = s[nj];
                    MMA16816(ss[0], ss[1], ss[2], ss[3],
                             qah[kk][0], qah[kk][1], qah[kk][2], qah[kk][3],
                             kl[nj][0], kl[nj][1]);
                }
            }
        }

        // ---- online softmax (exp2 domain; Q pre-scaled by log2e) ----
        float mr0 = s[0][0], mr1 = s[0][2];
#pragma unroll
        for (int nj = 0; nj < 8; nj++) {
            mr0 = fmaxf(mr0, fmaxf(s[nj][0], s[nj][1]));
            mr1 = fmaxf(mr1, fmaxf(s[nj][2], s[nj][3]));
        }
        mr0 = fmaxf(mr0, __shfl_xor_sync(0xffffffffu, mr0, 1, 4));
        mr0 = fmaxf(mr0, __shfl_xor_sync(0xffffffffu, mr0, 2, 4));
        mr1 = fmaxf(mr1, __shfl_xor_sync(0xffffffffu, mr1, 1, 4));
        mr1 = fmaxf(mr1, __shfl_xor_sync(0xffffffffu, mr1, 2, 4));
        float mn0 = fmaxf(m0, mr0), mn1 = fmaxf(m1, mr1);
        float cor0 = exp2f(m0 - mn0), cor1 = exp2f(m1 - mn1);
        m0 = mn0; m1 = mn1;
        float rs0 = 0.0f, rs1 = 0.0f;
#pragma unroll
        for (int nj = 0; nj < 8; nj++) {
            s[nj][0] = exp2f(s[nj][0] - mn0);
            s[nj][1] = exp2f(s[nj][1] - mn0);
            s[nj][2] = exp2f(s[nj][2] - mn1);
            s[nj][3] = exp2f(s[nj][3] - mn1);
            rs0 += s[nj][0] + s[nj][1];
            rs1 += s[nj][2] + s[nj][3];
        }
        rs0 += __shfl_xor_sync(0xffffffffu, rs0, 1, 4);
        rs0 += __shfl_xor_sync(0xffffffffu, rs0, 2, 4);
        rs1 += __shfl_xor_sync(0xffffffffu, rs1, 1, 4);
        rs1 += __shfl_xor_sync(0xffffffffu, rs1, 2, 4);
        l0 = l0 * cor0 + rs0;
        l1 = l1 * cor1 + rs1;
#pragma unroll
        for (int nd = 0; nd < 8; nd++) {
            o[nd][0] *= cor0; o[nd][1] *= cor0;
            o[nd][2] *= cor1; o[nd][3] *= cor1;
        }

        // ---- repack P (C-frag -> A-frag) with hi/lo split ----
        uint32_t pah[4][4], pal[4][4];
#pragma unroll
        for (int kk = 0; kk < 4; kk++) {
            pah[kk][0] = packbf2(s[2 * kk][0], s[2 * kk][1]);
            pah[kk][1] = packbf2(s[2 * kk][2], s[2 * kk][3]);
            pah[kk][2] = packbf2(s[2 * kk + 1][0], s[2 * kk + 1][1]);
            pah[kk][3] = packbf2(s[2 * kk + 1][2], s[2 * kk + 1][3]);
            pal[kk][0] = packlo2(s[2 * kk][0], s[2 * kk][1], pah[kk][0]);
            pal[kk][1] = packlo2(s[2 * kk][2], s[2 * kk][3], pah[kk][1]);
            pal[kk][2] = packlo2(s[2 * kk + 1][0], s[2 * kk + 1][1], pah[kk][2]);
            pal[kk][3] = packlo2(s[2 * kk + 1][2], s[2 * kk + 1][3], pah[kk][3]);
        }

        // ---- wait V(kt), publish, then O += P V ----
        if (kt + 1 < NKT) { CP_WAIT1(); } else { CP_WAIT0(); }
        __syncthreads();

#pragma unroll
        for (int kk = 0; kk < 4; kk++) {
            {
                uint32_t vb[8][2];
#pragma unroll
                for (int q = 0; q < 4; q++) {
                    uint32_t off = SW128B((uint32_t)((kk * 16 + lrV) * 128 +
                                                     (q * 2 + vsl) * 16));
                    LDM_X4_T(vb[q * 2][0], vb[q * 2][1], vb[q * 2 + 1][0], vb[q * 2 + 1][1],
                             smB + FL_VH + off);
                }
#pragma unroll
                for (int nd = 0; nd < 8; nd++) {
                    float* oo = o[nd];
                    MMA16816(oo[0], oo[1], oo[2], oo[3],
                             pah[kk][0], pah[kk][1], pah[kk][2], pah[kk][3],
                             vb[nd][0], vb[nd][1]);
                    MMA16816(oo[0], oo[1], oo[2], oo[3],
                             pal[kk][0], pal[kk][1], pal[kk][2], pal[kk][3],
                             vb[nd][0], vb[nd][1]);
                }
            }
            {
                uint32_t vl[8][2];
#pragma unroll
                for (int q = 0; q < 4; q++) {
                    uint32_t off = SW128B((uint32_t)((kk * 16 + lrV) * 128 +
                                                     (q * 2 + vsl) * 16));
                    LDM_X4_T(vl[q * 2][0], vl[q * 2][1], vl[q * 2 + 1][0], vl[q * 2 + 1][1],
                             smB + FL_VL + off);
                }
#pragma unroll
                for (int nd = 0; nd < 8; nd++) {
                    float* oo = o[nd];
                    MMA16816(oo[0], oo[1], oo[2], oo[3],
                             pah[kk][0], pah[kk][1], pah[kk][2], pah[kk][3],
                             vl[nd][0], vl[nd][1]);
                }
            }
        }
    }

    // ---- epilogue: ctx = (1-w) * O / l ----
    float w1 = g_wmix[1];
    float inv0 = w1 / l0, inv1 = w1 / l1;
    int row0 = q0 + r0 + (lane >> 2);
    float* dst0 = g_ctx + (size_t)(b * TT + row0) * DD + hOff + (lane & 3) * 2;
    float* dst1 = dst0 + 8 * DD;
#pragma unroll
    for (int nd = 0; nd < 8; nd++) {
        *(float2*)(dst0 + nd * 8) = make_float2(o[nd][0] * inv0, o[nd][1] * inv0);
        *(float2*)(dst1 + nd * 8) = make_float2(o[nd][2] * inv1, o[nd][3] * inv1);
    }
}

// ---------------- prefix sums of V along t, per (b,h,c): hierarchical ----------------
__global__ __launch_bounds__(256) void prefix_kernel() {
    __shared__ float part[4][64];
    int b = blockIdx.x >> 4;
    int h = blockIdx.x & 15;
    int c = threadIdx.x & 63;
    int ch = threadIdx.x >> 6;
    const float* vp = g_V + ((size_t)(b * TT + ch * 512)) * DD + h * HCC + c;
    float s0 = 0.0f, s1 = 0.0f, s2 = 0.0f, s3 = 0.0f;
    for (int t = 0; t < 512; t += 4) {
        s0 += vp[(size_t)(t + 0) * DD];
        s1 += vp[(size_t)(t + 1) * DD];
        s2 += vp[(size_t)(t + 2) * DD];
        s3 += vp[(size_t)(t + 3) * DD];
    }
    part[ch][c] = (s0 + s1) + (s2 + s3);
    __syncthreads();
    float run = 0.0f;
    for (int i = 0; i < ch; i++) run += part[i][c];
    float* ps = g_PS + ((size_t)(b * TT + ch * 512)) * DD + h * HCC + c;
    for (int t = 0; t < 512; t++) {
        run += vp[(size_t)t * DD];
        ps[(size_t)t * DD] = run;
    }
}

// ---------------- PV: out_split = ctx + w * (P @ V) via 99-tap conv + prefix ----------------
__global__ __launch_bounds__(256) void pv_kernel() {
    __shared__ float Vw[162 * 64];
    __shared__ float Pv[MAXL + 1];
    int b = blockIdx.z, h = blockIdx.y;
    int q0 = blockIdx.x * 64;
    int tid = threadIdx.x;
    if (tid <= MAXL) Pv[tid] = g_Pval[h][tid];
    for (int idx = tid; idx < 162 * 64; idx += 256) {
        int r = idx >> 6, c = idx & 63;
        int tg = q0 - 99 + r;
        Vw[idx] = (tg >= 0) ? g_V[((size_t)(b * TT + tg)) * DD + h * HCC + c] : 0.0f;
    }
    __syncthreads();
    int c = tid & 63, qq = tid >> 6;
    float w = g_wmix[0];
#pragma unroll 1
    for (int ii = 0; ii < 16; ii++) {
        int ql = qq * 16 + ii;
        int qg = q0 + ql;
        float a0 = 0.0f, a1 = 0.0f, a2 = 0.0f, a3 = 0.0f;
        int jmax = min(99, qg);
        int j = 1;
        for (; j + 3 <= jmax; j += 4) {
            a0 += Pv[j]     * Vw[((ql - j + 99) << 6) | c];
            a1 += Pv[j + 1] * Vw[((ql - j + 98) << 6) | c];
            a2 += Pv[j + 2] * Vw[((ql - j + 97) << 6) | c];
            a3 += Pv[j + 3] * Vw[((ql - j + 96) << 6) | c];
        }
        for (; j <= jmax; j++)
            a0 += Pv[j] * Vw[((ql - j + 99) << 6) | c];
        float acc = (a0 + a1) + (a2 + a3);
        if (qg >= 100)
            acc += Pv[MAXL] * g_PS[((size_t)(b * TT + qg - 100)) * DD + h * HCC + c];
        size_t oi = ((size_t)(b * TT + qg)) * DD + h * HCC + c;
        float outv = g_ctx[oi] + w * acc;
        __nv_bfloat16 hh = __float2bfloat16(outv);
        g_xh[oi] = hh;
        g_xl[oi] = __float2bfloat16(outv - __bfloat162float(hh));
    }
}

// ---------------- launch ----------------
extern "C" void kernel_launch(void* const* d_in, const int* in_sizes, int n_in,
                              void* d_out, int out_size) {
    const float* x   = (const float*)d_in[0];
    const float* mu  = (const float*)d_in[1];
    const float* lam = (const float*)d_in[2];
    const float* g1  = (const float*)d_in[3];
    const float* g2  = (const float*)d_in[4];
    const float* th1 = (const float*)d_in[5];
    const float* th2 = (const float*)d_in[6];
    const float* Wq  = (const float*)d_in[7];
    const float* bq  = (const float*)d_in[8];
    const float* Wk  = (const float*)d_in[9];
    const float* bk  = (const float*)d_in[10];
    const float* Wv  = (const float*)d_in[11];
    const float* bv  = (const float*)d_in[12];
    const float* Wf  = (const float*)d_in[13];
    const float* bf  = (const float*)d_in[14];
    float* out = (float*)d_out;

    float *Vd;
    cudaGetSymbolAddress((void**)&Vd, g_V);
    __nv_bfloat16 *xh, *xl, *wh, *wl, *qh, *ql, *kh, *kl, *vh, *vl;
    cudaGetSymbolAddress((void**)&xh, g_xh);
    cudaGetSymbolAddress((void**)&xl, g_xl);
    cudaGetSymbolAddress((void**)&wh, g_wh);
    cudaGetSymbolAddress((void**)&wl, g_wl);
    cudaGetSymbolAddress((void**)&qh, g_Qh);
    cudaGetSymbolAddress((void**)&ql, g_Ql);
    cudaGetSymbolAddress((void**)&kh, g_Kh);
    cudaGetSymbolAddress((void**)&kl, g_Kl);
    cudaGetSymbolAddress((void**)&vh, g_Vh);
    cudaGetSymbolAddress((void**)&vl, g_Vl);

    setup_kernel<<<1, 32>>>(mu, lam, g1, g2, th1, th2);

    const int NX4 = (BB * TT * DD) / 4;
    const int NW4ALL = (4 * DD * DD) / 4;
    cvt_split<<<(NX4 + 255) / 256, 256>>>(x, xh, xl, NX4);
    cvt_split_w<<<NW4ALL / 256, 256>>>(Wq, Wk, Wv, Wf);

    const float LOG2E = 1.4426950408889634f;
    cudaFuncSetAttribute(gemm_mma, cudaFuncAttributeMaxDynamicSharedMemorySize, G_SMEM);
    dim3 ggrid(DD / 128, (BB * TT) / 128);
    gemm_mma<<<ggrid, 256, G_SMEM>>>(xh, xl, wh + 0 * DD * DD, wl + 0 * DD * DD, bq,
                                     nullptr, qh, ql, LOG2E);
    gemm_mma<<<ggrid, 256, G_SMEM>>>(xh, xl, wh + 1 * DD * DD, wl + 1 * DD * DD, bk,
                                     nullptr, kh, kl, 1.0f);
    gemm_mma<<<ggrid, 256, G_SMEM>>>(xh, xl, wh + 2 * DD * DD, wl + 2 * DD * DD, bv,
                                     Vd, vh, vl, 1.0f);

    cudaFuncSetAttribute(flash_mma, cudaFuncAttributeMaxDynamicSharedMemorySize, FL_SMEM_B);
    dim3 fgrid(TT / 64, NHH, BB);
    flash_mma<<<fgrid, 128, FL_SMEM_B>>>();

    prefix_kernel<<<BB * NHH, 256>>>();

    dim3 pvgrid(TT / 64, NHH, BB);
    pv_kernel<<<pvgrid, 256>>>();

    gemm_mma<<<ggrid, 256, G_SMEM>>>(xh, xl, wh + 3 * DD * DD, wl + 3 * DD * DD, bf, out,
                                     nullptr, nullptr, 1.0f);
}

// round 12
// speedup vs baseline: 3.0839x; 1.0391x over previous
#include <cuda_runtime.h>
#include <cuda_bf16.h>
#include <math.h>
#include <stdint.h>

#define BB 4
#define TT 2048
#define NHH 16
#define HCC 64
#define DD 1024
#define RHH 4
#define SHH 6
#define MAXL 100

// ---------------- scratch (device globals: allowed) ----------------
__device__ float g_V[BB * TT * DD];
__device__ float g_ctx[BB * TT * DD];
__device__ float g_PS[BB * TT * DD];
__device__ float g_Pval[NHH][MAXL + 1];
__device__ float g_wmix[2];  // [0]=w, [1]=1-w

// bf16 split operand buffers
__device__ __nv_bfloat16 g_xh[BB * TT * DD];
__device__ __nv_bfloat16 g_xl[BB * TT * DD];
__device__ __nv_bfloat16 g_wh[4 * DD * DD];
__device__ __nv_bfloat16 g_wl[4 * DD * DD];
__device__ __nv_bfloat16 g_Qh[BB * TT * DD];
__device__ __nv_bfloat16 g_Ql[BB * TT * DD];
__device__ __nv_bfloat16 g_Kh[BB * TT * DD];
__device__ __nv_bfloat16 g_Kl[BB * TT * DD];
__device__ __nv_bfloat16 g_Vh[BB * TT * DD];
__device__ __nv_bfloat16 g_Vl[BB * TT * DD];

// ---------------- PTX helpers (baseline ISA only: sm_80-class) ----------------
__device__ __forceinline__ uint32_t smem_u32(const void* p) {
    uint32_t a;
    asm("{ .reg .u64 t; cvta.to.shared.u64 t, %1; cvt.u32.u64 %0, t; }" : "=r"(a) : "l"(p));
    return a;
}

#define CP_ASYNC16(dst, src) \
    asm volatile("cp.async.cg.shared.global [%0], [%1], 16;" :: "r"(dst), "l"(src))
#define CP_COMMIT() asm volatile("cp.async.commit_group;")
#define CP_WAIT1() asm volatile("cp.async.wait_group 1;")
#define CP_WAIT0() asm volatile("cp.async.wait_group 0;")

#define LDM_X4(r0, r1, r2, r3, addr) \
    asm volatile("ldmatrix.sync.aligned.m8n8.x4.shared.b16 {%0,%1,%2,%3}, [%4];" \
                 : "=r"(r0), "=r"(r1), "=r"(r2), "=r"(r3) : "r"(addr))

#define LDM_X4_T(r0, r1, r2, r3, addr) \
    asm volatile("ldmatrix.sync.aligned.m8n8.x4.trans.shared.b16 {%0,%1,%2,%3}, [%4];" \
                 : "=r"(r0), "=r"(r1), "=r"(r2), "=r"(r3) : "r"(addr))

#define MMA16816(c0, c1, c2, c3, a0, a1, a2, a3, b0, b1) \
    asm volatile("mma.sync.aligned.m16n8k16.row.col.f32.bf16.bf16.f32 " \
                 "{%0,%1,%2,%3}, {%4,%5,%6,%7}, {%8,%9}, {%0,%1,%2,%3};" \
                 : "+f"(c0), "+f"(c1), "+f"(c2), "+f"(c3) \
                 : "r"(a0), "r"(a1), "r"(a2), "r"(a3), "r"(b0), "r"(b1))

// SW128 swizzle (Swizzle<3,4,3>): XOR bits [6:4] with bits [9:7]
#define SW128B(o) ((o) ^ (((o) >> 3) & 0x70))

__device__ __forceinline__ uint32_t packbf2(float a, float b) {
    __nv_bfloat162 t = __floats2bfloat162_rn(a, b);
    return *(uint32_t*)&t;
}
__device__ __forceinline__ uint32_t packlo2(float a, float b, uint32_t hi) {
    __nv_bfloat162 hv = *(__nv_bfloat162*)&hi;
    return packbf2(a - __bfloat162float(hv.x), b - __bfloat162float(hv.y));
}

// ---------------- setup: Pval table + mix weight ----------------
__global__ void setup_kernel(const float* __restrict__ mu,
                             const float* __restrict__ lam,
                             const float* __restrict__ g1,
                             const float* __restrict__ g2,
                             const float* __restrict__ th1,
                             const float* __restrict__ th2) {
    int h = threadIdx.x;
    if (h == 0) {
        float w = 1.0f / (1.0f + __expf(-mu[0]));
        g_wmix[0] = w;
        g_wmix[1] = 1.0f - w;
    }
    if (h < NHH) {
        float base, theta = 0.0f;
        int kind;
        if (h < RHH) { base = lam[h]; kind = 0; }
        else if (h < RHH + SHH) { base = g1[h - RHH]; theta = th1[h - RHH]; kind = 1; }
        else { base = g2[h - RHH - SHH]; theta = th2[h - RHH - SHH]; kind = 2; }
        float p = 1.0f;
        g_Pval[h][0] = 0.0f;
        for (int L = 1; L <= MAXL; L++) {
            p *= base;
            float v = p;
            if (kind == 1) v *= sinf(theta * (float)L);
            else if (kind == 2) v *= cosf(theta * (float)L);
            g_Pval[h][L] = v;
        }
    }
}

// ---------------- fp32 -> bf16 hi/lo split (x / activations) ----------------
__global__ __launch_bounds__(256) void cvt_split(const float* __restrict__ in,
                                                 __nv_bfloat16* __restrict__ hi,
                                                 __nv_bfloat16* __restrict__ lo,
                                                 int n4) {
    int i = blockIdx.x * blockDim.x + threadIdx.x;
    if (i >= n4) return;
    float4 v = ((const float4*)in)[i];
    __nv_bfloat16 h0 = __float2bfloat16(v.x);
    __nv_bfloat16 h1 = __float2bfloat16(v.y);
    __nv_bfloat16 h2 = __float2bfloat16(v.z);
    __nv_bfloat16 h3 = __float2bfloat16(v.w);
    __nv_bfloat16 l0 = __float2bfloat16(v.x - __bfloat162float(h0));
    __nv_bfloat16 l1 = __float2bfloat16(v.y - __bfloat162float(h1));
    __nv_bfloat16 l2 = __float2bfloat16(v.z - __bfloat162float(h2));
    __nv_bfloat16 l3 = __float2bfloat16(v.w - __bfloat162float(h3));
    __nv_bfloat162 hp0 = __halves2bfloat162(h0, h1);
    __nv_bfloat162 hp1 = __halves2bfloat162(h2, h3);
    __nv_bfloat162 lp0 = __halves2bfloat162(l0, l1);
    __nv_bfloat162 lp1 = __halves2bfloat162(l2, l3);
    uint2 hw, lw;
    hw.x = *(uint32_t*)&hp0; hw.y = *(uint32_t*)&hp1;
    lw.x = *(uint32_t*)&lp0; lw.y = *(uint32_t*)&lp1;
    ((uint2*)hi)[i] = hw;
    ((uint2*)lo)[i] = lw;
}

// fused: all 4 weight matrices -> g_wh/g_wl (contiguous)
__global__ __launch_bounds__(256) void cvt_split_w(const float* __restrict__ w0,
                                                   const float* __restrict__ w1,
                                                   const float* __restrict__ w2,
                                                   const float* __restrict__ w3) {
    int i = blockIdx.x * blockDim.x + threadIdx.x;
    const int per = DD * DD / 4;
    int mat = i / per, local = i - mat * per;
    const float* src = (mat == 0) ? w0 : (mat == 1) ? w1 : (mat == 2) ? w2 : w3;
    float4 v = ((const float4*)src)[local];
    __nv_bfloat16 h0 = __float2bfloat16(v.x);
    __nv_bfloat16 h1 = __float2bfloat16(v.y);
    __nv_bfloat16 h2 = __float2bfloat16(v.z);
    __nv_bfloat16 h3 = __float2bfloat16(v.w);
    __nv_bfloat16 l0 = __float2bfloat16(v.x - __bfloat162float(h0));
    __nv_bfloat16 l1 = __float2bfloat16(v.y - __bfloat162float(h1));
    __nv_bfloat16 l2 = __float2bfloat16(v.z - __bfloat162float(h2));
    __nv_bfloat16 l3 = __float2bfloat16(v.w - __bfloat162float(h3));
    __nv_bfloat162 hp0 = __halves2bfloat162(h0, h1);
    __nv_bfloat162 hp1 = __halves2bfloat162(h2, h3);
    __nv_bfloat162 lp0 = __halves2bfloat162(l0, l1);
    __nv_bfloat162 lp1 = __halves2bfloat162(l2, l3);
    uint2 hw, lw;
    hw.x = *(uint32_t*)&hp0; hw.y = *(uint32_t*)&hp1;
    lw.x = *(uint32_t*)&lp0; lw.y = *(uint32_t*)&lp1;
    ((uint2*)g_wh)[i] = hw;
    ((uint2*)g_wl)[i] = lw;
}

// ---------------- HMMA bf16x2 GEMM body: C = oscale*(A @ W^T + bias) ----
#define G_TILE_B 10240          // 128*40*2
#define G_STAGE_B (4 * G_TILE_B)
#define G_SMEM (2 * G_STAGE_B)  // 81920

__device__ __forceinline__ void gemm_body(
    const __nv_bfloat16* __restrict__ Ah, const __nv_bfloat16* __restrict__ Al,
    const __nv_bfloat16* __restrict__ Bh, const __nv_bfloat16* __restrict__ Bl,
    const float* __restrict__ bias, float* __restrict__ C,
    __nv_bfloat16* __restrict__ Chi, __nv_bfloat16* __restrict__ Clo,
    float oscale, int m0, int n0, char* gsm) {
    const uint32_t smBase = smem_u32(gsm);

    const int tid = threadIdx.x;
    const int lane = tid & 31;
    const int wid = tid >> 5;
    const int wm = wid & 3;
    const int wn = wid >> 2;

    const __nv_bfloat16* srcs[4];
    srcs[0] = Ah + (size_t)m0 * DD;
    srcs[1] = Al + (size_t)m0 * DD;
    srcs[2] = Bh + (size_t)n0 * DD;
    srcs[3] = Bl + (size_t)n0 * DD;

    const int ch0 = tid * 2;
    const int lrow0 = ch0 >> 2, lcol0 = (ch0 & 3) * 8;
    const int lrow1 = (ch0 + 1) >> 2, lcol1 = ((ch0 + 1) & 3) * 8;

    float c[2][8][4];
#pragma unroll
    for (int mi = 0; mi < 2; mi++)
#pragma unroll
        for (int ni = 0; ni < 8; ni++)
#pragma unroll
            for (int r = 0; r < 4; r++) c[mi][ni][r] = 0.0f;

    {
        uint32_t sb = smBase;
#pragma unroll
        for (int t = 0; t < 4; t++) {
            CP_ASYNC16(sb + t * G_TILE_B + lrow0 * 80 + lcol0 * 2,
                       srcs[t] + (size_t)lrow0 * DD + lcol0);
            CP_ASYNC16(sb + t * G_TILE_B + lrow1 * 80 + lcol1 * 2,
                       srcs[t] + (size_t)lrow1 * DD + lcol1);
        }
        CP_COMMIT();
    }

    const uint32_t aOff = (uint32_t)((wm * 32 + (lane & 15)) * 80 + ((lane >> 4) * 8) * 2);
    const uint32_t bOff = (uint32_t)((wn * 64 + ((lane >> 4) & 1) * 8 + (lane & 7)) * 80 +
                                     (((lane >> 3) & 1) * 8) * 2);

    const int NIT = DD / 32;
    for (int it = 0; it < NIT; it++) {
        if (it + 1 < NIT) {
            uint32_t sb = smBase + ((it + 1) & 1) * G_STAGE_B;
            int k0 = (it + 1) * 32;
#pragma unroll
            for (int t = 0; t < 4; t++) {
                CP_ASYNC16(sb + t * G_TILE_B + lrow0 * 80 + lcol0 * 2,
                           srcs[t] + (size_t)lrow0 * DD + k0 + lcol0);
                CP_ASYNC16(sb + t * G_TILE_B + lrow1 * 80 + lcol1 * 2,
                           srcs[t] + (size_t)lrow1 * DD + k0 + lcol1);
            }
            CP_COMMIT();
            CP_WAIT1();
        } else {
            CP_WAIT0();
        }
        __syncthreads();

        const uint32_t aBase = smBase + (it & 1) * G_STAGE_B;
        const uint32_t bBase = aBase + 2 * G_TILE_B;
#pragma unroll
        for (int kk = 0; kk < 2; kk++) {
            uint32_t ah[2][4], al[2][4];
#pragma unroll
            for (int mi = 0; mi < 2; mi++) {
                uint32_t a = aBase + aOff + (uint32_t)(mi * 16 * 80 + kk * 32);
                LDM_X4(ah[mi][0], ah[mi][1], ah[mi][2], ah[mi][3], a);
                LDM_X4(al[mi][0], al[mi][1], al[mi][2], al[mi][3], a + G_TILE_B);
            }
            {
                uint32_t bh[8][2];
#pragma unroll
                for (int nq = 0; nq < 4; nq++) {
                    uint32_t a = bBase + bOff + (uint32_t)(nq * 16 * 80 + kk * 32);
                    LDM_X4(bh[nq * 2][0], bh[nq * 2][1], bh[nq * 2 + 1][0], bh[nq * 2 + 1][1], a);
                }
                // pass 1: hh — 16 distinct accumulators before any reuse
#pragma unroll
                for (int mi = 0; mi < 2; mi++)
#pragma unroll
                    for (int ni = 0; ni < 8; ni++) {
                        float* cc = c[mi][ni];
                        MMA16816(cc[0], cc[1], cc[2], cc[3],
                                 ah[mi][0], ah[mi][1], ah[mi][2], ah[mi][3],
                                 bh[ni][0], bh[ni][1]);
                    }
                // pass 2: lh
#pragma unroll
                for (int mi = 0; mi < 2; mi++)
#pragma unroll
                    for (int ni = 0; ni < 8; ni++) {
                        float* cc = c[mi][ni];
                        MMA16816(cc[0], cc[1], cc[2], cc[3],
                                 al[mi][0], al[mi][1], al[mi][2], al[mi][3],
                                 bh[ni][0], bh[ni][1]);
                    }
            }
            {
                uint32_t bl[8][2];
#pragma unroll
                for (int nq = 0; nq < 4; nq++) {
                    uint32_t a = bBase + bOff + (uint32_t)(nq * 16 * 80 + kk * 32) + G_TILE_B;
                    LDM_X4(bl[nq * 2][0], bl[nq * 2][1], bl[nq * 2 + 1][0], bl[nq * 2 + 1][1], a);
                }
                // pass 3: hl
#pragma unroll
                for (int mi = 0; mi < 2; mi++)
#pragma unroll
                    for (int ni = 0; ni < 8; ni++) {
                        float* cc = c[mi][ni];
                        MMA16816(cc[0], cc[1], cc[2], cc[3],
                                 ah[mi][0], ah[mi][1], ah[mi][2], ah[mi][3],
                                 bl[ni][0], bl[ni][1]);
                    }
            }
        }
        __syncthreads();
    }

    // ---- epilogue ----
#pragma unroll
    for (int mi = 0; mi < 2; mi++) {
        int row = m0 + wm * 32 + mi * 16 + (lane >> 2);
#pragma unroll
        for (int ni = 0; ni < 8; ni++) {
            int col = n0 + wn * 64 + ni * 8 + (lane & 3) * 2;
            float b0 = bias[col], b1 = bias[col + 1];
            float v00 = (c[mi][ni][0] + b0) * oscale, v01 = (c[mi][ni][1] + b1) * oscale;
            float v10 = (c[mi][ni][2] + b0) * oscale, v11 = (c[mi][ni][3] + b1) * oscale;
            if (C != nullptr) {
                *(float2*)(C + (size_t)row * DD + col) = make_float2(v00, v01);
                *(float2*)(C + (size_t)(row + 8) * DD + col) = make_float2(v10, v11);
            }
            if (Chi != nullptr) {
                uint32_t h0 = packbf2(v00, v01);
                uint32_t l0v = packlo2(v00, v01, h0);
                uint32_t h1 = packbf2(v10, v11);
                uint32_t l1v = packlo2(v10, v11, h1);
                *(uint32_t*)(Chi + (size_t)row * DD + col) = h0;
                *(uint32_t*)(Clo + (size_t)row * DD + col) = l0v;
                *(uint32_t*)(Chi + (size_t)(row + 8) * DD + col) = h1;
                *(uint32_t*)(Clo + (size_t)(row + 8) * DD + col) = l1v;
            }
        }
    }
}

// final projection: ctx_split @ Wf^T + bf -> out (fp32 only)
__global__ __launch_bounds__(256, 2) void gemm_mma(
    const __nv_bfloat16* __restrict__ Ah, const __nv_bfloat16* __restrict__ Al,
    const __nv_bfloat16* __restrict__ Bh, const __nv_bfloat16* __restrict__ Bl,
    const float* __restrict__ bias, float* __restrict__ C,
    __nv_bfloat16* __restrict__ Chi, __nv_bfloat16* __restrict__ Clo,
    float oscale) {
    extern __shared__ char gsm[];
    gemm_body(Ah, Al, Bh, Bl, bias, C, Chi, Clo, oscale,
              blockIdx.y * 128, blockIdx.x * 128, gsm);
}

// fused Q/K/V projections: z selects weight/bias/output set
__global__ __launch_bounds__(256, 2) void gemm_qkv(
    const float* __restrict__ bq, const float* __restrict__ bk,
    const float* __restrict__ bv) {
    extern __shared__ char gsm[];
    const int z = blockIdx.z;
    const float LOG2E = 1.4426950408889634f;
    const __nv_bfloat16* Bh = g_wh + (size_t)z * DD * DD;
    const __nv_bfloat16* Bl = g_wl + (size_t)z * DD * DD;
    const float* bias; float* C; __nv_bfloat16 *Chi, *Clo; float osc;
    if (z == 0)      { bias = bq; C = nullptr; Chi = g_Qh; Clo = g_Ql; osc = LOG2E; }
    else if (z == 1) { bias = bk; C = nullptr; Chi = g_Kh; Clo = g_Kl; osc = 1.0f; }
    else             { bias = bv; C = g_V;     Chi = g_Vh; Clo = g_Vl; osc = 1.0f; }
    gemm_body(g_xh, g_xl, Bh, Bl, bias, C, Chi, Clo, osc,
              blockIdx.y * 128, blockIdx.x * 128, gsm);
}

// ---------------- HMMA flash attention: ctx = (1-w) * softmax(Q K^T) V ----------------
// 4 warps, q-tile 64, k-tile 64. SW128-swizzled zero-pad tiles (8KB each).
// K hi/lo double-buffered; V hi/lo single-buffered. occ 4.
#define FL_KH 0            // [2 stages x 8192]
#define FL_KL 16384        // [2 stages x 8192]
#define FL_VH 32768
#define FL_VL 40960
#define FL_SMEM_B (49152 + 1024)

__global__ __launch_bounds__(128, 4) void flash_mma() {
    extern __shared__ char fsmem[];
    uint32_t smRaw = smem_u32(fsmem);
    const uint32_t smB = (smRaw + 1023u) & ~1023u;  // 1KB align for SW128
    const int tid = threadIdx.x;
    const int lane = tid & 31, wid = tid >> 5;
    const int b = blockIdx.z, h = blockIdx.y, q0 = blockIdx.x * 64;
    const size_t hOff = (size_t)h * HCC;

    const __nv_bfloat16* ksrc[2] = {
        g_Kh + (size_t)(b * TT) * DD + hOff,
        g_Kl + (size_t)(b * TT) * DD + hOff };
    const __nv_bfloat16* vsrc[2] = {
        g_Vh + (size_t)(b * TT) * DD + hOff,
        g_Vl + (size_t)(b * TT) * DD + hOff };

    // prologue: K(0) into stage 0
    {
#pragma unroll
        for (int i = 0; i < 8; i++) {
            int cck = tid + i * 128;
            int arr = cck >> 9;
            int r = (cck >> 3) & 63, c16 = cck & 7;
            uint32_t off = SW128B((uint32_t)(r * 128 + c16 * 16));
            CP_ASYNC16(smB + FL_KH + arr * 16384 + off,
                       ksrc[arr] + (size_t)r * DD + c16 * 8);
        }
        CP_COMMIT();
    }

    const int r0 = wid * 16;
    // ---- Q fragments straight from global ----
    uint32_t qah[4][4], qal[4][4];
    {
        const int rA = lane >> 2, cA = (lane & 3) * 2;
        const __nv_bfloat16* qhp = g_Qh + (size_t)(b * TT + q0 + r0 + rA) * DD + hOff + cA;
        const __nv_bfloat16* qlp = g_Ql + (size_t)(b * TT + q0 + r0 + rA) * DD + hOff + cA;
#pragma unroll
        for (int kk = 0; kk < 4; kk++) {
            qah[kk][0] = *(const uint32_t*)(qhp + kk * 16);
            qah[kk][1] = *(const uint32_t*)(qhp + 8 * DD + kk * 16);
            qah[kk][2] = *(const uint32_t*)(qhp + kk * 16 + 8);
            qah[kk][3] = *(const uint32_t*)(qhp + 8 * DD + kk * 16 + 8);
            qal[kk][0] = *(const uint32_t*)(qlp + kk * 16);
            qal[kk][1] = *(const uint32_t*)(qlp + 8 * DD + kk * 16);
            qal[kk][2] = *(const uint32_t*)(qlp + kk * 16 + 8);
            qal[kk][3] = *(const uint32_t*)(qlp + 8 * DD + kk * 16 + 8);
        }
    }

    const int lrK = (lane & 7) + (lane >> 4) * 8;
    const int ksl = (lane >> 3) & 1;
    const int lrV = (lane & 7) + ((lane >> 3) & 1) * 8;
    const int vsl = (lane >> 4);

    float m0 = -3.0e38f, m1 = -3.0e38f, l0 = 0.0f, l1 = 0.0f;
    float o[8][4];
#pragma unroll
    for (int i = 0; i < 8; i++)
#pragma unroll
        for (int j = 0; j < 4; j++) o[i][j] = 0.0f;

    const int NKT = TT / 64;  // 32
    for (int kt = 0; kt < NKT; kt++) {
        CP_WAIT0();
        __syncthreads();

        if (kt + 1 < NKT) {
            int t0 = (kt + 1) * 64;
            uint32_t sb = smB + FL_KH + ((kt + 1) & 1) * 8192;
#pragma unroll
            for (int i = 0; i < 8; i++) {
                int cck = tid + i * 128;
                int arr = cck >> 9;
                int r = (cck >> 3) & 63, c16 = cck & 7;
                uint32_t off = SW128B((uint32_t)(r * 128 + c16 * 16));
                CP_ASYNC16(sb + arr * 16384 + off,
                           ksrc[arr] + (size_t)(t0 + r) * DD + c16 * 8);
            }
            CP_COMMIT();
        }
        {
            int t0 = kt * 64;
#pragma unroll
            for (int i = 0; i < 8; i++) {
                int cck = tid + i * 128;
                int arr = cck >> 9;
                int r = (cck >> 3) & 63, c16 = cck & 7;
                uint32_t off = SW128B((uint32_t)(r * 128 + c16 * 16));
                CP_ASYNC16(smB + FL_VH + arr * 8192 + off,
                           vsrc[arr] + (size_t)(t0 + r) * DD + c16 * 8);
            }
            CP_COMMIT();
        }

        const uint32_t kstg = smB + FL_KH + (kt & 1) * 8192;

        // ---- S = Q K^T (16 x 64 per warp), 3-mma split, RAW-distance maximized ----
        float s[8][4];
#pragma unroll
        for (int i = 0; i < 8; i++)
#pragma unroll
            for (int j = 0; j < 4; j++) s[i][j] = 0.0f;
#pragma unroll
        for (int kk = 0; kk < 4; kk++) {
            {
                uint32_t kb[8][2];
#pragma unroll
                for (int p = 0; p < 4; p++) {
                    uint32_t off = SW128B((uint32_t)((p * 16 + lrK) * 128 +
                                                     (kk * 2 + ksl) * 16));
                    LDM_X4(kb[p * 2][0], kb[p * 2][1], kb[p * 2 + 1][0], kb[p * 2 + 1][1],
                           kstg + off);
                }
#pragma unroll
                for (int nj = 0; nj < 8; nj++)
                    MMA16816(s[nj][0], s[nj][1], s[nj][2], s[nj][3],
                             qah[kk][0], qah[kk][1], qah[kk][2], qah[kk][3],
                             kb[nj][0], kb[nj][1]);
#pragma unroll
                for (int nj = 0; nj < 8; nj++)
                    MMA16816(s[nj][0], s[nj][1], s[nj][2], s[nj][3],
                             qal[kk][0], qal[kk][1], qal[kk][2], qal[kk][3],
                             kb[nj][0], kb[nj][1]);
            }
            {
                uint32_t kl[8][2];
#pragma unroll
                for (int p = 0; p < 4; p++) {
                    uint32_t off = SW128B((uint32_t)((p * 16 + lrK) * 128 +
                                                     (kk * 2 + ksl) * 16));
                    LDM_X4(kl[p * 2][0], kl[p * 2][1], kl[p * 2 + 1][0], kl[p * 2 + 1][1],
                           kstg + 16384 + off);
                }
#pragma unroll
                for (int nj = 0; nj < 8; nj++)
                    MMA16816(s[nj][0], s[nj][1], s[nj][2], s[nj][3],
                             qah[kk][0], qah[kk][1], qah[kk][2], qah[kk][3],
                             kl[nj][0], kl[nj][1]);
            }
        }

        // ---- online softmax (exp2 domain; Q pre-scaled by log2e) ----
        float mr0 = s[0][0], mr1 = s[0][2];
#pragma unroll
        for (int nj = 0; nj < 8; nj++) {
            mr0 = fmaxf(mr0, fmaxf(s[nj][0], s[nj][1]));
            mr1 = fmaxf(mr1, fmaxf(s[nj][2], s[nj][3]));
        }
        mr0 = fmaxf(mr0, __shfl_xor_sync(0xffffffffu, mr0, 1, 4));
        mr0 = fmaxf(mr0, __shfl_xor_sync(0xffffffffu, mr0, 2, 4));
        mr1 = fmaxf(mr1, __shfl_xor_sync(0xffffffffu, mr1, 1, 4));
        mr1 = fmaxf(mr1, __shfl_xor_sync(0xffffffffu, mr1, 2, 4));
        float mn0 = fmaxf(m0, mr0), mn1 = fmaxf(m1, mr1);
        float cor0 = exp2f(m0 - mn0), cor1 = exp2f(m1 - mn1);
        m0 = mn0; m1 = mn1;
        float rs0 = 0.0f, rs1 = 0.0f;
#pragma unroll
        for (int nj = 0; nj < 8; nj++) {
            s[nj][0] = exp2f(s[nj][0] - mn0);
            s[nj][1] = exp2f(s[nj][1] - mn0);
            s[nj][2] = exp2f(s[nj][2] - mn1);
            s[nj][3] = exp2f(s[nj][3] - mn1);
            rs0 += s[nj][0] + s[nj][1];
            rs1 += s[nj][2] + s[nj][3];
        }
        rs0 += __shfl_xor_sync(0xffffffffu, rs0, 1, 4);
        rs0 += __shfl_xor_sync(0xffffffffu, rs0, 2, 4);
        rs1 += __shfl_xor_sync(0xffffffffu, rs1, 1, 4);
        rs1 += __shfl_xor_sync(0xffffffffu, rs1, 2, 4);
        l0 = l0 * cor0 + rs0;
        l1 = l1 * cor1 + rs1;
#pragma unroll
        for (int nd = 0; nd < 8; nd++) {
            o[nd][0] *= cor0; o[nd][1] *= cor0;
            o[nd][2] *= cor1; o[nd][3] *= cor1;
        }

        // ---- repack P (C-frag -> A-frag) with hi/lo split ----
        uint32_t pah[4][4], pal[4][4];
#pragma unroll
        for (int kk = 0; kk < 4; kk++) {
            pah[kk][0] = packbf2(s[2 * kk][0], s[2 * kk][1]);
            pah[kk][1] = packbf2(s[2 * kk][2], s[2 * kk][3]);
            pah[kk][2] = packbf2(s[2 * kk + 1][0], s[2 * kk + 1][1]);
            pah[kk][3] = packbf2(s[2 * kk + 1][2], s[2 * kk + 1][3]);
            pal[kk][0] = packlo2(s[2 * kk][0], s[2 * kk][1], pah[kk][0]);
            pal[kk][1] = packlo2(s[2 * kk][2], s[2 * kk][3], pah[kk][1]);
            pal[kk][2] = packlo2(s[2 * kk + 1][0], s[2 * kk + 1][1], pah[kk][2]);
            pal[kk][3] = packlo2(s[2 * kk + 1][2], s[2 * kk + 1][3], pah[kk][3]);
        }

        // ---- wait V(kt), publish, then O += P V ----
        if (kt + 1 < NKT) { CP_WAIT1(); } else { CP_WAIT0(); }
        __syncthreads();

#pragma unroll
        for (int kk = 0; kk < 4; kk++) {
            {
                uint32_t vb[8][2];
#pragma unroll
                for (int q = 0; q < 4; q++) {
                    uint32_t off = SW128B((uint32_t)((kk * 16 + lrV) * 128 +
                                                     (q * 2 + vsl) * 16));
                    LDM_X4_T(vb[q * 2][0], vb[q * 2][1], vb[q * 2 + 1][0], vb[q * 2 + 1][1],
                             smB + FL_VH + off);
                }
#pragma unroll
                for (int nd = 0; nd < 8; nd++)
                    MMA16816(o[nd][0], o[nd][1], o[nd][2], o[nd][3],
                             pah[kk][0], pah[kk][1], pah[kk][2], pah[kk][3],
                             vb[nd][0], vb[nd][1]);
#pragma unroll
                for (int nd = 0; nd < 8; nd++)
                    MMA16816(o[nd][0], o[nd][1], o[nd][2], o[nd][3],
                             pal[kk][0], pal[kk][1], pal[kk][2], pal[kk][3],
                             vb[nd][0], vb[nd][1]);
            }
            {
                uint32_t vl[8][2];
#pragma unroll
                for (int q = 0; q < 4; q++) {
                    uint32_t off = SW128B((uint32_t)((kk * 16 + lrV) * 128 +
                                                     (q * 2 + vsl) * 16));
                    LDM_X4_T(vl[q * 2][0], vl[q * 2][1], vl[q * 2 + 1][0], vl[q * 2 + 1][1],
                             smB + FL_VL + off);
                }
#pragma unroll
                for (int nd = 0; nd < 8; nd++)
                    MMA16816(o[nd][0], o[nd][1], o[nd][2], o[nd][3],
                             pah[kk][0], pah[kk][1], pah[kk][2], pah[kk][3],
                             vl[nd][0], vl[nd][1]);
            }
        }
    }

    // ---- epilogue: ctx = (1-w) * O / l ----
    float w1 = g_wmix[1];
    float inv0 = w1 / l0, inv1 = w1 / l1;
    int row0 = q0 + r0 + (lane >> 2);
    float* dst0 = g_ctx + (size_t)(b * TT + row0) * DD + hOff + (lane & 3) * 2;
    float* dst1 = dst0 + 8 * DD;
#pragma unroll
    for (int nd = 0; nd < 8; nd++) {
        *(float2*)(dst0 + nd * 8) = make_float2(o[nd][0] * inv0, o[nd][1] * inv0);
        *(float2*)(dst1 + nd * 8) = make_float2(o[nd][2] * inv1, o[nd][3] * inv1);
    }
}

// ---------------- prefix sums of V along t, per (b,h,c): hierarchical ----------------
__global__ __launch_bounds__(256) void prefix_kernel() {
    __shared__ float part[4][64];
    int b = blockIdx.x >> 4;
    int h = blockIdx.x & 15;
    int c = threadIdx.x & 63;
    int ch = threadIdx.x >> 6;
    const float* vp = g_V + ((size_t)(b * TT + ch * 512)) * DD + h * HCC + c;
    float s0 = 0.0f, s1 = 0.0f, s2 = 0.0f, s3 = 0.0f;
    for (int t = 0; t < 512; t += 4) {
        s0 += vp[(size_t)(t + 0) * DD];
        s1 += vp[(size_t)(t + 1) * DD];
        s2 += vp[(size_t)(t + 2) * DD];
        s3 += vp[(size_t)(t + 3) * DD];
    }
    part[ch][c] = (s0 + s1) + (s2 + s3);
    __syncthreads();
    float run = 0.0f;
    for (int i = 0; i < ch; i++) run += part[i][c];
    float* ps = g_PS + ((size_t)(b * TT + ch * 512)) * DD + h * HCC + c;
    for (int t = 0; t < 512; t++) {
        run += vp[(size_t)t * DD];
        ps[(size_t)t * DD] = run;
    }
}

// ---------------- PV: out_split = ctx + w * (P @ V) via 99-tap conv + prefix ----------------
__global__ __launch_bounds__(256) void pv_kernel() {
    __shared__ float Vw[162 * 64];
    __shared__ float Pv[MAXL + 1];
    int b = blockIdx.z, h = blockIdx.y;
    int q0 = blockIdx.x * 64;
    int tid = threadIdx.x;
    if (tid <= MAXL) Pv[tid] = g_Pval[h][tid];
    for (int idx = tid; idx < 162 * 64; idx += 256) {
        int r = idx >> 6, c = idx & 63;
        int tg = q0 - 99 + r;
        Vw[idx] = (tg >= 0) ? g_V[((size_t)(b * TT + tg)) * DD + h * HCC + c] : 0.0f;
    }
    __syncthreads();
    int c = tid & 63, qq = tid >> 6;
    float w = g_wmix[0];
#pragma unroll 1
    for (int ii = 0; ii < 16; ii++) {
        int ql = qq * 16 + ii;
        int qg = q0 + ql;
        float a0 = 0.0f, a1 = 0.0f, a2 = 0.0f, a3 = 0.0f;
        int jmax = min(99, qg);
        int j = 1;
        for (; j + 3 <= jmax; j += 4) {
            a0 += Pv[j]     * Vw[((ql - j + 99) << 6) | c];
            a1 += Pv[j + 1] * Vw[((ql - j + 98) << 6) | c];
            a2 += Pv[j + 2] * Vw[((ql - j + 97) << 6) | c];
            a3 += Pv[j + 3] * Vw[((ql - j + 96) << 6) | c];
        }
        for (; j <= jmax; j++)
            a0 += Pv[j] * Vw[((ql - j + 99) << 6) | c];
        float acc = (a0 + a1) + (a2 + a3);
        if (qg >= 100)
            acc += Pv[MAXL] * g_PS[((size_t)(b * TT + qg - 100)) * DD + h * HCC + c];
        size_t oi = ((size_t)(b * TT + qg)) * DD + h * HCC + c;
        float outv = g_ctx[oi] + w * acc;
        __nv_bfloat16 hh = __float2bfloat16(outv);
        g_xh[oi] = hh;
        g_xl[oi] = __float2bfloat16(outv - __bfloat162float(hh));
    }
}

// ---------------- launch ----------------
extern "C" void kernel_launch(void* const* d_in, const int* in_sizes, int n_in,
                              void* d_out, int out_size) {
    const float* x   = (const float*)d_in[0];
    const float* mu  = (const float*)d_in[1];
    const float* lam = (const float*)d_in[2];
    const float* g1  = (const float*)d_in[3];
    const float* g2  = (const float*)d_in[4];
    const float* th1 = (const float*)d_in[5];
    const float* th2 = (const float*)d_in[6];
    const float* Wq  = (const float*)d_in[7];
    const float* bq  = (const float*)d_in[8];
    const float* Wk  = (const float*)d_in[9];
    const float* bk  = (const float*)d_in[10];
    const float* Wv  = (const float*)d_in[11];
    const float* bv  = (const float*)d_in[12];
    const float* Wf  = (const float*)d_in[13];
    const float* bf  = (const float*)d_in[14];
    float* out = (float*)d_out;

    __nv_bfloat16 *xh, *xl, *wh, *wl;
    cudaGetSymbolAddress((void**)&xh, g_xh);
    cudaGetSymbolAddress((void**)&xl, g_xl);
    cudaGetSymbolAddress((void**)&wh, g_wh);
    cudaGetSymbolAddress((void**)&wl, g_wl);

    setup_kernel<<<1, 32>>>(mu, lam, g1, g2, th1, th2);

    const int NX4 = (BB * TT * DD) / 4;
    const int NW4ALL = (4 * DD * DD) / 4;
    cvt_split<<<(NX4 + 255) / 256, 256>>>(x, xh, xl, NX4);
    cvt_split_w<<<NW4ALL / 256, 256>>>(Wq, Wk, Wv, Wf);

    cudaFuncSetAttribute(gemm_qkv, cudaFuncAttributeMaxDynamicSharedMemorySize, G_SMEM);
    cudaFuncSetAttribute(gemm_mma, cudaFuncAttributeMaxDynamicSharedMemorySize, G_SMEM);
    dim3 qkvgrid(DD / 128, (BB * TT) / 128, 3);
    gemm_qkv<<<qkvgrid, 256, G_SMEM>>>(bq, bk, bv);

    cudaFuncSetAttribute(flash_mma, cudaFuncAttributeMaxDynamicSharedMemorySize, FL_SMEM_B);
    dim3 fgrid(TT / 64, NHH, BB);
    flash_mma<<<fgrid, 128, FL_SMEM_B>>>();

    prefix_kernel<<<BB * NHH, 256>>>();

    dim3 pvgrid(TT / 64, NHH, BB);
    pv_kernel<<<pvgrid, 256>>>();

    dim3 ggrid(DD / 128, (BB * TT) / 128);
    gemm_mma<<<ggrid, 256, G_SMEM>>>(xh, xl, wh + 3 * DD * DD, wl + 3 * DD * DD, bf, out,
                                     nullptr, nullptr, 1.0f);
}